// round 1
// baseline (speedup 1.0000x reference)
#include <cuda_runtime.h>
#include <math.h>

#define NB 4
#define NH 8
#define SEGL 1024
#define MEML 1024
#define TOT 2048
#define DD 128

// ---------------- scratch (device globals; no allocations) ----------------
__device__ float g_q[NB*NH*SEGL*DD];      // 16 MB  [b][h][s][e]
__device__ float g_k[NB*NH*TOT*DD];       // 32 MB  [b][h][t][e]
__device__ float g_v[NB*NH*TOT*DD];       // 32 MB  [b][h][t][e]
__device__ float g_r[NH*TOT*DD];          //  8 MB  [h][t][e]
__device__ float g_u1k[NB*NH*TOT];        // 256 KB [b][h][t]
__device__ float g_u2r[NH*TOT];           //  64 KB [h][t]
__device__ float g_att[NB*SEGL*NH*DD];    // 16 MB  att3 layout (4,1024,1024)

// ---------------- projection GEMMs with scatter epilogue ----------------
// C(M x N) = A(M x 128) @ W(128 x N), tile 64x64, K staged in 2 chunks of 64.
// MODE 0: q-proj  (A = x rows, M=4096,  N=1024)
// MODE 1: kv-proj (A = concat(mem,x),   M=8192,  N=2048)
// MODE 2: r-proj  (A = sinusoid pos,    M=2048,  N=1024)
template<int MODE>
__global__ __launch_bounds__(256) void proj_kernel(const float* __restrict__ X,
                                                   const float* __restrict__ MEMI,
                                                   const float* __restrict__ W, int N)
{
    __shared__ float As[64][64];
    __shared__ float Bs[64][64];
    const int m0 = blockIdx.y * 64;
    const int n0 = blockIdx.x * 64;
    const int tid = threadIdx.x;
    const int tx = tid & 15, ty = tid >> 4;

    float c[4][4] = {};

    for (int k0 = 0; k0 < 128; k0 += 64) {
        __syncthreads();
        // load A half-tile: 64 rows x 64 k (1024 float4, 4 per thread)
        #pragma unroll
        for (int i = 0; i < 4; i++) {
            int f = tid + i * 256;
            int row = f >> 4;
            int col = (f & 15) << 2;
            int m = m0 + row;
            float4 a;
            if (MODE == 0) {
                a = *(const float4*)(X + (size_t)m * 128 + k0 + col);
            } else if (MODE == 1) {
                int bb = m >> 11, sp = m & 2047;
                const float* src = (sp < 1024) ? (MEMI + ((size_t)bb * 1024 + sp) * 128)
                                               : (X    + ((size_t)bb * 1024 + sp - 1024) * 128);
                a = *(const float4*)(src + k0 + col);
            } else {
                float pp = (float)(2047 - m);
                float vv[4];
                #pragma unroll
                for (int cc = 0; cc < 4; cc++) {
                    int e = k0 + col + cc;
                    float ang = pp / powf(10000.0f, (float)(2 * e) * (1.0f / 128.0f));
                    vv[cc] = ((e & 1) == 0) ? sinf(ang) : cosf(ang);
                }
                a = make_float4(vv[0], vv[1], vv[2], vv[3]);
            }
            *(float4*)(&As[row][col]) = a;
        }
        // load B half-tile: 64 k-rows x 64 n
        #pragma unroll
        for (int i = 0; i < 4; i++) {
            int f = tid + i * 256;
            int krow = f >> 4;
            int nv = (f & 15) << 2;
            *(float4*)(&Bs[krow][nv]) = *(const float4*)(W + (size_t)(k0 + krow) * N + n0 + nv);
        }
        __syncthreads();

        #pragma unroll
        for (int k4 = 0; k4 < 16; k4++) {
            float4 a[4], b[4];
            #pragma unroll
            for (int i = 0; i < 4; i++) a[i] = *(float4*)&As[ty * 4 + i][k4 * 4];
            #pragma unroll
            for (int j = 0; j < 4; j++) b[j] = *(float4*)&Bs[k4 * 4 + j][tx * 4];
            #pragma unroll
            for (int i = 0; i < 4; i++) {
                c[i][0] += a[i].x*b[0].x + a[i].y*b[1].x + a[i].z*b[2].x + a[i].w*b[3].x;
                c[i][1] += a[i].x*b[0].y + a[i].y*b[1].y + a[i].z*b[2].y + a[i].w*b[3].y;
                c[i][2] += a[i].x*b[0].z + a[i].y*b[1].z + a[i].z*b[2].z + a[i].w*b[3].z;
                c[i][3] += a[i].x*b[0].w + a[i].y*b[1].w + a[i].z*b[2].w + a[i].w*b[3].w;
            }
        }
    }

    // scatter epilogue per raw-reshape semantics
    const int fp = n0 + tx * 4;
    #pragma unroll
    for (int i = 0; i < 4; i++) {
        int m = m0 + ty * 4 + i;
        float4 val = make_float4(c[i][0], c[i][1], c[i][2], c[i][3]);
        if (MODE == 0) {
            int b_ = m >> 10, sp = m & 1023;
            int h = sp >> 7;
            int s = ((sp & 127) << 3) + (fp >> 7);
            int e = fp & 127;
            *(float4*)(g_q + ((((size_t)b_ * 8 + h) * 1024 + s) << 7) + e) = val;
        } else if (MODE == 1) {
            int bb = m >> 11, sp = m & 2047;
            int cc = bb * 2 + (sp >> 10);
            int h = (sp & 1023) >> 7;
            int t = ((sp & 127) << 4) + (fp >> 7);
            int e = fp & 127;
            float* dst = (cc < 4) ? (g_k + ((((size_t)cc * 8 + h) * 2048 + t) << 7) + e)
                                  : (g_v + ((((size_t)(cc - 4) * 8 + h) * 2048 + t) << 7) + e);
            *(float4*)dst = val;
        } else {
            int h = m >> 8;
            int t = ((m & 255) << 3) + (fp >> 7);
            int e = fp & 127;
            *(float4*)(g_r + (((size_t)h * 2048 + t) << 7) + e) = val;
        }
    }
}

// ---------------- u1·k and u2·r (warp per 128-dot) ----------------
__global__ __launch_bounds__(256) void udot_kernel(const float* __restrict__ U, int which, int nrows)
{
    int row = blockIdx.x * 8 + (threadIdx.x >> 5);
    int lane = threadIdx.x & 31;
    if (row >= nrows) return;
    const float* Mat = which ? g_r : g_k;
    float* Out = which ? g_u2r : g_u1k;
    int h = (row >> 11) & 7;
    float4 u = *(const float4*)(U + h * 128 + lane * 4);
    float4 m = *(const float4*)(Mat + (size_t)row * 128 + lane * 4);
    float s = u.x * m.x + u.y * m.y + u.z * m.z + u.w * m.w;
    #pragma unroll
    for (int o = 16; o; o >>= 1) s += __shfl_xor_sync(0xffffffffu, s, o);
    if (lane == 0) Out[row] = s;
}

// ---------------- fused flash attention with relative-position band ----------------
// grid (16 s-tiles, 32 bh), 256 threads, 64x64 tiles, 4x4 register fragments.
__global__ __launch_bounds__(256, 1) void attn_kernel()
{
    extern __shared__ float sm[];
    float* Qs = sm;               // 64*128
    float* Ks = Qs + 64 * 128;    // 64*128
    float* Vs = Ks + 64 * 128;    // 64*128
    float* Rs = Vs + 64 * 128;    // 127*128
    float* Ps = Rs + 127 * 128;   // 64*64
    float* bias = Ps + 64 * 64;   // 64

    const int s0 = blockIdx.x * 64;
    const int bh = blockIdx.y;
    const int h = bh & 7;
    const int tid = threadIdx.x;
    const int tx = tid & 15, ty = tid >> 4;

    const float* qbase = g_q + (size_t)bh * (1024 * 128);
    const float* kbase = g_k + (size_t)bh * (2048 * 128);
    const float* vbase = g_v + (size_t)bh * (2048 * 128);
    const float* rbase = g_r + (size_t)h * (2048 * 128);

    #pragma unroll
    for (int i = 0; i < 8; i++) {
        int f = tid + i * 256;
        int row = f >> 5, col = (f & 31) << 2;
        *(float4*)(Qs + row * 128 + col) = *(const float4*)(qbase + (size_t)(s0 + row) * 128 + col);
    }

    float m_run[4], l_run[4], o[4][8];
    #pragma unroll
    for (int i = 0; i < 4; i++) {
        m_run[i] = -1e30f; l_run[i] = 0.f;
        #pragma unroll
        for (int e = 0; e < 8; e++) o[i][e] = 0.f;
    }

    const int ntiles = (s0 >> 6) + 17;       // valid t <= s+1024
    const int base_d = tx * 4 - ty * 4 + 60; // diagonal base into Rs (always in [0,120])

    for (int tt = 0; tt < ntiles; tt++) {
        int t0 = tt * 64;
        __syncthreads();
        #pragma unroll
        for (int i = 0; i < 8; i++) {
            int f = tid + i * 256;
            int row = f >> 5, col = (f & 31) << 2;
            *(float4*)(Ks + row * 128 + col) = *(const float4*)(kbase + (size_t)(t0 + row) * 128 + col);
            *(float4*)(Vs + row * 128 + col) = *(const float4*)(vbase + (size_t)(t0 + row) * 128 + col);
        }
        int relbase = t0 - s0 + 960;  // r row for band offset 0 (>=0 always)
        #pragma unroll
        for (int i = 0; i < 16; i++) {
            int f = tid + i * 256;
            if (f < 127 * 32) {
                int row = f >> 5, col = (f & 31) << 2;
                int rel = relbase + row;
                float4 rv = make_float4(0.f, 0.f, 0.f, 0.f);
                if (rel < 2048) rv = *(const float4*)(rbase + (size_t)rel * 128 + col);
                *(float4*)(Rs + row * 128 + col) = rv;
            }
        }
        if (tid < 64) bias[tid] = g_u1k[(size_t)bh * 2048 + t0 + tid] + g_u2r[(size_t)h * 2048 + t0 + tid];
        __syncthreads();

        // scores: q·k + q·r[t-s+1023]  (7 diagonal r-rows per thread)
        float c[4][4] = {};
        #pragma unroll
        for (int k4 = 0; k4 < 32; k4++) {
            float4 q[4], k[4], r[7];
            #pragma unroll
            for (int i = 0; i < 4; i++) q[i] = *(float4*)(Qs + (ty * 4 + i) * 128 + k4 * 4);
            #pragma unroll
            for (int j = 0; j < 4; j++) k[j] = *(float4*)(Ks + (tx * 4 + j) * 128 + k4 * 4);
            #pragma unroll
            for (int d = 0; d < 7; d++) r[d] = *(float4*)(Rs + (base_d + d) * 128 + k4 * 4);
            #pragma unroll
            for (int i = 0; i < 4; i++)
                #pragma unroll
                for (int j = 0; j < 4; j++) {
                    float4 rr = r[j - i + 3];
                    c[i][j] += q[i].x * (k[j].x + rr.x) + q[i].y * (k[j].y + rr.y)
                             + q[i].z * (k[j].z + rr.z) + q[i].w * (k[j].w + rr.w);
                }
        }

        const float scale = 0.08838834764831843f; // 1/sqrt(128)
        #pragma unroll
        for (int i = 0; i < 4; i++) {
            int sg = s0 + ty * 4 + i;
            #pragma unroll
            for (int j = 0; j < 4; j++) {
                int tg = t0 + tx * 4 + j;
                float v = (c[i][j] + bias[tx * 4 + j]) * scale;
                c[i][j] = (tg - sg <= 1024) ? v : -1e30f;
            }
        }

        #pragma unroll
        for (int i = 0; i < 4; i++) {
            float mt = fmaxf(fmaxf(c[i][0], c[i][1]), fmaxf(c[i][2], c[i][3]));
            #pragma unroll
            for (int off = 8; off; off >>= 1) mt = fmaxf(mt, __shfl_xor_sync(0xffffffffu, mt, off));
            float mnew = fmaxf(m_run[i], mt);
            float alpha = __expf(m_run[i] - mnew);
            float rs = 0.f;
            #pragma unroll
            for (int j = 0; j < 4; j++) { float p = __expf(c[i][j] - mnew); c[i][j] = p; rs += p; }
            #pragma unroll
            for (int off = 8; off; off >>= 1) rs += __shfl_xor_sync(0xffffffffu, rs, off);
            l_run[i] = l_run[i] * alpha + rs;
            m_run[i] = mnew;
            #pragma unroll
            for (int e = 0; e < 8; e++) o[i][e] *= alpha;
            *(float4*)(Ps + (ty * 4 + i) * 64 + tx * 4) = make_float4(c[i][0], c[i][1], c[i][2], c[i][3]);
        }
        __syncthreads();

        #pragma unroll 4
        for (int tj = 0; tj < 64; tj++) {
            float4 v0 = *(float4*)(Vs + tj * 128 + tx * 8);
            float4 v1 = *(float4*)(Vs + tj * 128 + tx * 8 + 4);
            #pragma unroll
            for (int i = 0; i < 4; i++) {
                float p = Ps[(ty * 4 + i) * 64 + tj];
                o[i][0] += p * v0.x; o[i][1] += p * v0.y; o[i][2] += p * v0.z; o[i][3] += p * v0.w;
                o[i][4] += p * v1.x; o[i][5] += p * v1.y; o[i][6] += p * v1.z; o[i][7] += p * v1.w;
            }
        }
    }

    // write to att3 layout (inverse raw reshape)
    const int b_ = bh >> 3;
    #pragma unroll
    for (int i = 0; i < 4; i++) {
        float inv = 1.0f / l_run[i];
        int sg = s0 + ty * 4 + i;
        int sp = h * 128 + (sg >> 3);
        int fp = ((sg & 7) << 7) + tx * 8;
        float* dst = g_att + ((size_t)b_ * 1024 + sp) * 1024 + fp;
        *(float4*)dst       = make_float4(o[i][0] * inv, o[i][1] * inv, o[i][2] * inv, o[i][3] * inv);
        *(float4*)(dst + 4) = make_float4(o[i][4] * inv, o[i][5] * inv, o[i][6] * inv, o[i][7] * inv);
    }
}

// ---------------- fused MLP + residual + LayerNorm ----------------
// y = att3 @ w_mlp + x ; LN over last dim (128). 64 rows per block.
__global__ __launch_bounds__(256) void mlp_ln_kernel(const float* __restrict__ X,
                                                     const float* __restrict__ Wm,
                                                     const float* __restrict__ gamma,
                                                     const float* __restrict__ beta,
                                                     float* __restrict__ out)
{
    __shared__ float At[64][32];
    __shared__ float Wt[32][128];
    const int m0 = blockIdx.x * 64;
    const int tid = threadIdx.x;
    const int tx = tid & 15, ty = tid >> 4;

    float acc[4][8] = {};

    for (int k0 = 0; k0 < 1024; k0 += 32) {
        __syncthreads();
        #pragma unroll
        for (int i = 0; i < 2; i++) {   // At: 64x32 = 512 float4
            int f = tid + i * 256;
            int row = f >> 3;
            int col = (f & 7) << 2;
            *(float4*)(&At[row][col]) = *(const float4*)(g_att + (size_t)(m0 + row) * 1024 + k0 + col);
        }
        #pragma unroll
        for (int i = 0; i < 4; i++) {   // Wt: 32x128 = 1024 float4
            int f = tid + i * 256;
            int row = f >> 5;
            int col = (f & 31) << 2;
            *(float4*)(&Wt[row][col]) = *(const float4*)(Wm + (size_t)(k0 + row) * 128 + col);
        }
        __syncthreads();

        #pragma unroll
        for (int k4 = 0; k4 < 8; k4++) {
            float4 a[4];
            #pragma unroll
            for (int i = 0; i < 4; i++) a[i] = *(float4*)&At[ty * 4 + i][k4 * 4];
            float ws[4][8];
            #pragma unroll
            for (int kk = 0; kk < 4; kk++) {
                float4 u = *(float4*)&Wt[k4 * 4 + kk][tx * 8];
                float4 v = *(float4*)&Wt[k4 * 4 + kk][tx * 8 + 4];
                ws[kk][0] = u.x; ws[kk][1] = u.y; ws[kk][2] = u.z; ws[kk][3] = u.w;
                ws[kk][4] = v.x; ws[kk][5] = v.y; ws[kk][6] = v.z; ws[kk][7] = v.w;
            }
            #pragma unroll
            for (int i = 0; i < 4; i++)
                #pragma unroll
                for (int j = 0; j < 8; j++)
                    acc[i][j] += a[i].x * ws[0][j] + a[i].y * ws[1][j] + a[i].z * ws[2][j] + a[i].w * ws[3][j];
        }
    }

    float gj[8], bj[8];
    #pragma unroll
    for (int j = 0; j < 8; j++) { gj[j] = gamma[tx * 8 + j]; bj[j] = beta[tx * 8 + j]; }

    #pragma unroll
    for (int i = 0; i < 4; i++) {
        int r = m0 + ty * 4 + i;
        float y[8];
        float s = 0.f;
        #pragma unroll
        for (int j = 0; j < 8; j++) {
            y[j] = acc[i][j] + X[(size_t)r * 128 + tx * 8 + j];
            s += y[j];
        }
        #pragma unroll
        for (int off = 8; off; off >>= 1) s += __shfl_xor_sync(0xffffffffu, s, off);
        float mu = s * (1.0f / 128.0f);
        float vs = 0.f;
        #pragma unroll
        for (int j = 0; j < 8; j++) { float d = y[j] - mu; vs += d * d; }
        #pragma unroll
        for (int off = 8; off; off >>= 1) vs += __shfl_xor_sync(0xffffffffu, vs, off);
        float inv = rsqrtf(vs * (1.0f / 128.0f) + 1e-5f);
        #pragma unroll
        for (int j = 0; j < 8; j++)
            out[(size_t)r * 128 + tx * 8 + j] = (y[j] - mu) * inv * gj[j] + bj[j];
    }
}

// ---------------- launch ----------------
extern "C" void kernel_launch(void* const* d_in, const int* in_sizes, int n_in,
                              void* d_out, int out_size)
{
    const float* x     = (const float*)d_in[0];
    const float* memp  = (const float*)d_in[1];
    // d_in[2] = att_mask (unused by reference)
    const float* u1    = (const float*)d_in[3];
    const float* u2    = (const float*)d_in[4];
    const float* w_q   = (const float*)d_in[5];
    const float* w_kv  = (const float*)d_in[6];
    const float* w_r   = (const float*)d_in[7];
    const float* w_mlp = (const float*)d_in[8];
    const float* ln_g  = (const float*)d_in[9];
    const float* ln_b  = (const float*)d_in[10];
    float* out = (float*)d_out;

    static const size_t attn_smem = (64 * 128 * 3 + 127 * 128 + 64 * 64 + 64) * sizeof(float); // 179,968 B
    cudaFuncSetAttribute(attn_kernel, cudaFuncAttributeMaxDynamicSharedMemorySize, (int)attn_smem);

    proj_kernel<0><<<dim3(16, 64), 256>>>(x, nullptr, w_q, 1024);
    proj_kernel<1><<<dim3(32, 128), 256>>>(x, memp, w_kv, 2048);
    proj_kernel<2><<<dim3(16, 32), 256>>>(nullptr, nullptr, w_r, 1024);
    udot_kernel<<<8192, 256>>>(u1, 0, NB * NH * TOT);
    udot_kernel<<<2048, 256>>>(u2, 1, NH * TOT);
    attn_kernel<<<dim3(16, 32), 256, attn_smem>>>();
    mlp_ln_kernel<<<64, 256>>>(x, w_mlp, ln_g, ln_b, out);
}

// round 2
// speedup vs baseline: 1.0008x; 1.0008x over previous
#include <cuda_runtime.h>
#include <math.h>

#define NB 4
#define NH 8
#define SEGL 1024
#define MEML 1024
#define TOT 2048
#define DD 128

// ---------------- scratch (device globals; no allocations) ----------------
__device__ float g_q[NB*NH*SEGL*DD];      // 16 MB  [b][h][s][e]
__device__ float g_k[NB*NH*TOT*DD];       // 32 MB  [b][h][t][e]
__device__ float g_v[NB*NH*TOT*DD];       // 32 MB  [b][h][t][e]
__device__ float g_r[NH*TOT*DD];          //  8 MB  [h][t][e]
__device__ float g_u1k[NB*NH*TOT];        // 256 KB [b][h][t]
__device__ float g_u2r[NH*TOT];           //  64 KB [h][t]
__device__ float g_att[NB*SEGL*NH*DD];    // 16 MB  att3 layout (4,1024,1024)

// ---------------- projection GEMMs with scatter epilogue ----------------
// C(M x N) = A(M x 128) @ W(128 x N), tile 64x64, K staged in 2 chunks of 64.
// MODE 0: q-proj  (A = x rows, M=4096,  N=1024)
// MODE 1: kv-proj (A = concat(mem,x),   M=8192,  N=2048)
// MODE 2: r-proj  (A = sinusoid pos,    M=2048,  N=1024)
template<int MODE>
__global__ __launch_bounds__(256) void proj_kernel(const float* __restrict__ X,
                                                   const float* __restrict__ MEMI,
                                                   const float* __restrict__ W, int N)
{
    __shared__ float As[64][64];
    __shared__ float Bs[64][64];
    const int m0 = blockIdx.y * 64;
    const int n0 = blockIdx.x * 64;
    const int tid = threadIdx.x;
    const int tx = tid & 15, ty = tid >> 4;

    float c[4][4] = {};

    for (int k0 = 0; k0 < 128; k0 += 64) {
        __syncthreads();
        // load A half-tile: 64 rows x 64 k (1024 float4, 4 per thread)
        #pragma unroll
        for (int i = 0; i < 4; i++) {
            int f = tid + i * 256;
            int row = f >> 4;
            int col = (f & 15) << 2;
            int m = m0 + row;
            float4 a;
            if (MODE == 0) {
                a = *(const float4*)(X + (size_t)m * 128 + k0 + col);
            } else if (MODE == 1) {
                int bb = m >> 11, sp = m & 2047;
                const float* src = (sp < 1024) ? (MEMI + ((size_t)bb * 1024 + sp) * 128)
                                               : (X    + ((size_t)bb * 1024 + sp - 1024) * 128);
                a = *(const float4*)(src + k0 + col);
            } else {
                float pp = (float)(2047 - m);
                float vv[4];
                #pragma unroll
                for (int cc = 0; cc < 4; cc++) {
                    int e = k0 + col + cc;
                    float ang = pp / powf(10000.0f, (float)(2 * e) * (1.0f / 128.0f));
                    vv[cc] = ((e & 1) == 0) ? sinf(ang) : cosf(ang);
                }
                a = make_float4(vv[0], vv[1], vv[2], vv[3]);
            }
            *(float4*)(&As[row][col]) = a;
        }
        // load B half-tile: 64 k-rows x 64 n
        #pragma unroll
        for (int i = 0; i < 4; i++) {
            int f = tid + i * 256;
            int krow = f >> 4;
            int nv = (f & 15) << 2;
            *(float4*)(&Bs[krow][nv]) = *(const float4*)(W + (size_t)(k0 + krow) * N + n0 + nv);
        }
        __syncthreads();

        #pragma unroll
        for (int k4 = 0; k4 < 16; k4++) {
            float4 a[4], b[4];
            #pragma unroll
            for (int i = 0; i < 4; i++) a[i] = *(float4*)&As[ty * 4 + i][k4 * 4];
            #pragma unroll
            for (int j = 0; j < 4; j++) b[j] = *(float4*)&Bs[k4 * 4 + j][tx * 4];
            #pragma unroll
            for (int i = 0; i < 4; i++) {
                c[i][0] += a[i].x*b[0].x + a[i].y*b[1].x + a[i].z*b[2].x + a[i].w*b[3].x;
                c[i][1] += a[i].x*b[0].y + a[i].y*b[1].y + a[i].z*b[2].y + a[i].w*b[3].y;
                c[i][2] += a[i].x*b[0].z + a[i].y*b[1].z + a[i].z*b[2].z + a[i].w*b[3].z;
                c[i][3] += a[i].x*b[0].w + a[i].y*b[1].w + a[i].z*b[2].w + a[i].w*b[3].w;
            }
        }
    }

    // scatter epilogue per raw-reshape semantics
    const int fp = n0 + tx * 4;
    #pragma unroll
    for (int i = 0; i < 4; i++) {
        int m = m0 + ty * 4 + i;
        float4 val = make_float4(c[i][0], c[i][1], c[i][2], c[i][3]);
        if (MODE == 0) {
            int b_ = m >> 10, sp = m & 1023;
            int h = sp >> 7;
            int s = ((sp & 127) << 3) + (fp >> 7);
            int e = fp & 127;
            *(float4*)(g_q + ((((size_t)b_ * 8 + h) * 1024 + s) << 7) + e) = val;
        } else if (MODE == 1) {
            int bb = m >> 11, sp = m & 2047;
            int cc = bb * 2 + (sp >> 10);
            int h = (sp & 1023) >> 7;
            int t = ((sp & 127) << 4) + (fp >> 7);
            int e = fp & 127;
            float* dst = (cc < 4) ? (g_k + ((((size_t)cc * 8 + h) * 2048 + t) << 7) + e)
                                  : (g_v + ((((size_t)(cc - 4) * 8 + h) * 2048 + t) << 7) + e);
            *(float4*)dst = val;
        } else {
            int h = m >> 8;
            int t = ((m & 255) << 3) + (fp >> 7);
            int e = fp & 127;
            *(float4*)(g_r + (((size_t)h * 2048 + t) << 7) + e) = val;
        }
    }
}

// ---------------- u1·k and u2·r (warp per 128-dot) ----------------
__global__ __launch_bounds__(256) void udot_kernel(const float* __restrict__ U, int which, int nrows)
{
    int row = blockIdx.x * 8 + (threadIdx.x >> 5);
    int lane = threadIdx.x & 31;
    if (row >= nrows) return;
    const float* Mat = which ? g_r : g_k;
    float* Out = which ? g_u2r : g_u1k;
    int h = (row >> 11) & 7;
    float4 u = *(const float4*)(U + h * 128 + lane * 4);
    float4 m = *(const float4*)(Mat + (size_t)row * 128 + lane * 4);
    float s = u.x * m.x + u.y * m.y + u.z * m.z + u.w * m.w;
    #pragma unroll
    for (int o = 16; o; o >>= 1) s += __shfl_xor_sync(0xffffffffu, s, o);
    if (lane == 0) Out[row] = s;
}

// ---------------- fused flash attention with relative-position band ----------------
// grid (16 s-tiles, 32 bh), 256 threads, 64x64 tiles, 4x4 register fragments.
__global__ __launch_bounds__(256, 1) void attn_kernel()
{
    extern __shared__ float sm[];
    float* Qs = sm;               // 64*128
    float* Ks = Qs + 64 * 128;    // 64*128
    float* Vs = Ks + 64 * 128;    // 64*128
    float* Rs = Vs + 64 * 128;    // 127*128
    float* Ps = Rs + 127 * 128;   // 64*64
    float* bias = Ps + 64 * 64;   // 64

    const int s0 = blockIdx.x * 64;
    const int bh = blockIdx.y;
    const int h = bh & 7;
    const int tid = threadIdx.x;
    const int tx = tid & 15, ty = tid >> 4;

    const float* qbase = g_q + (size_t)bh * (1024 * 128);
    const float* kbase = g_k + (size_t)bh * (2048 * 128);
    const float* vbase = g_v + (size_t)bh * (2048 * 128);
    const float* rbase = g_r + (size_t)h * (2048 * 128);

    #pragma unroll
    for (int i = 0; i < 8; i++) {
        int f = tid + i * 256;
        int row = f >> 5, col = (f & 31) << 2;
        *(float4*)(Qs + row * 128 + col) = *(const float4*)(qbase + (size_t)(s0 + row) * 128 + col);
    }

    float m_run[4], l_run[4], o[4][8];
    #pragma unroll
    for (int i = 0; i < 4; i++) {
        m_run[i] = -1e30f; l_run[i] = 0.f;
        #pragma unroll
        for (int e = 0; e < 8; e++) o[i][e] = 0.f;
    }

    const int ntiles = (s0 >> 6) + 17;       // valid t <= s+1024
    const int base_d = tx * 4 - ty * 4 + 60; // diagonal base into Rs (always in [0,120])

    for (int tt = 0; tt < ntiles; tt++) {
        int t0 = tt * 64;
        __syncthreads();
        #pragma unroll
        for (int i = 0; i < 8; i++) {
            int f = tid + i * 256;
            int row = f >> 5, col = (f & 31) << 2;
            *(float4*)(Ks + row * 128 + col) = *(const float4*)(kbase + (size_t)(t0 + row) * 128 + col);
            *(float4*)(Vs + row * 128 + col) = *(const float4*)(vbase + (size_t)(t0 + row) * 128 + col);
        }
        int relbase = t0 - s0 + 960;  // r row for band offset 0 (>=0 always)
        #pragma unroll
        for (int i = 0; i < 16; i++) {
            int f = tid + i * 256;
            if (f < 127 * 32) {
                int row = f >> 5, col = (f & 31) << 2;
                int rel = relbase + row;
                float4 rv = make_float4(0.f, 0.f, 0.f, 0.f);
                if (rel < 2048) rv = *(const float4*)(rbase + (size_t)rel * 128 + col);
                *(float4*)(Rs + row * 128 + col) = rv;
            }
        }
        if (tid < 64) bias[tid] = g_u1k[(size_t)bh * 2048 + t0 + tid] + g_u2r[(size_t)h * 2048 + t0 + tid];
        __syncthreads();

        // scores: q·k + q·r[t-s+1023]  (7 diagonal r-rows per thread)
        float c[4][4] = {};
        #pragma unroll
        for (int k4 = 0; k4 < 32; k4++) {
            float4 q[4], k[4], r[7];
            #pragma unroll
            for (int i = 0; i < 4; i++) q[i] = *(float4*)(Qs + (ty * 4 + i) * 128 + k4 * 4);
            #pragma unroll
            for (int j = 0; j < 4; j++) k[j] = *(float4*)(Ks + (tx * 4 + j) * 128 + k4 * 4);
            #pragma unroll
            for (int d = 0; d < 7; d++) r[d] = *(float4*)(Rs + (base_d + d) * 128 + k4 * 4);
            #pragma unroll
            for (int i = 0; i < 4; i++)
                #pragma unroll
                for (int j = 0; j < 4; j++) {
                    float4 rr = r[j - i + 3];
                    c[i][j] += q[i].x * (k[j].x + rr.x) + q[i].y * (k[j].y + rr.y)
                             + q[i].z * (k[j].z + rr.z) + q[i].w * (k[j].w + rr.w);
                }
        }

        const float scale = 0.08838834764831843f; // 1/sqrt(128)
        #pragma unroll
        for (int i = 0; i < 4; i++) {
            int sg = s0 + ty * 4 + i;
            #pragma unroll
            for (int j = 0; j < 4; j++) {
                int tg = t0 + tx * 4 + j;
                float v = (c[i][j] + bias[tx * 4 + j]) * scale;
                c[i][j] = (tg - sg <= 1024) ? v : -1e30f;
            }
        }

        #pragma unroll
        for (int i = 0; i < 4; i++) {
            float mt = fmaxf(fmaxf(c[i][0], c[i][1]), fmaxf(c[i][2], c[i][3]));
            #pragma unroll
            for (int off = 8; off; off >>= 1) mt = fmaxf(mt, __shfl_xor_sync(0xffffffffu, mt, off));
            float mnew = fmaxf(m_run[i], mt);
            float alpha = __expf(m_run[i] - mnew);
            float rs = 0.f;
            #pragma unroll
            for (int j = 0; j < 4; j++) { float p = __expf(c[i][j] - mnew); c[i][j] = p; rs += p; }
            #pragma unroll
            for (int off = 8; off; off >>= 1) rs += __shfl_xor_sync(0xffffffffu, rs, off);
            l_run[i] = l_run[i] * alpha + rs;
            m_run[i] = mnew;
            #pragma unroll
            for (int e = 0; e < 8; e++) o[i][e] *= alpha;
            *(float4*)(Ps + (ty * 4 + i) * 64 + tx * 4) = make_float4(c[i][0], c[i][1], c[i][2], c[i][3]);
        }
        __syncthreads();

        #pragma unroll 4
        for (int tj = 0; tj < 64; tj++) {
            float4 v0 = *(float4*)(Vs + tj * 128 + tx * 8);
            float4 v1 = *(float4*)(Vs + tj * 128 + tx * 8 + 4);
            #pragma unroll
            for (int i = 0; i < 4; i++) {
                float p = Ps[(ty * 4 + i) * 64 + tj];
                o[i][0] += p * v0.x; o[i][1] += p * v0.y; o[i][2] += p * v0.z; o[i][3] += p * v0.w;
                o[i][4] += p * v1.x; o[i][5] += p * v1.y; o[i][6] += p * v1.z; o[i][7] += p * v1.w;
            }
        }
    }

    // write to att3 layout (inverse raw reshape)
    const int b_ = bh >> 3;
    #pragma unroll
    for (int i = 0; i < 4; i++) {
        float inv = 1.0f / l_run[i];
        int sg = s0 + ty * 4 + i;
        int sp = h * 128 + (sg >> 3);
        int fp = ((sg & 7) << 7) + tx * 8;
        float* dst = g_att + ((size_t)b_ * 1024 + sp) * 1024 + fp;
        *(float4*)dst       = make_float4(o[i][0] * inv, o[i][1] * inv, o[i][2] * inv, o[i][3] * inv);
        *(float4*)(dst + 4) = make_float4(o[i][4] * inv, o[i][5] * inv, o[i][6] * inv, o[i][7] * inv);
    }
}

// ---------------- fused MLP + residual + LayerNorm ----------------
// y = att3 @ w_mlp + x ; LN over last dim (128). 64 rows per block.
__global__ __launch_bounds__(256) void mlp_ln_kernel(const float* __restrict__ X,
                                                     const float* __restrict__ Wm,
                                                     const float* __restrict__ gamma,
                                                     const float* __restrict__ beta,
                                                     float* __restrict__ out)
{
    __shared__ float At[64][32];
    __shared__ float Wt[32][128];
    const int m0 = blockIdx.x * 64;
    const int tid = threadIdx.x;
    const int tx = tid & 15, ty = tid >> 4;

    float acc[4][8] = {};

    for (int k0 = 0; k0 < 1024; k0 += 32) {
        __syncthreads();
        #pragma unroll
        for (int i = 0; i < 2; i++) {   // At: 64x32 = 512 float4
            int f = tid + i * 256;
            int row = f >> 3;
            int col = (f & 7) << 2;
            *(float4*)(&At[row][col]) = *(const float4*)(g_att + (size_t)(m0 + row) * 1024 + k0 + col);
        }
        #pragma unroll
        for (int i = 0; i < 4; i++) {   // Wt: 32x128 = 1024 float4
            int f = tid + i * 256;
            int row = f >> 5;
            int col = (f & 31) << 2;
            *(float4*)(&Wt[row][col]) = *(const float4*)(Wm + (size_t)(k0 + row) * 128 + col);
        }
        __syncthreads();

        #pragma unroll
        for (int k4 = 0; k4 < 8; k4++) {
            float4 a[4];
            #pragma unroll
            for (int i = 0; i < 4; i++) a[i] = *(float4*)&At[ty * 4 + i][k4 * 4];
            float ws[4][8];
            #pragma unroll
            for (int kk = 0; kk < 4; kk++) {
                float4 u = *(float4*)&Wt[k4 * 4 + kk][tx * 8];
                float4 v = *(float4*)&Wt[k4 * 4 + kk][tx * 8 + 4];
                ws[kk][0] = u.x; ws[kk][1] = u.y; ws[kk][2] = u.z; ws[kk][3] = u.w;
                ws[kk][4] = v.x; ws[kk][5] = v.y; ws[kk][6] = v.z; ws[kk][7] = v.w;
            }
            #pragma unroll
            for (int i = 0; i < 4; i++)
                #pragma unroll
                for (int j = 0; j < 8; j++)
                    acc[i][j] += a[i].x * ws[0][j] + a[i].y * ws[1][j] + a[i].z * ws[2][j] + a[i].w * ws[3][j];
        }
    }

    float gj[8], bj[8];
    #pragma unroll
    for (int j = 0; j < 8; j++) { gj[j] = gamma[tx * 8 + j]; bj[j] = beta[tx * 8 + j]; }

    #pragma unroll
    for (int i = 0; i < 4; i++) {
        int r = m0 + ty * 4 + i;
        float y[8];
        float s = 0.f;
        #pragma unroll
        for (int j = 0; j < 8; j++) {
            y[j] = acc[i][j] + X[(size_t)r * 128 + tx * 8 + j];
            s += y[j];
        }
        #pragma unroll
        for (int off = 8; off; off >>= 1) s += __shfl_xor_sync(0xffffffffu, s, off);
        float mu = s * (1.0f / 128.0f);
        float vs = 0.f;
        #pragma unroll
        for (int j = 0; j < 8; j++) { float d = y[j] - mu; vs += d * d; }
        #pragma unroll
        for (int off = 8; off; off >>= 1) vs += __shfl_xor_sync(0xffffffffu, vs, off);
        float inv = rsqrtf(vs * (1.0f / 128.0f) + 1e-5f);
        #pragma unroll
        for (int j = 0; j < 8; j++)
            out[(size_t)r * 128 + tx * 8 + j] = (y[j] - mu) * inv * gj[j] + bj[j];
    }
}

// ---------------- launch ----------------
extern "C" void kernel_launch(void* const* d_in, const int* in_sizes, int n_in,
                              void* d_out, int out_size)
{
    const float* x     = (const float*)d_in[0];
    const float* memp  = (const float*)d_in[1];
    // d_in[2] = att_mask (unused by reference)
    const float* u1    = (const float*)d_in[3];
    const float* u2    = (const float*)d_in[4];
    const float* w_q   = (const float*)d_in[5];
    const float* w_kv  = (const float*)d_in[6];
    const float* w_r   = (const float*)d_in[7];
    const float* w_mlp = (const float*)d_in[8];
    const float* ln_g  = (const float*)d_in[9];
    const float* ln_b  = (const float*)d_in[10];
    float* out = (float*)d_out;

    static const size_t attn_smem = (64 * 128 * 3 + 127 * 128 + 64 * 64 + 64) * sizeof(float); // 179,968 B
    cudaFuncSetAttribute(attn_kernel, cudaFuncAttributeMaxDynamicSharedMemorySize, (int)attn_smem);

    proj_kernel<0><<<dim3(16, 64), 256>>>(x, nullptr, w_q, 1024);
    proj_kernel<1><<<dim3(32, 128), 256>>>(x, memp, w_kv, 2048);
    proj_kernel<2><<<dim3(16, 32), 256>>>(nullptr, nullptr, w_r, 1024);
    udot_kernel<<<8192, 256>>>(u1, 0, NB * NH * TOT);
    udot_kernel<<<2048, 256>>>(u2, 1, NH * TOT);
    attn_kernel<<<dim3(16, 32), 256, attn_smem>>>();
    mlp_ln_kernel<<<64, 256>>>(x, w_mlp, ln_g, ln_b, out);
}

// round 3
// speedup vs baseline: 3.3969x; 3.3943x over previous
#include <cuda_runtime.h>
#include <math.h>

#define NB 4
#define NH 8
#define SEGL 1024
#define TOT 2048
#define DD 128

// ---------------- scratch (device globals; no allocations) ----------------
__device__ float g_q[NB*NH*SEGL*DD];      // [b][h][s][e]
__device__ float g_k[NB*NH*TOT*DD];       // [b][h][t][e]
__device__ float g_v[NB*NH*TOT*DD];       // [b][h][t][e]
__device__ float g_r[NH*TOT*DD];          // [h][rel][e]
__device__ float g_u1k[NB*NH*TOT];
__device__ float g_u2r[NH*TOT];
__device__ float g_att[NB*SEGL*NH*DD];    // att3 layout (4,1024,1024)
__device__ float g_G[(size_t)NB*NH*SEGL*TOT]; // 268MB: [bh][s][rel] = q.r

// ---------------- f32x2 helpers ----------------
typedef unsigned long long u64t;
__device__ __forceinline__ u64t fma2(u64t a, u64t b, u64t c) {
    u64t d; asm("fma.rn.f32x2 %0, %1, %2, %3;" : "=l"(d) : "l"(a), "l"(b), "l"(c)); return d;
}
__device__ __forceinline__ u64t mul2(u64t a, u64t b) {
    u64t d; asm("mul.rn.f32x2 %0, %1, %2;" : "=l"(d) : "l"(a), "l"(b)); return d;
}
__device__ __forceinline__ u64t pack2(float lo, float hi) {
    u64t d; asm("mov.b64 %0, {%1, %2};" : "=l"(d) : "f"(lo), "f"(hi)); return d;
}
__device__ __forceinline__ float2 unpack2(u64t v) {
    float lo, hi; asm("mov.b64 {%0, %1}, %2;" : "=f"(lo), "=f"(hi) : "l"(v));
    return make_float2(lo, hi);
}

// ---------------- projection GEMMs with scatter epilogue (unchanged, conflict-free) ----------------
template<int MODE>
__global__ __launch_bounds__(256) void proj_kernel(const float* __restrict__ X,
                                                   const float* __restrict__ MEMI,
                                                   const float* __restrict__ W, int N)
{
    __shared__ float As[64][64];
    __shared__ float Bs[64][64];
    const int m0 = blockIdx.y * 64;
    const int n0 = blockIdx.x * 64;
    const int tid = threadIdx.x;
    const int tx = tid & 15, ty = tid >> 4;

    float c[4][4] = {};

    for (int k0 = 0; k0 < 128; k0 += 64) {
        __syncthreads();
        #pragma unroll
        for (int i = 0; i < 4; i++) {
            int f = tid + i * 256;
            int row = f >> 4;
            int col = (f & 15) << 2;
            int m = m0 + row;
            float4 a;
            if (MODE == 0) {
                a = *(const float4*)(X + (size_t)m * 128 + k0 + col);
            } else if (MODE == 1) {
                int bb = m >> 11, sp = m & 2047;
                const float* src = (sp < 1024) ? (MEMI + ((size_t)bb * 1024 + sp) * 128)
                                               : (X    + ((size_t)bb * 1024 + sp - 1024) * 128);
                a = *(const float4*)(src + k0 + col);
            } else {
                float pp = (float)(2047 - m);
                float vv[4];
                #pragma unroll
                for (int cc = 0; cc < 4; cc++) {
                    int e = k0 + col + cc;
                    float ang = pp / powf(10000.0f, (float)(2 * e) * (1.0f / 128.0f));
                    vv[cc] = ((e & 1) == 0) ? sinf(ang) : cosf(ang);
                }
                a = make_float4(vv[0], vv[1], vv[2], vv[3]);
            }
            *(float4*)(&As[row][col]) = a;
        }
        #pragma unroll
        for (int i = 0; i < 4; i++) {
            int f = tid + i * 256;
            int krow = f >> 4;
            int nv = (f & 15) << 2;
            *(float4*)(&Bs[krow][nv]) = *(const float4*)(W + (size_t)(k0 + krow) * N + n0 + nv);
        }
        __syncthreads();

        #pragma unroll
        for (int k4 = 0; k4 < 16; k4++) {
            float4 a[4], b[4];
            #pragma unroll
            for (int i = 0; i < 4; i++) a[i] = *(float4*)&As[ty * 4 + i][k4 * 4];
            #pragma unroll
            for (int j = 0; j < 4; j++) b[j] = *(float4*)&Bs[k4 * 4 + j][tx * 4];
            #pragma unroll
            for (int i = 0; i < 4; i++) {
                c[i][0] += a[i].x*b[0].x + a[i].y*b[1].x + a[i].z*b[2].x + a[i].w*b[3].x;
                c[i][1] += a[i].x*b[0].y + a[i].y*b[1].y + a[i].z*b[2].y + a[i].w*b[3].y;
                c[i][2] += a[i].x*b[0].z + a[i].y*b[1].z + a[i].z*b[2].z + a[i].w*b[3].z;
                c[i][3] += a[i].x*b[0].w + a[i].y*b[1].w + a[i].z*b[2].w + a[i].w*b[3].w;
            }
        }
    }

    const int fp = n0 + tx * 4;
    #pragma unroll
    for (int i = 0; i < 4; i++) {
        int m = m0 + ty * 4 + i;
        float4 val = make_float4(c[i][0], c[i][1], c[i][2], c[i][3]);
        if (MODE == 0) {
            int b_ = m >> 10, sp = m & 1023;
            int h = sp >> 7;
            int s = ((sp & 127) << 3) + (fp >> 7);
            int e = fp & 127;
            *(float4*)(g_q + ((((size_t)b_ * 8 + h) * 1024 + s) << 7) + e) = val;
        } else if (MODE == 1) {
            int bb = m >> 11, sp = m & 2047;
            int cc = bb * 2 + (sp >> 10);
            int h = (sp & 1023) >> 7;
            int t = ((sp & 127) << 4) + (fp >> 7);
            int e = fp & 127;
            float* dst = (cc < 4) ? (g_k + ((((size_t)cc * 8 + h) * 2048 + t) << 7) + e)
                                  : (g_v + ((((size_t)(cc - 4) * 8 + h) * 2048 + t) << 7) + e);
            *(float4*)dst = val;
        } else {
            int h = m >> 8;
            int t = ((m & 255) << 3) + (fp >> 7);
            int e = fp & 127;
            *(float4*)(g_r + (((size_t)h * 2048 + t) << 7) + e) = val;
        }
    }
}

// ---------------- u1·k and u2·r ----------------
__global__ __launch_bounds__(256) void udot_kernel(const float* __restrict__ U, int which, int nrows)
{
    int row = blockIdx.x * 8 + (threadIdx.x >> 5);
    int lane = threadIdx.x & 31;
    if (row >= nrows) return;
    const float* Mat = which ? g_r : g_k;
    float* Out = which ? g_u2r : g_u1k;
    int h = (row >> 11) & 7;
    float4 u = *(const float4*)(U + h * 128 + lane * 4);
    float4 m = *(const float4*)(Mat + (size_t)row * 128 + lane * 4);
    float s = u.x * m.x + u.y * m.y + u.z * m.z + u.w * m.w;
    #pragma unroll
    for (int o = 16; o; o >>= 1) s += __shfl_xor_sync(0xffffffffu, s, o);
    if (lane == 0) Out[row] = s;
}

// ---------------- banded G = q . r GEMM (128s x 64rel tiles, 8x4 frags, f32x2) ----------------
__global__ __launch_bounds__(256, 1) void ggemm_kernel()
{
    extern __shared__ float sm[];
    float* Qs = sm;                 // 128*128 (unpadded: broadcast reads only)
    float* Rs = Qs + 128 * 128;     // 64*130  (padded: per-lane row reads)

    const int rt = blockIdx.x, st = blockIdx.y, bh = blockIdx.z;
    if (rt < 14 - 2 * st) return;   // band skip: rel >= 896 - 128*st
    const int h = bh & 7;
    const int s0 = st * 128, r0 = rt * 64;
    const int tid = threadIdx.x, tx = tid & 15, ty = tid >> 4;

    const float* qb = g_q + (size_t)bh * (1024 * 128);
    const float* rb = g_r + (size_t)h * (2048 * 128);

    #pragma unroll
    for (int i = 0; i < 16; i++) {  // Q: 4096 float4
        int f = tid + i * 256;
        int row = f >> 5, col = (f & 31) << 2;
        *(float4*)(Qs + row * 128 + col) = *(const float4*)(qb + (size_t)(s0 + row) * 128 + col);
    }
    #pragma unroll
    for (int i = 0; i < 16; i++) {  // R: 4096 float2 (stride 130 -> float2 stores for alignment)
        int f = tid + i * 256;
        int row = f >> 6, col = (f & 63) << 1;
        *(float2*)(Rs + row * 130 + col) = *(const float2*)(rb + (size_t)(r0 + row) * 128 + col);
    }
    __syncthreads();

    u64t acc[8][4];
    #pragma unroll
    for (int i = 0; i < 8; i++)
        #pragma unroll
        for (int j = 0; j < 4; j++) acc[i][j] = 0ULL;

    #pragma unroll 8
    for (int k = 0; k < 64; k++) {
        u64t q2[8], r2[4];
        #pragma unroll
        for (int i = 0; i < 8; i++) q2[i] = *(u64t*)(Qs + (ty + 16 * i) * 128 + 2 * k);
        #pragma unroll
        for (int j = 0; j < 4; j++) r2[j] = *(u64t*)(Rs + (tx + 16 * j) * 130 + 2 * k);
        #pragma unroll
        for (int i = 0; i < 8; i++)
            #pragma unroll
            for (int j = 0; j < 4; j++) acc[i][j] = fma2(q2[i], r2[j], acc[i][j]);
    }

    float* Gb = g_G + (size_t)bh * (1024 * 2048);
    #pragma unroll
    for (int i = 0; i < 8; i++) {
        int s = s0 + ty + 16 * i;
        #pragma unroll
        for (int j = 0; j < 4; j++) {
            float2 a = unpack2(acc[i][j]);
            Gb[(size_t)s * 2048 + r0 + tx + 16 * j] = a.x + a.y;
        }
    }
}

// ---------------- flash attention: 128(s) x 64(t) tiles, 8x4 frags, f32x2, conflict-free ----------------
__global__ __launch_bounds__(256, 1) void attn_kernel()
{
    extern __shared__ float sm[];
    float* Qs = sm;                  // 128*128 (broadcast reads)
    float* Ks = Qs + 128 * 128;      // 64*130  (padded per-lane rows)
    float* Vs = Ks + 64 * 130;       // 64*128  (unpadded, column-varying reads)
    float* Ps = Vs + 64 * 128;       // 128*65  (G stage, then P)
    float* bias = Ps + 128 * 65;     // 64

    const int st = blockIdx.x, bh = blockIdx.y, h = bh & 7;
    const int s0 = st * 128;
    const int tid = threadIdx.x, tx = tid & 15, ty = tid >> 4;

    const float* qb = g_q + (size_t)bh * (1024 * 128);
    const float* kb = g_k + (size_t)bh * (2048 * 128);
    const float* vb = g_v + (size_t)bh * (2048 * 128);
    const float* Gb = g_G + (size_t)bh * (1024 * 2048);

    #pragma unroll
    for (int i = 0; i < 16; i++) {
        int f = tid + i * 256;
        int row = f >> 5, col = (f & 31) << 2;
        *(float4*)(Qs + row * 128 + col) = *(const float4*)(qb + (size_t)(s0 + row) * 128 + col);
    }

    u64t o2[8][4];
    float m_[8], l_[8];
    #pragma unroll
    for (int i = 0; i < 8; i++) {
        m_[i] = -1e30f; l_[i] = 0.f;
        #pragma unroll
        for (int c = 0; c < 4; c++) o2[i][c] = 0ULL;
    }

    const int ntiles = 2 * st + 18;
    for (int tt = 0; tt < ntiles; tt++) {
        const int t0 = tt * 64;
        __syncthreads();
        #pragma unroll
        for (int i = 0; i < 16; i++) {   // K: float2 stores (stride-130 alignment)
            int f = tid + i * 256;
            int row = f >> 6, col = (f & 63) << 1;
            *(float2*)(Ks + row * 130 + col) = *(const float2*)(kb + (size_t)(t0 + row) * 128 + col);
        }
        #pragma unroll
        for (int i = 0; i < 8; i++) {    // V: float4
            int f = tid + i * 256;
            int row = f >> 5, col = (f & 31) << 2;
            *(float4*)(Vs + row * 128 + col) = *(const float4*)(vb + (size_t)(t0 + row) * 128 + col);
        }
        const int relbase = t0 - s0 + 1023;
        #pragma unroll
        for (int i = 0; i < 32; i++) {   // stage G band into Ps (coalesced rows)
            int idx = tid + i * 256;
            int row = idx >> 6, col = idx & 63;
            int rel = relbase + col - row;
            Ps[row * 65 + col] = (rel <= 2047) ? Gb[(size_t)(s0 + row) * 2048 + rel] : 0.f;
        }
        if (tid < 64) bias[tid] = g_u1k[(size_t)bh * 2048 + t0 + tid] + g_u2r[(size_t)h * 2048 + t0 + tid];
        __syncthreads();

        // scores: q.k (f32x2), conflict-free
        u64t acc[8][4];
        #pragma unroll
        for (int i = 0; i < 8; i++)
            #pragma unroll
            for (int j = 0; j < 4; j++) acc[i][j] = 0ULL;
        #pragma unroll 8
        for (int k = 0; k < 64; k++) {
            u64t q2[8], k2[4];
            #pragma unroll
            for (int i = 0; i < 8; i++) q2[i] = *(u64t*)(Qs + (ty + 16 * i) * 128 + 2 * k);
            #pragma unroll
            for (int j = 0; j < 4; j++) k2[j] = *(u64t*)(Ks + (tx + 16 * j) * 130 + 2 * k);
            #pragma unroll
            for (int i = 0; i < 8; i++)
                #pragma unroll
                for (int j = 0; j < 4; j++) acc[i][j] = fma2(q2[i], k2[j], acc[i][j]);
        }

        const float scale = 0.08838834764831843f; // 1/sqrt(128)
        float p_[8][4];
        #pragma unroll
        for (int i = 0; i < 8; i++) {
            int sg = s0 + ty + 16 * i;
            #pragma unroll
            for (int j = 0; j < 4; j++) {
                int tg = t0 + tx + 16 * j;
                float2 a = unpack2(acc[i][j]);
                float sc = (a.x + a.y + Ps[(ty + 16 * i) * 65 + tx + 16 * j] + bias[tx + 16 * j]) * scale;
                p_[i][j] = (tg - sg <= 1024) ? sc : -1e30f;
            }
        }

        // online softmax (row group = half-warp, same ty)
        #pragma unroll
        for (int i = 0; i < 8; i++) {
            float mt = fmaxf(fmaxf(p_[i][0], p_[i][1]), fmaxf(p_[i][2], p_[i][3]));
            #pragma unroll
            for (int off = 8; off; off >>= 1) mt = fmaxf(mt, __shfl_xor_sync(0xffffffffu, mt, off));
            float mnew = fmaxf(m_[i], mt);
            float al = __expf(m_[i] - mnew);
            float rs = 0.f;
            #pragma unroll
            for (int j = 0; j < 4; j++) { float e = __expf(p_[i][j] - mnew); p_[i][j] = e; rs += e; }
            #pragma unroll
            for (int off = 8; off; off >>= 1) rs += __shfl_xor_sync(0xffffffffu, rs, off);
            l_[i] = l_[i] * al + rs;
            m_[i] = mnew;
            u64t a2 = pack2(al, al);
            #pragma unroll
            for (int c = 0; c < 4; c++) o2[i][c] = mul2(o2[i][c], a2);
            #pragma unroll
            for (int j = 0; j < 4; j++) Ps[(ty + 16 * i) * 65 + tx + 16 * j] = p_[i][j];
        }
        __syncthreads();

        // PV: p broadcast, v column-sliced (bank-clean), f32x2
        #pragma unroll 4
        for (int tj = 0; tj < 64; tj++) {
            u64t v2[4];
            #pragma unroll
            for (int c = 0; c < 4; c++) v2[c] = *(u64t*)(Vs + tj * 128 + 2 * tx + 32 * c);
            #pragma unroll
            for (int i = 0; i < 8; i++) {
                float p = Ps[(ty + 16 * i) * 65 + tj];
                u64t p2 = pack2(p, p);
                #pragma unroll
                for (int c = 0; c < 4; c++) o2[i][c] = fma2(p2, v2[c], o2[i][c]);
            }
        }
    }

    // epilogue: normalize, write to att3 layout (inverse raw reshape)
    const int b_ = bh >> 3;
    #pragma unroll
    for (int i = 0; i < 8; i++) {
        float inv = 1.0f / l_[i];
        int sg = s0 + ty + 16 * i;
        int sp = h * 128 + (sg >> 3);
        int fp = (sg & 7) << 7;
        float* dst = g_att + ((size_t)b_ * 1024 + sp) * 1024 + fp;
        #pragma unroll
        for (int c = 0; c < 4; c++) {
            float2 v = unpack2(o2[i][c]);
            *(float2*)(dst + 2 * tx + 32 * c) = make_float2(v.x * inv, v.y * inv);
        }
    }
}

// ---------------- fused MLP + residual + LayerNorm (unchanged) ----------------
__global__ __launch_bounds__(256) void mlp_ln_kernel(const float* __restrict__ X,
                                                     const float* __restrict__ Wm,
                                                     const float* __restrict__ gamma,
                                                     const float* __restrict__ beta,
                                                     float* __restrict__ out)
{
    __shared__ float At[64][32];
    __shared__ float Wt[32][128];
    const int m0 = blockIdx.x * 64;
    const int tid = threadIdx.x;
    const int tx = tid & 15, ty = tid >> 4;

    float acc[4][8] = {};

    for (int k0 = 0; k0 < 1024; k0 += 32) {
        __syncthreads();
        #pragma unroll
        for (int i = 0; i < 2; i++) {
            int f = tid + i * 256;
            int row = f >> 3;
            int col = (f & 7) << 2;
            *(float4*)(&At[row][col]) = *(const float4*)(g_att + (size_t)(m0 + row) * 1024 + k0 + col);
        }
        #pragma unroll
        for (int i = 0; i < 4; i++) {
            int f = tid + i * 256;
            int row = f >> 5;
            int col = (f & 31) << 2;
            *(float4*)(&Wt[row][col]) = *(const float4*)(Wm + (size_t)(k0 + row) * 128 + col);
        }
        __syncthreads();

        #pragma unroll
        for (int k4 = 0; k4 < 8; k4++) {
            float4 a[4];
            #pragma unroll
            for (int i = 0; i < 4; i++) a[i] = *(float4*)&At[ty * 4 + i][k4 * 4];
            float ws[4][8];
            #pragma unroll
            for (int kk = 0; kk < 4; kk++) {
                float4 u = *(float4*)&Wt[k4 * 4 + kk][tx * 8];
                float4 v = *(float4*)&Wt[k4 * 4 + kk][tx * 8 + 4];
                ws[kk][0] = u.x; ws[kk][1] = u.y; ws[kk][2] = u.z; ws[kk][3] = u.w;
                ws[kk][4] = v.x; ws[kk][5] = v.y; ws[kk][6] = v.z; ws[kk][7] = v.w;
            }
            #pragma unroll
            for (int i = 0; i < 4; i++)
                #pragma unroll
                for (int j = 0; j < 8; j++)
                    acc[i][j] += a[i].x * ws[0][j] + a[i].y * ws[1][j] + a[i].z * ws[2][j] + a[i].w * ws[3][j];
        }
    }

    float gj[8], bj[8];
    #pragma unroll
    for (int j = 0; j < 8; j++) { gj[j] = gamma[tx * 8 + j]; bj[j] = beta[tx * 8 + j]; }

    #pragma unroll
    for (int i = 0; i < 4; i++) {
        int r = m0 + ty * 4 + i;
        float y[8];
        float s = 0.f;
        #pragma unroll
        for (int j = 0; j < 8; j++) {
            y[j] = acc[i][j] + X[(size_t)r * 128 + tx * 8 + j];
            s += y[j];
        }
        #pragma unroll
        for (int off = 8; off; off >>= 1) s += __shfl_xor_sync(0xffffffffu, s, off);
        float mu = s * (1.0f / 128.0f);
        float vs = 0.f;
        #pragma unroll
        for (int j = 0; j < 8; j++) { float d = y[j] - mu; vs += d * d; }
        #pragma unroll
        for (int off = 8; off; off >>= 1) vs += __shfl_xor_sync(0xffffffffu, vs, off);
        float inv = rsqrtf(vs * (1.0f / 128.0f) + 1e-5f);
        #pragma unroll
        for (int j = 0; j < 8; j++)
            out[(size_t)r * 128 + tx * 8 + j] = (y[j] - mu) * inv * gj[j] + bj[j];
    }
}

// ---------------- launch ----------------
extern "C" void kernel_launch(void* const* d_in, const int* in_sizes, int n_in,
                              void* d_out, int out_size)
{
    const float* x     = (const float*)d_in[0];
    const float* memp  = (const float*)d_in[1];
    const float* u1    = (const float*)d_in[3];
    const float* u2    = (const float*)d_in[4];
    const float* w_q   = (const float*)d_in[5];
    const float* w_kv  = (const float*)d_in[6];
    const float* w_r   = (const float*)d_in[7];
    const float* w_mlp = (const float*)d_in[8];
    const float* ln_g  = (const float*)d_in[9];
    const float* ln_b  = (const float*)d_in[10];
    float* out = (float*)d_out;

    const int ggemm_smem = (128 * 128 + 64 * 130) * 4;                              // 98,816
    const int attn_smem  = (128 * 128 + 64 * 130 + 64 * 128 + 128 * 65 + 64) * 4;   // 165,120
    cudaFuncSetAttribute(ggemm_kernel, cudaFuncAttributeMaxDynamicSharedMemorySize, ggemm_smem);
    cudaFuncSetAttribute(attn_kernel,  cudaFuncAttributeMaxDynamicSharedMemorySize, attn_smem);

    proj_kernel<0><<<dim3(16, 64), 256>>>(x, nullptr, w_q, 1024);
    proj_kernel<1><<<dim3(32, 128), 256>>>(x, memp, w_kv, 2048);
    proj_kernel<2><<<dim3(16, 32), 256>>>(nullptr, nullptr, w_r, 1024);
    udot_kernel<<<8192, 256>>>(u1, 0, NB * NH * TOT);
    udot_kernel<<<2048, 256>>>(u2, 1, NH * TOT);
    ggemm_kernel<<<dim3(32, 8, 32), 256, ggemm_smem>>>();
    attn_kernel<<<dim3(8, 32), 256, attn_smem>>>();
    mlp_ln_kernel<<<64, 256>>>(x, w_mlp, ln_g, ln_b, out);
}

// round 5
// speedup vs baseline: 4.0974x; 1.2062x over previous
#include <cuda_runtime.h>
#include <cuda_bf16.h>
#include <math.h>
#include <stdint.h>

#define NB 4
#define NH 8
#define SEGL 1024
#define TOT 2048
#define DD 128

// ---------------- scratch (device globals; no allocations) ----------------
__device__ float g_q[NB*NH*SEGL*DD];      // [b][h][s][e]
__device__ float g_k[NB*NH*TOT*DD];       // [b][h][t][e]
__device__ float g_v[NB*NH*TOT*DD];       // [b][h][t][e]
__device__ float g_r[NH*TOT*DD];          // [h][rel][e]
__device__ __nv_bfloat16 g_qh[NB*NH*SEGL*DD];  // bf16 hi plane of q
__device__ __nv_bfloat16 g_ql[NB*NH*SEGL*DD];  // bf16 lo plane (residual)
__device__ __nv_bfloat16 g_rh[NH*TOT*DD];
__device__ __nv_bfloat16 g_rl[NH*TOT*DD];
__device__ float g_u1k[NB*NH*TOT];
__device__ float g_u2r[NH*TOT];
__device__ float g_att[NB*SEGL*NH*DD];    // att3 layout (4,1024,1024)
__device__ float g_G[(size_t)NB*NH*SEGL*TOT]; // 268MB: [bh][s][rel] = q.r

// ---------------- f32x2 / misc helpers ----------------
typedef unsigned long long u64t;
__device__ __forceinline__ u64t fma2(u64t a, u64t b, u64t c) {
    u64t d; asm("fma.rn.f32x2 %0, %1, %2, %3;" : "=l"(d) : "l"(a), "l"(b), "l"(c)); return d;
}
__device__ __forceinline__ u64t mul2(u64t a, u64t b) {
    u64t d; asm("mul.rn.f32x2 %0, %1, %2;" : "=l"(d) : "l"(a), "l"(b)); return d;
}
__device__ __forceinline__ u64t pack2(float lo, float hi) {
    u64t d; asm("mov.b64 %0, {%1, %2};" : "=l"(d) : "f"(lo), "f"(hi)); return d;
}
__device__ __forceinline__ float2 unpack2(u64t v) {
    float lo, hi; asm("mov.b64 {%0, %1}, %2;" : "=f"(lo), "=f"(hi) : "l"(v));
    return make_float2(lo, hi);
}
__device__ __forceinline__ uint32_t smem_u32(const void* p) {
    uint32_t a;
    asm("{ .reg .u64 t; cvta.to.shared.u64 t, %1; cvt.u32.u64 %0, t; }" : "=r"(a) : "l"(p));
    return a;
}

// ---------------- mma.sync / ldmatrix (compute_103-safe, sm_80-era PTX) ----------------
#define LDSM_X4(r, addr) \
    asm volatile("ldmatrix.sync.aligned.m8n8.x4.shared.b16 {%0,%1,%2,%3}, [%4];" \
        : "=r"((r)[0]), "=r"((r)[1]), "=r"((r)[2]), "=r"((r)[3]) : "r"(addr))
#define LDSM_X2(r, addr) \
    asm volatile("ldmatrix.sync.aligned.m8n8.x2.shared.b16 {%0,%1}, [%2];" \
        : "=r"((r)[0]), "=r"((r)[1]) : "r"(addr))
#define MMA_BF16(c, a, b) \
    asm volatile("mma.sync.aligned.m16n8k16.row.col.f32.bf16.bf16.f32 " \
        "{%0,%1,%2,%3}, {%4,%5,%6,%7}, {%8,%9}, {%0,%1,%2,%3};" \
        : "+f"((c)[0]), "+f"((c)[1]), "+f"((c)[2]), "+f"((c)[3]) \
        : "r"((a)[0]), "r"((a)[1]), "r"((a)[2]), "r"((a)[3]), "r"((b)[0]), "r"((b)[1]))

// bf16 hi/lo split of a float4 -> two ushort4
__device__ __forceinline__ void split4_bf16(float4 v, ushort4& hv, ushort4& lv) {
    __nv_bfloat16 b;
    b = __float2bfloat16(v.x); hv.x = __bfloat16_as_ushort(b);
    lv.x = __bfloat16_as_ushort(__float2bfloat16(v.x - __bfloat162float(b)));
    b = __float2bfloat16(v.y); hv.y = __bfloat16_as_ushort(b);
    lv.y = __bfloat16_as_ushort(__float2bfloat16(v.y - __bfloat162float(b)));
    b = __float2bfloat16(v.z); hv.z = __bfloat16_as_ushort(b);
    lv.z = __bfloat16_as_ushort(__float2bfloat16(v.z - __bfloat162float(b)));
    b = __float2bfloat16(v.w); hv.w = __bfloat16_as_ushort(b);
    lv.w = __bfloat16_as_ushort(__float2bfloat16(v.w - __bfloat162float(b)));
}

// ---------------- projection GEMMs (R3-proven inner loop; bf16 hi/lo epilogue) ----------------
template<int MODE>
__global__ __launch_bounds__(256) void proj_kernel(const float* __restrict__ X,
                                                   const float* __restrict__ MEMI,
                                                   const float* __restrict__ W, int N)
{
    __shared__ float As[64][64];
    __shared__ float Bs[64][64];
    const int m0 = blockIdx.y * 64;
    const int n0 = blockIdx.x * 64;
    const int tid = threadIdx.x;
    const int tx = tid & 15, ty = tid >> 4;

    float c[4][4] = {};

    for (int k0 = 0; k0 < 128; k0 += 64) {
        __syncthreads();
        #pragma unroll
        for (int i = 0; i < 4; i++) {
            int f = tid + i * 256;
            int row = f >> 4;
            int col = (f & 15) << 2;
            int m = m0 + row;
            float4 a;
            if (MODE == 0) {
                a = *(const float4*)(X + (size_t)m * 128 + k0 + col);
            } else if (MODE == 1) {
                int bb = m >> 11, sp = m & 2047;
                const float* src = (sp < 1024) ? (MEMI + ((size_t)bb * 1024 + sp) * 128)
                                               : (X    + ((size_t)bb * 1024 + sp - 1024) * 128);
                a = *(const float4*)(src + k0 + col);
            } else {
                float pp = (float)(2047 - m);
                float vv[4];
                #pragma unroll
                for (int cc = 0; cc < 4; cc++) {
                    int e = k0 + col + cc;
                    float ang = pp / powf(10000.0f, (float)(2 * e) * (1.0f / 128.0f));
                    vv[cc] = ((e & 1) == 0) ? sinf(ang) : cosf(ang);
                }
                a = make_float4(vv[0], vv[1], vv[2], vv[3]);
            }
            *(float4*)(&As[row][col]) = a;
        }
        #pragma unroll
        for (int i = 0; i < 4; i++) {
            int f = tid + i * 256;
            int krow = f >> 4;
            int nv = (f & 15) << 2;
            *(float4*)(&Bs[krow][nv]) = *(const float4*)(W + (size_t)(k0 + krow) * N + n0 + nv);
        }
        __syncthreads();

        #pragma unroll
        for (int k4 = 0; k4 < 16; k4++) {
            float4 a[4], b[4];
            #pragma unroll
            for (int i = 0; i < 4; i++) a[i] = *(float4*)&As[ty * 4 + i][k4 * 4];
            #pragma unroll
            for (int j = 0; j < 4; j++) b[j] = *(float4*)&Bs[k4 * 4 + j][tx * 4];
            #pragma unroll
            for (int i = 0; i < 4; i++) {
                c[i][0] += a[i].x*b[0].x + a[i].y*b[1].x + a[i].z*b[2].x + a[i].w*b[3].x;
                c[i][1] += a[i].x*b[0].y + a[i].y*b[1].y + a[i].z*b[2].y + a[i].w*b[3].y;
                c[i][2] += a[i].x*b[0].z + a[i].y*b[1].z + a[i].z*b[2].z + a[i].w*b[3].z;
                c[i][3] += a[i].x*b[0].w + a[i].y*b[1].w + a[i].z*b[2].w + a[i].w*b[3].w;
            }
        }
    }

    const int fp = n0 + tx * 4;
    #pragma unroll
    for (int i = 0; i < 4; i++) {
        int m = m0 + ty * 4 + i;
        float4 val = make_float4(c[i][0], c[i][1], c[i][2], c[i][3]);
        if (MODE == 0) {
            int b_ = m >> 10, sp = m & 1023;
            int h = sp >> 7;
            int s = ((sp & 127) << 3) + (fp >> 7);
            int e = fp & 127;
            size_t off = ((((size_t)b_ * 8 + h) * 1024 + s) << 7) + e;
            *(float4*)(g_q + off) = val;
            ushort4 hv, lv;
            split4_bf16(val, hv, lv);
            *(ushort4*)(g_qh + off) = hv;
            *(ushort4*)(g_ql + off) = lv;
        } else if (MODE == 1) {
            int bb = m >> 11, sp = m & 2047;
            int cc = bb * 2 + (sp >> 10);
            int h = (sp & 1023) >> 7;
            int t = ((sp & 127) << 4) + (fp >> 7);
            int e = fp & 127;
            float* dst = (cc < 4) ? (g_k + ((((size_t)cc * 8 + h) * 2048 + t) << 7) + e)
                                  : (g_v + ((((size_t)(cc - 4) * 8 + h) * 2048 + t) << 7) + e);
            *(float4*)dst = val;
        } else {
            int h = m >> 8;
            int t = ((m & 255) << 3) + (fp >> 7);
            int e = fp & 127;
            size_t off = (((size_t)h * 2048 + t) << 7) + e;
            *(float4*)(g_r + off) = val;
            ushort4 hv, lv;
            split4_bf16(val, hv, lv);
            *(ushort4*)(g_rh + off) = hv;
            *(ushort4*)(g_rl + off) = lv;
        }
    }
}

// ---------------- u1·k and u2·r ----------------
__global__ __launch_bounds__(256) void udot_kernel(const float* __restrict__ U, int which, int nrows)
{
    int row = blockIdx.x * 8 + (threadIdx.x >> 5);
    int lane = threadIdx.x & 31;
    if (row >= nrows) return;
    const float* Mat = which ? g_r : g_k;
    float* Out = which ? g_u2r : g_u1k;
    int h = (row >> 11) & 7;
    float4 u = *(const float4*)(U + h * 128 + lane * 4);
    float4 m = *(const float4*)(Mat + (size_t)row * 128 + lane * 4);
    float s = u.x * m.x + u.y * m.y + u.z * m.z + u.w * m.w;
    #pragma unroll
    for (int o = 16; o; o >>= 1) s += __shfl_xor_sync(0xffffffffu, s, o);
    if (lane == 0) Out[row] = s;
}

// ---------------- banded G = q.r via bf16 mma.sync (3-term split) ----------------
// Tile: D[128 s][64 rel]. 8 warps as 4(m)x2(n): each warp 32m x 32n.
// smem bf16 stride 136 (272B rows: LDSM-conflict-free, 16B aligned).
__global__ __launch_bounds__(256, 2) void ggemm_mma_kernel()
{
    extern __shared__ __align__(16) unsigned short sm16[];
    unsigned short* Qh = sm16;              // 128*136
    unsigned short* Ql = Qh + 128 * 136;
    unsigned short* Rh = Ql + 128 * 136;    // 64*136
    unsigned short* Rl = Rh + 64 * 136;

    const int rt = blockIdx.x, st = blockIdx.y, bh = blockIdx.z;
    if (rt < 14 - 2 * st) return;           // band skip (proven in R3)
    const int h = bh & 7;
    const int s0 = st * 128, r0 = rt * 64;
    const int tid = threadIdx.x, wid = tid >> 5, lane = tid & 31;

    // stage Q hi/lo (128 x 128 bf16 each)
    const unsigned short* qh = (const unsigned short*)g_qh + ((size_t)bh * 1024 + s0) * 128;
    const unsigned short* ql = (const unsigned short*)g_ql + ((size_t)bh * 1024 + s0) * 128;
    #pragma unroll
    for (int i = 0; i < 8; i++) {
        int f = tid + i * 256;              // 2048 uint4 per array
        int row = f >> 4, c8 = (f & 15) << 3;
        *(uint4*)(Qh + row * 136 + c8) = *(const uint4*)(qh + (size_t)row * 128 + c8);
        *(uint4*)(Ql + row * 136 + c8) = *(const uint4*)(ql + (size_t)row * 128 + c8);
    }
    // stage R hi/lo (64 x 128 bf16 each)
    const unsigned short* rh = (const unsigned short*)g_rh + ((size_t)h * 2048 + r0) * 128;
    const unsigned short* rl = (const unsigned short*)g_rl + ((size_t)h * 2048 + r0) * 128;
    #pragma unroll
    for (int i = 0; i < 4; i++) {
        int f = tid + i * 256;              // 1024 uint4 per array
        int row = f >> 4, c8 = (f & 15) << 3;
        *(uint4*)(Rh + row * 136 + c8) = *(const uint4*)(rh + (size_t)row * 128 + c8);
        *(uint4*)(Rl + row * 136 + c8) = *(const uint4*)(rl + (size_t)row * 128 + c8);
    }
    __syncthreads();

    const int wm = (wid >> 1) * 32;         // 4 m-warps
    const int wn = (wid & 1) * 32;          // 2 n-warps

    float c[2][4][4];
    #pragma unroll
    for (int mt = 0; mt < 2; mt++)
        #pragma unroll
        for (int nt = 0; nt < 4; nt++)
            #pragma unroll
            for (int e = 0; e < 4; e++) c[mt][nt][e] = 0.f;

    // ldmatrix lane addressing
    const int arow = (lane & 7) + ((lane >> 3) & 1) * 8;   // + matrix pair row
    const int akoff = (lane >> 4) * 16;                    // bytes: matrices 2,3 -> k+8
    const int brow = lane & 7;
    const int bkoff = ((lane >> 3) & 1) * 16;

    const uint32_t qh_b = smem_u32(Qh), ql_b = smem_u32(Ql);
    const uint32_t rh_b = smem_u32(Rh), rl_b = smem_u32(Rl);

    #pragma unroll
    for (int ks = 0; ks < 8; ks++) {
        uint32_t ah[2][4], al[2][4];
        #pragma unroll
        for (int mt = 0; mt < 2; mt++) {
            uint32_t off = (uint32_t)((wm + mt * 16 + arow) * 272 + ks * 32 + akoff);
            LDSM_X4(ah[mt], qh_b + off);
            LDSM_X4(al[mt], ql_b + off);
        }
        uint32_t bhf[4][2], blf[4][2];
        #pragma unroll
        for (int nt = 0; nt < 4; nt++) {
            uint32_t off = (uint32_t)((wn + nt * 8 + brow) * 272 + ks * 32 + bkoff);
            LDSM_X2(bhf[nt], rh_b + off);
            LDSM_X2(blf[nt], rl_b + off);
        }
        #pragma unroll
        for (int mt = 0; mt < 2; mt++)
            #pragma unroll
            for (int nt = 0; nt < 4; nt++) {
                MMA_BF16(c[mt][nt], ah[mt], bhf[nt]);
                MMA_BF16(c[mt][nt], ah[mt], blf[nt]);
                MMA_BF16(c[mt][nt], al[mt], bhf[nt]);
            }
    }

    // epilogue: write D tiles to g_G
    const int gp = lane >> 2, tg = lane & 3;
    float* Gb = g_G + (size_t)bh * (1024 * 2048);
    #pragma unroll
    for (int mt = 0; mt < 2; mt++) {
        int mrow = s0 + wm + mt * 16 + gp;
        #pragma unroll
        for (int nt = 0; nt < 4; nt++) {
            int n = r0 + wn + nt * 8 + 2 * tg;
            *(float2*)(Gb + (size_t)mrow * 2048 + n)       = make_float2(c[mt][nt][0], c[mt][nt][1]);
            *(float2*)(Gb + (size_t)(mrow + 8) * 2048 + n) = make_float2(c[mt][nt][2], c[mt][nt][3]);
        }
    }
}

// ---------------- flash attention (unchanged from R3: conflict-free f32x2) ----------------
__global__ __launch_bounds__(256, 1) void attn_kernel()
{
    extern __shared__ float sm[];
    float* Qs = sm;                  // 128*128
    float* Ks = Qs + 128 * 128;      // 64*130
    float* Vs = Ks + 64 * 130;       // 64*128
    float* Ps = Vs + 64 * 128;       // 128*65
    float* bias = Ps + 128 * 65;     // 64

    const int st = blockIdx.x, bh = blockIdx.y, h = bh & 7;
    const int s0 = st * 128;
    const int tid = threadIdx.x, tx = tid & 15, ty = tid >> 4;

    const float* qb = g_q + (size_t)bh * (1024 * 128);
    const float* kb = g_k + (size_t)bh * (2048 * 128);
    const float* vb = g_v + (size_t)bh * (2048 * 128);
    const float* Gb = g_G + (size_t)bh * (1024 * 2048);

    #pragma unroll
    for (int i = 0; i < 16; i++) {
        int f = tid + i * 256;
        int row = f >> 5, col = (f & 31) << 2;
        *(float4*)(Qs + row * 128 + col) = *(const float4*)(qb + (size_t)(s0 + row) * 128 + col);
    }

    u64t o2[8][4];
    float m_[8], l_[8];
    #pragma unroll
    for (int i = 0; i < 8; i++) {
        m_[i] = -1e30f; l_[i] = 0.f;
        #pragma unroll
        for (int c = 0; c < 4; c++) o2[i][c] = 0ULL;
    }

    const int ntiles = 2 * st + 18;
    for (int tt = 0; tt < ntiles; tt++) {
        const int t0 = tt * 64;
        __syncthreads();
        #pragma unroll
        for (int i = 0; i < 16; i++) {
            int f = tid + i * 256;
            int row = f >> 6, col = (f & 63) << 1;
            *(float2*)(Ks + row * 130 + col) = *(const float2*)(kb + (size_t)(t0 + row) * 128 + col);
        }
        #pragma unroll
        for (int i = 0; i < 8; i++) {
            int f = tid + i * 256;
            int row = f >> 5, col = (f & 31) << 2;
            *(float4*)(Vs + row * 128 + col) = *(const float4*)(vb + (size_t)(t0 + row) * 128 + col);
        }
        const int relbase = t0 - s0 + 1023;
        #pragma unroll
        for (int i = 0; i < 32; i++) {
            int idx = tid + i * 256;
            int row = idx >> 6, col = idx & 63;
            int rel = relbase + col - row;
            Ps[row * 65 + col] = (rel <= 2047) ? Gb[(size_t)(s0 + row) * 2048 + rel] : 0.f;
        }
        if (tid < 64) bias[tid] = g_u1k[(size_t)bh * 2048 + t0 + tid] + g_u2r[(size_t)h * 2048 + t0 + tid];
        __syncthreads();

        u64t acc[8][4];
        #pragma unroll
        for (int i = 0; i < 8; i++)
            #pragma unroll
            for (int j = 0; j < 4; j++) acc[i][j] = 0ULL;
        #pragma unroll 8
        for (int k = 0; k < 64; k++) {
            u64t q2[8], k2[4];
            #pragma unroll
            for (int i = 0; i < 8; i++) q2[i] = *(u64t*)(Qs + (ty + 16 * i) * 128 + 2 * k);
            #pragma unroll
            for (int j = 0; j < 4; j++) k2[j] = *(u64t*)(Ks + (tx + 16 * j) * 130 + 2 * k);
            #pragma unroll
            for (int i = 0; i < 8; i++)
                #pragma unroll
                for (int j = 0; j < 4; j++) acc[i][j] = fma2(q2[i], k2[j], acc[i][j]);
        }

        const float scale = 0.08838834764831843f;
        float p_[8][4];
        #pragma unroll
        for (int i = 0; i < 8; i++) {
            int sg = s0 + ty + 16 * i;
            #pragma unroll
            for (int j = 0; j < 4; j++) {
                int tg = t0 + tx + 16 * j;
                float2 a = unpack2(acc[i][j]);
                float sc = (a.x + a.y + Ps[(ty + 16 * i) * 65 + tx + 16 * j] + bias[tx + 16 * j]) * scale;
                p_[i][j] = (tg - sg <= 1024) ? sc : -1e30f;
            }
        }

        #pragma unroll
        for (int i = 0; i < 8; i++) {
            float mt = fmaxf(fmaxf(p_[i][0], p_[i][1]), fmaxf(p_[i][2], p_[i][3]));
            #pragma unroll
            for (int off = 8; off; off >>= 1) mt = fmaxf(mt, __shfl_xor_sync(0xffffffffu, mt, off));
            float mnew = fmaxf(m_[i], mt);
            float al = __expf(m_[i] - mnew);
            float rs = 0.f;
            #pragma unroll
            for (int j = 0; j < 4; j++) { float e = __expf(p_[i][j] - mnew); p_[i][j] = e; rs += e; }
            #pragma unroll
            for (int off = 8; off; off >>= 1) rs += __shfl_xor_sync(0xffffffffu, rs, off);
            l_[i] = l_[i] * al + rs;
            m_[i] = mnew;
            u64t a2 = pack2(al, al);
            #pragma unroll
            for (int c = 0; c < 4; c++) o2[i][c] = mul2(o2[i][c], a2);
            #pragma unroll
            for (int j = 0; j < 4; j++) Ps[(ty + 16 * i) * 65 + tx + 16 * j] = p_[i][j];
        }
        __syncthreads();

        #pragma unroll 4
        for (int tj = 0; tj < 64; tj++) {
            u64t v2[4];
            #pragma unroll
            for (int c = 0; c < 4; c++) v2[c] = *(u64t*)(Vs + tj * 128 + 2 * tx + 32 * c);
            #pragma unroll
            for (int i = 0; i < 8; i++) {
                float p = Ps[(ty + 16 * i) * 65 + tj];
                u64t p2 = pack2(p, p);
                #pragma unroll
                for (int c = 0; c < 4; c++) o2[i][c] = fma2(p2, v2[c], o2[i][c]);
            }
        }
    }

    const int b_ = bh >> 3;
    #pragma unroll
    for (int i = 0; i < 8; i++) {
        float inv = 1.0f / l_[i];
        int sg = s0 + ty + 16 * i;
        int sp = h * 128 + (sg >> 3);
        int fp = (sg & 7) << 7;
        float* dst = g_att + ((size_t)b_ * 1024 + sp) * 1024 + fp;
        #pragma unroll
        for (int c = 0; c < 4; c++) {
            float2 v = unpack2(o2[i][c]);
            *(float2*)(dst + 2 * tx + 32 * c) = make_float2(v.x * inv, v.y * inv);
        }
    }
}

// ---------------- fused MLP + residual + LayerNorm ----------------
__global__ __launch_bounds__(256) void mlp_ln_kernel(const float* __restrict__ X,
                                                     const float* __restrict__ Wm,
                                                     const float* __restrict__ gamma,
                                                     const float* __restrict__ beta,
                                                     float* __restrict__ out)
{
    __shared__ float At[64][32];
    __shared__ float Wt[32][128];
    const int m0 = blockIdx.x * 64;
    const int tid = threadIdx.x;
    const int tx = tid & 15, ty = tid >> 4;

    float acc[4][8] = {};

    for (int k0 = 0; k0 < 1024; k0 += 32) {
        __syncthreads();
        #pragma unroll
        for (int i = 0; i < 2; i++) {
            int f = tid + i * 256;
            int row = f >> 3;
            int col = (f & 7) << 2;
            *(float4*)(&At[row][col]) = *(const float4*)(g_att + (size_t)(m0 + row) * 1024 + k0 + col);
        }
        #pragma unroll
        for (int i = 0; i < 4; i++) {
            int f = tid + i * 256;
            int row = f >> 5;
            int col = (f & 31) << 2;
            *(float4*)(&Wt[row][col]) = *(const float4*)(Wm + (size_t)(k0 + row) * 128 + col);
        }
        __syncthreads();

        #pragma unroll
        for (int k4 = 0; k4 < 8; k4++) {
            float4 a[4];
            #pragma unroll
            for (int i = 0; i < 4; i++) a[i] = *(float4*)&At[ty * 4 + i][k4 * 4];
            float ws[4][8];
            #pragma unroll
            for (int kk = 0; kk < 4; kk++) {
                float4 u = *(float4*)&Wt[k4 * 4 + kk][tx * 8];
                float4 v = *(float4*)&Wt[k4 * 4 + kk][tx * 8 + 4];
                ws[kk][0] = u.x; ws[kk][1] = u.y; ws[kk][2] = u.z; ws[kk][3] = u.w;
                ws[kk][4] = v.x; ws[kk][5] = v.y; ws[kk][6] = v.z; ws[kk][7] = v.w;
            }
            #pragma unroll
            for (int i = 0; i < 4; i++)
                #pragma unroll
                for (int j = 0; j < 8; j++)
                    acc[i][j] += a[i].x * ws[0][j] + a[i].y * ws[1][j] + a[i].z * ws[2][j] + a[i].w * ws[3][j];
        }
    }

    float gj[8], bj[8];
    #pragma unroll
    for (int j = 0; j < 8; j++) { gj[j] = gamma[tx * 8 + j]; bj[j] = beta[tx * 8 + j]; }

    #pragma unroll
    for (int i = 0; i < 4; i++) {
        int r = m0 + ty * 4 + i;
        float y[8];
        float s = 0.f;
        #pragma unroll
        for (int j = 0; j < 8; j++) {
            y[j] = acc[i][j] + X[(size_t)r * 128 + tx * 8 + j];
            s += y[j];
        }
        #pragma unroll
        for (int off = 8; off; off >>= 1) s += __shfl_xor_sync(0xffffffffu, s, off);
        float mu = s * (1.0f / 128.0f);
        float vs = 0.f;
        #pragma unroll
        for (int j = 0; j < 8; j++) { float d = y[j] - mu; vs += d * d; }
        #pragma unroll
        for (int off = 8; off; off >>= 1) vs += __shfl_xor_sync(0xffffffffu, vs, off);
        float inv = rsqrtf(vs * (1.0f / 128.0f) + 1e-5f);
        #pragma unroll
        for (int j = 0; j < 8; j++)
            out[(size_t)r * 128 + tx * 8 + j] = (y[j] - mu) * inv * gj[j] + bj[j];
    }
}

// ---------------- launch ----------------
extern "C" void kernel_launch(void* const* d_in, const int* in_sizes, int n_in,
                              void* d_out, int out_size)
{
    const float* x     = (const float*)d_in[0];
    const float* memp  = (const float*)d_in[1];
    const float* u1    = (const float*)d_in[3];
    const float* u2    = (const float*)d_in[4];
    const float* w_q   = (const float*)d_in[5];
    const float* w_kv  = (const float*)d_in[6];
    const float* w_r   = (const float*)d_in[7];
    const float* w_mlp = (const float*)d_in[8];
    const float* ln_g  = (const float*)d_in[9];
    const float* ln_b  = (const float*)d_in[10];
    float* out = (float*)d_out;

    const int ggemm_smem = (128 * 136 * 2 + 64 * 136 * 2) * 2;                      // 104,448 B
    const int attn_smem  = (128 * 128 + 64 * 130 + 64 * 128 + 128 * 65 + 64) * 4;   // 165,120 B
    cudaFuncSetAttribute(ggemm_mma_kernel, cudaFuncAttributeMaxDynamicSharedMemorySize, ggemm_smem);
    cudaFuncSetAttribute(attn_kernel,      cudaFuncAttributeMaxDynamicSharedMemorySize, attn_smem);

    proj_kernel<0><<<dim3(16, 64), 256>>>(x, nullptr, w_q, 1024);
    proj_kernel<1><<<dim3(32, 128), 256>>>(x, memp, w_kv, 2048);
    proj_kernel<2><<<dim3(16, 32), 256>>>(nullptr, nullptr, w_r, 1024);
    udot_kernel<<<8192, 256>>>(u1, 0, NB * NH * TOT);
    udot_kernel<<<2048, 256>>>(u2, 1, NH * TOT);
    ggemm_mma_kernel<<<dim3(32, 8, 32), 256, ggemm_smem>>>();
    attn_kernel<<<dim3(8, 32), 256, attn_smem>>>();
    mlp_ln_kernel<<<64, 256>>>(x, w_mlp, ln_g, ln_b, out);
}

// round 7
// speedup vs baseline: 4.6337x; 1.1309x over previous
#include <cuda_runtime.h>
#include <cuda_bf16.h>
#include <math.h>
#include <stdint.h>

#define NB 4
#define NH 8
#define SEGL 1024
#define TOT 2048
#define DD 128

// ---------------- scratch (device globals; no allocations) ----------------
__device__ float g_k[NB*NH*TOT*DD];       // [b][h][t][e] fp32 (udot)
__device__ float g_v[NB*NH*TOT*DD];       // [b][h][t][e]
__device__ float g_r[NH*TOT*DD];          // [h][rel][e] fp32 (udot)
__device__ __nv_bfloat16 g_qh[NB*NH*SEGL*DD];  // bf16 hi plane of q
__device__ __nv_bfloat16 g_ql[NB*NH*SEGL*DD];  // bf16 lo plane (residual)
__device__ __nv_bfloat16 g_kh[NB*NH*TOT*DD];
__device__ __nv_bfloat16 g_kl[NB*NH*TOT*DD];
__device__ __nv_bfloat16 g_rh[NH*TOT*DD];
__device__ __nv_bfloat16 g_rl[NH*TOT*DD];
__device__ float g_u1k[NB*NH*TOT];
__device__ float g_u2r[NH*TOT];
__device__ float g_att[NB*SEGL*NH*DD];    // att3 layout (4,1024,1024)
__device__ float g_G[(size_t)NB*NH*SEGL*TOT]; // 268MB: [bh][s][rel] = q.r

// ---------------- f32x2 / misc helpers ----------------
typedef unsigned long long u64t;
__device__ __forceinline__ u64t fma2(u64t a, u64t b, u64t c) {
    u64t d; asm("fma.rn.f32x2 %0, %1, %2, %3;" : "=l"(d) : "l"(a), "l"(b), "l"(c)); return d;
}
__device__ __forceinline__ u64t mul2(u64t a, u64t b) {
    u64t d; asm("mul.rn.f32x2 %0, %1, %2;" : "=l"(d) : "l"(a), "l"(b)); return d;
}
__device__ __forceinline__ u64t pack2(float lo, float hi) {
    u64t d; asm("mov.b64 %0, {%1, %2};" : "=l"(d) : "f"(lo), "f"(hi)); return d;
}
__device__ __forceinline__ float2 unpack2(u64t v) {
    float lo, hi; asm("mov.b64 {%0, %1}, %2;" : "=f"(lo), "=f"(hi) : "l"(v));
    return make_float2(lo, hi);
}
__device__ __forceinline__ uint32_t smem_u32(const void* p) {
    uint32_t a;
    asm("{ .reg .u64 t; cvta.to.shared.u64 t, %1; cvt.u32.u64 %0, t; }" : "=r"(a) : "l"(p));
    return a;
}

// ---------------- mma.sync / ldmatrix (compute_103-safe) ----------------
#define LDSM_X4(r, addr) \
    asm volatile("ldmatrix.sync.aligned.m8n8.x4.shared.b16 {%0,%1,%2,%3}, [%4];" \
        : "=r"((r)[0]), "=r"((r)[1]), "=r"((r)[2]), "=r"((r)[3]) : "r"(addr))
#define LDSM_X2(r, addr) \
    asm volatile("ldmatrix.sync.aligned.m8n8.x2.shared.b16 {%0,%1}, [%2];" \
        : "=r"((r)[0]), "=r"((r)[1]) : "r"(addr))
#define MMA_BF16(c, a, b) \
    asm volatile("mma.sync.aligned.m16n8k16.row.col.f32.bf16.bf16.f32 " \
        "{%0,%1,%2,%3}, {%4,%5,%6,%7}, {%8,%9}, {%0,%1,%2,%3};" \
        : "+f"((c)[0]), "+f"((c)[1]), "+f"((c)[2]), "+f"((c)[3]) \
        : "r"((a)[0]), "r"((a)[1]), "r"((a)[2]), "r"((a)[3]), "r"((b)[0]), "r"((b)[1]))

__device__ __forceinline__ void split4_bf16(float4 v, ushort4& hv, ushort4& lv) {
    __nv_bfloat16 b;
    b = __float2bfloat16(v.x); hv.x = __bfloat16_as_ushort(b);
    lv.x = __bfloat16_as_ushort(__float2bfloat16(v.x - __bfloat162float(b)));
    b = __float2bfloat16(v.y); hv.y = __bfloat16_as_ushort(b);
    lv.y = __bfloat16_as_ushort(__float2bfloat16(v.y - __bfloat162float(b)));
    b = __float2bfloat16(v.z); hv.z = __bfloat16_as_ushort(b);
    lv.z = __bfloat16_as_ushort(__float2bfloat16(v.z - __bfloat162float(b)));
    b = __float2bfloat16(v.w); hv.w = __bfloat16_as_ushort(b);
    lv.w = __bfloat16_as_ushort(__float2bfloat16(v.w - __bfloat162float(b)));
}

// ---------------- projection GEMMs (bf16 hi/lo epilogues for q, k, r) ----------------
template<int MODE>
__global__ __launch_bounds__(256) void proj_kernel(const float* __restrict__ X,
                                                   const float* __restrict__ MEMI,
                                                   const float* __restrict__ W, int N)
{
    __shared__ float As[64][64];
    __shared__ float Bs[64][64];
    const int m0 = blockIdx.y * 64;
    const int n0 = blockIdx.x * 64;
    const int tid = threadIdx.x;
    const int tx = tid & 15, ty = tid >> 4;

    float c[4][4] = {};

    for (int k0 = 0; k0 < 128; k0 += 64) {
        __syncthreads();
        #pragma unroll
        for (int i = 0; i < 4; i++) {
            int f = tid + i * 256;
            int row = f >> 4;
            int col = (f & 15) << 2;
            int m = m0 + row;
            float4 a;
            if (MODE == 0) {
                a = *(const float4*)(X + (size_t)m * 128 + k0 + col);
            } else if (MODE == 1) {
                int bb = m >> 11, sp = m & 2047;
                const float* src = (sp < 1024) ? (MEMI + ((size_t)bb * 1024 + sp) * 128)
                                               : (X    + ((size_t)bb * 1024 + sp - 1024) * 128);
                a = *(const float4*)(src + k0 + col);
            } else {
                float pp = (float)(2047 - m);
                float vv[4];
                #pragma unroll
                for (int cc = 0; cc < 4; cc++) {
                    int e = k0 + col + cc;
                    float ang = pp / powf(10000.0f, (float)(2 * e) * (1.0f / 128.0f));
                    vv[cc] = ((e & 1) == 0) ? sinf(ang) : cosf(ang);
                }
                a = make_float4(vv[0], vv[1], vv[2], vv[3]);
            }
            *(float4*)(&As[row][col]) = a;
        }
        #pragma unroll
        for (int i = 0; i < 4; i++) {
            int f = tid + i * 256;
            int krow = f >> 4;
            int nv = (f & 15) << 2;
            *(float4*)(&Bs[krow][nv]) = *(const float4*)(W + (size_t)(k0 + krow) * N + n0 + nv);
        }
        __syncthreads();

        #pragma unroll
        for (int k4 = 0; k4 < 16; k4++) {
            float4 a[4], b[4];
            #pragma unroll
            for (int i = 0; i < 4; i++) a[i] = *(float4*)&As[ty * 4 + i][k4 * 4];
            #pragma unroll
            for (int j = 0; j < 4; j++) b[j] = *(float4*)&Bs[k4 * 4 + j][tx * 4];
            #pragma unroll
            for (int i = 0; i < 4; i++) {
                c[i][0] += a[i].x*b[0].x + a[i].y*b[1].x + a[i].z*b[2].x + a[i].w*b[3].x;
                c[i][1] += a[i].x*b[0].y + a[i].y*b[1].y + a[i].z*b[2].y + a[i].w*b[3].y;
                c[i][2] += a[i].x*b[0].z + a[i].y*b[1].z + a[i].z*b[2].z + a[i].w*b[3].z;
                c[i][3] += a[i].x*b[0].w + a[i].y*b[1].w + a[i].z*b[2].w + a[i].w*b[3].w;
            }
        }
    }

    const int fp = n0 + tx * 4;
    #pragma unroll
    for (int i = 0; i < 4; i++) {
        int m = m0 + ty * 4 + i;
        float4 val = make_float4(c[i][0], c[i][1], c[i][2], c[i][3]);
        if (MODE == 0) {
            int b_ = m >> 10, sp = m & 1023;
            int h = sp >> 7;
            int s = ((sp & 127) << 3) + (fp >> 7);
            int e = fp & 127;
            size_t off = ((((size_t)b_ * 8 + h) * 1024 + s) << 7) + e;
            ushort4 hv, lv;
            split4_bf16(val, hv, lv);
            *(ushort4*)(g_qh + off) = hv;
            *(ushort4*)(g_ql + off) = lv;
        } else if (MODE == 1) {
            int bb = m >> 11, sp = m & 2047;
            int cc = bb * 2 + (sp >> 10);
            int h = (sp & 1023) >> 7;
            int t = ((sp & 127) << 4) + (fp >> 7);
            int e = fp & 127;
            if (cc < 4) {
                size_t off = ((((size_t)cc * 8 + h) * 2048 + t) << 7) + e;
                *(float4*)(g_k + off) = val;
                ushort4 hv, lv;
                split4_bf16(val, hv, lv);
                *(ushort4*)(g_kh + off) = hv;
                *(ushort4*)(g_kl + off) = lv;
            } else {
                *(float4*)(g_v + ((((size_t)(cc - 4) * 8 + h) * 2048 + t) << 7) + e) = val;
            }
        } else {
            int h = m >> 8;
            int t = ((m & 255) << 3) + (fp >> 7);
            int e = fp & 127;
            size_t off = (((size_t)h * 2048 + t) << 7) + e;
            *(float4*)(g_r + off) = val;
            ushort4 hv, lv;
            split4_bf16(val, hv, lv);
            *(ushort4*)(g_rh + off) = hv;
            *(ushort4*)(g_rl + off) = lv;
        }
    }
}

// ---------------- u1·k and u2·r ----------------
__global__ __launch_bounds__(256) void udot_kernel(const float* __restrict__ U, int which, int nrows)
{
    int row = blockIdx.x * 8 + (threadIdx.x >> 5);
    int lane = threadIdx.x & 31;
    if (row >= nrows) return;
    const float* Mat = which ? g_r : g_k;
    float* Out = which ? g_u2r : g_u1k;
    int h = (row >> 11) & 7;
    float4 u = *(const float4*)(U + h * 128 + lane * 4);
    float4 m = *(const float4*)(Mat + (size_t)row * 128 + lane * 4);
    float s = u.x * m.x + u.y * m.y + u.z * m.z + u.w * m.w;
    #pragma unroll
    for (int o = 16; o; o >>= 1) s += __shfl_xor_sync(0xffffffffu, s, o);
    if (lane == 0) Out[row] = s;
}

// ---------------- banded G = q.r via bf16 mma.sync (R5-proven) ----------------
__global__ __launch_bounds__(256, 2) void ggemm_mma_kernel()
{
    extern __shared__ __align__(16) unsigned short sm16[];
    unsigned short* Qh = sm16;              // 128*136
    unsigned short* Ql = Qh + 128 * 136;
    unsigned short* Rh = Ql + 128 * 136;    // 64*136
    unsigned short* Rl = Rh + 64 * 136;

    const int rt = blockIdx.x, st = blockIdx.y, bh = blockIdx.z;
    if (rt < 14 - 2 * st) return;
    const int h = bh & 7;
    const int s0 = st * 128, r0 = rt * 64;
    const int tid = threadIdx.x, wid = tid >> 5, lane = tid & 31;

    const unsigned short* qh = (const unsigned short*)g_qh + ((size_t)bh * 1024 + s0) * 128;
    const unsigned short* ql = (const unsigned short*)g_ql + ((size_t)bh * 1024 + s0) * 128;
    #pragma unroll
    for (int i = 0; i < 8; i++) {
        int f = tid + i * 256;
        int row = f >> 4, c8 = (f & 15) << 3;
        *(uint4*)(Qh + row * 136 + c8) = *(const uint4*)(qh + (size_t)row * 128 + c8);
        *(uint4*)(Ql + row * 136 + c8) = *(const uint4*)(ql + (size_t)row * 128 + c8);
    }
    const unsigned short* rh = (const unsigned short*)g_rh + ((size_t)h * 2048 + r0) * 128;
    const unsigned short* rl = (const unsigned short*)g_rl + ((size_t)h * 2048 + r0) * 128;
    #pragma unroll
    for (int i = 0; i < 4; i++) {
        int f = tid + i * 256;
        int row = f >> 4, c8 = (f & 15) << 3;
        *(uint4*)(Rh + row * 136 + c8) = *(const uint4*)(rh + (size_t)row * 128 + c8);
        *(uint4*)(Rl + row * 136 + c8) = *(const uint4*)(rl + (size_t)row * 128 + c8);
    }
    __syncthreads();

    const int wm = (wid >> 1) * 32;
    const int wn = (wid & 1) * 32;

    float c[2][4][4];
    #pragma unroll
    for (int mt = 0; mt < 2; mt++)
        #pragma unroll
        for (int nt = 0; nt < 4; nt++)
            #pragma unroll
            for (int e = 0; e < 4; e++) c[mt][nt][e] = 0.f;

    const int arow = (lane & 7) + ((lane >> 3) & 1) * 8;
    const int akoff = (lane >> 4) * 16;
    const int brow = lane & 7;
    const int bkoff = ((lane >> 3) & 1) * 16;

    const uint32_t qh_b = smem_u32(Qh), ql_b = smem_u32(Ql);
    const uint32_t rh_b = smem_u32(Rh), rl_b = smem_u32(Rl);

    #pragma unroll
    for (int ks = 0; ks < 8; ks++) {
        uint32_t ah[2][4], al[2][4];
        #pragma unroll
        for (int mt = 0; mt < 2; mt++) {
            uint32_t off = (uint32_t)((wm + mt * 16 + arow) * 272 + ks * 32 + akoff);
            LDSM_X4(ah[mt], qh_b + off);
            LDSM_X4(al[mt], ql_b + off);
        }
        uint32_t bhf[4][2], blf[4][2];
        #pragma unroll
        for (int nt = 0; nt < 4; nt++) {
            uint32_t off = (uint32_t)((wn + nt * 8 + brow) * 272 + ks * 32 + bkoff);
            LDSM_X2(bhf[nt], rh_b + off);
            LDSM_X2(blf[nt], rl_b + off);
        }
        #pragma unroll
        for (int mt = 0; mt < 2; mt++)
            #pragma unroll
            for (int nt = 0; nt < 4; nt++) {
                MMA_BF16(c[mt][nt], ah[mt], bhf[nt]);
                MMA_BF16(c[mt][nt], ah[mt], blf[nt]);
                MMA_BF16(c[mt][nt], al[mt], bhf[nt]);
            }
    }

    const int gp = lane >> 2, tg = lane & 3;
    float* Gb = g_G + (size_t)bh * (1024 * 2048);
    #pragma unroll
    for (int mt = 0; mt < 2; mt++) {
        int mrow = s0 + wm + mt * 16 + gp;
        #pragma unroll
        for (int nt = 0; nt < 4; nt++) {
            int n = r0 + wn + nt * 8 + 2 * tg;
            *(float2*)(Gb + (size_t)mrow * 2048 + n)       = make_float2(c[mt][nt][0], c[mt][nt][1]);
            *(float2*)(Gb + (size_t)(mrow + 8) * 2048 + n) = make_float2(c[mt][nt][2], c[mt][nt][3]);
        }
    }
}

// ---------------- flash attention: QK via bf16 mma.sync, PV f32x2 SIMT ----------------
__global__ __launch_bounds__(256, 1) void attn_kernel()
{
    extern __shared__ __align__(16) char smraw[];
    unsigned short* Qh = (unsigned short*)smraw;   // 128*136 bf16
    unsigned short* Ql = Qh + 128 * 136;
    unsigned short* Kh = Ql + 128 * 136;           // 64*136
    unsigned short* Kl = Kh + 64 * 136;
    float* Vs   = (float*)(Kl + 64 * 136);         // 64*128
    float* Ps   = Vs + 64 * 128;                   // 128*65 (G stage, then P)
    float* alf  = Ps + 128 * 65;                   // 128 (alpha, then l)
    float* bias = alf + 128;                       // 64

    const int st = blockIdx.x, bh = blockIdx.y, h = bh & 7;
    const int s0 = st * 128;
    const int tid = threadIdx.x, tx = tid & 15, ty = tid >> 4;
    const int wid = tid >> 5, lane = tid & 31;
    const int wm = wid * 16;
    const int gp = lane >> 2, tg = lane & 3;
    const int arow = (lane & 7) + ((lane >> 3) & 1) * 8;
    const int akoff = (lane >> 4) * 16;
    const int brow = lane & 7;
    const int bkoff = ((lane >> 3) & 1) * 16;

    const unsigned short* qhp = (const unsigned short*)g_qh + ((size_t)bh * 1024 + s0) * 128;
    const unsigned short* qlp = (const unsigned short*)g_ql + ((size_t)bh * 1024 + s0) * 128;
    const unsigned short* khp = (const unsigned short*)g_kh + (size_t)bh * (2048 * 128);
    const unsigned short* klp = (const unsigned short*)g_kl + (size_t)bh * (2048 * 128);
    const float* vb = g_v + (size_t)bh * (2048 * 128);
    const float* Gb = g_G + (size_t)bh * (1024 * 2048);

    // stage Q hi/lo once
    #pragma unroll
    for (int i = 0; i < 8; i++) {
        int f = tid + i * 256;
        int row = f >> 4, c8 = (f & 15) << 3;
        *(uint4*)(Qh + row * 136 + c8) = *(const uint4*)(qhp + (size_t)row * 128 + c8);
        *(uint4*)(Ql + row * 136 + c8) = *(const uint4*)(qlp + (size_t)row * 128 + c8);
    }

    const uint32_t qh_b = smem_u32(Qh), ql_b = smem_u32(Ql);
    const uint32_t kh_b = smem_u32(Kh), kl_b = smem_u32(Kl);

    u64t o2[8][4];
    float mrow[2], lrow[2];
    mrow[0] = mrow[1] = -1e30f;
    lrow[0] = lrow[1] = 0.f;
    #pragma unroll
    for (int i = 0; i < 8; i++)
        #pragma unroll
        for (int c = 0; c < 4; c++) o2[i][c] = 0ULL;

    const float scale = 0.08838834764831843f; // 1/sqrt(128)
    const int r0 = wm + gp, r1 = r0 + 8;
    const int sg0 = s0 + r0, sg1 = s0 + r1;

    const int ntiles = 2 * st + 18;
    for (int tt = 0; tt < ntiles; tt++) {
        const int t0 = tt * 64;
        __syncthreads();
        // stage K hi/lo (64 x 128 bf16 each)
        #pragma unroll
        for (int i = 0; i < 4; i++) {
            int f = tid + i * 256;
            int row = f >> 4, c8 = (f & 15) << 3;
            *(uint4*)(Kh + row * 136 + c8) = *(const uint4*)(khp + (size_t)(t0 + row) * 128 + c8);
            *(uint4*)(Kl + row * 136 + c8) = *(const uint4*)(klp + (size_t)(t0 + row) * 128 + c8);
        }
        // stage V (fp32)
        #pragma unroll
        for (int i = 0; i < 8; i++) {
            int f = tid + i * 256;
            int row = f >> 5, col = (f & 31) << 2;
            *(float4*)(Vs + row * 128 + col) = *(const float4*)(vb + (size_t)(t0 + row) * 128 + col);
        }
        // stage G band into Ps
        const int relbase = t0 - s0 + 1023;
        #pragma unroll
        for (int i = 0; i < 32; i++) {
            int idx = tid + i * 256;
            int row = idx >> 6, col = idx & 63;
            int rel = relbase + col - row;
            Ps[row * 65 + col] = (rel <= 2047) ? Gb[(size_t)(s0 + row) * 2048 + rel] : 0.f;
        }
        if (tid < 64) bias[tid] = g_u1k[(size_t)bh * 2048 + t0 + tid] + g_u2r[(size_t)h * 2048 + t0 + tid];
        __syncthreads();

        // ---- QK via mma.sync: warp owns rows [wm, wm+16), cols 0..63 ----
        float cs[8][4];
        #pragma unroll
        for (int nt = 0; nt < 8; nt++)
            #pragma unroll
            for (int e = 0; e < 4; e++) cs[nt][e] = 0.f;

        #pragma unroll
        for (int ks = 0; ks < 8; ks++) {
            uint32_t ah[4], al4[4];
            uint32_t offA = (uint32_t)((wm + arow) * 272 + ks * 32 + akoff);
            LDSM_X4(ah, qh_b + offA);
            LDSM_X4(al4, ql_b + offA);
            #pragma unroll
            for (int nt = 0; nt < 8; nt++) {
                uint32_t bh2[2], bl2[2];
                uint32_t offB = (uint32_t)((nt * 8 + brow) * 272 + ks * 32 + bkoff);
                LDSM_X2(bh2, kh_b + offB);
                LDSM_X2(bl2, kl_b + offB);
                MMA_BF16(cs[nt], ah, bh2);
                MMA_BF16(cs[nt], ah, bl2);
                MMA_BF16(cs[nt], al4, bh2);
            }
        }

        // ---- bias + G + scale + mask (fragment layout) ----
        float mx0 = -1e30f, mx1 = -1e30f;
        #pragma unroll
        for (int nt = 0; nt < 8; nt++) {
            int col = nt * 8 + 2 * tg;
            int tgl = t0 + col;
            float b0 = bias[col], b1 = bias[col + 1];
            float v00 = (cs[nt][0] + Ps[r0 * 65 + col]     + b0) * scale;
            float v01 = (cs[nt][1] + Ps[r0 * 65 + col + 1] + b1) * scale;
            float v10 = (cs[nt][2] + Ps[r1 * 65 + col]     + b0) * scale;
            float v11 = (cs[nt][3] + Ps[r1 * 65 + col + 1] + b1) * scale;
            v00 = (tgl     - sg0 <= 1024) ? v00 : -1e30f;
            v01 = (tgl + 1 - sg0 <= 1024) ? v01 : -1e30f;
            v10 = (tgl     - sg1 <= 1024) ? v10 : -1e30f;
            v11 = (tgl + 1 - sg1 <= 1024) ? v11 : -1e30f;
            cs[nt][0] = v00; cs[nt][1] = v01; cs[nt][2] = v10; cs[nt][3] = v11;
            mx0 = fmaxf(mx0, fmaxf(v00, v01));
            mx1 = fmaxf(mx1, fmaxf(v10, v11));
        }
        mx0 = fmaxf(mx0, __shfl_xor_sync(0xffffffffu, mx0, 1));
        mx0 = fmaxf(mx0, __shfl_xor_sync(0xffffffffu, mx0, 2));
        mx1 = fmaxf(mx1, __shfl_xor_sync(0xffffffffu, mx1, 1));
        mx1 = fmaxf(mx1, __shfl_xor_sync(0xffffffffu, mx1, 2));

        float mn0 = fmaxf(mrow[0], mx0), mn1 = fmaxf(mrow[1], mx1);
        float al0 = __expf(mrow[0] - mn0), al1 = __expf(mrow[1] - mn1);
        float rs0 = 0.f, rs1 = 0.f;
        #pragma unroll
        for (int nt = 0; nt < 8; nt++) {
            float p00 = __expf(cs[nt][0] - mn0), p01 = __expf(cs[nt][1] - mn0);
            float p10 = __expf(cs[nt][2] - mn1), p11 = __expf(cs[nt][3] - mn1);
            rs0 += p00 + p01; rs1 += p10 + p11;
            int col = nt * 8 + 2 * tg;
            Ps[r0 * 65 + col]     = p00;   // scalar stores: stride-65 rows are
            Ps[r0 * 65 + col + 1] = p01;   // only 4-byte aligned (fix for the
            Ps[r1 * 65 + col]     = p10;   // R6 misaligned-float2 trap)
            Ps[r1 * 65 + col + 1] = p11;
        }
        rs0 += __shfl_xor_sync(0xffffffffu, rs0, 1);
        rs0 += __shfl_xor_sync(0xffffffffu, rs0, 2);
        rs1 += __shfl_xor_sync(0xffffffffu, rs1, 1);
        rs1 += __shfl_xor_sync(0xffffffffu, rs1, 2);
        lrow[0] = lrow[0] * al0 + rs0; mrow[0] = mn0;
        lrow[1] = lrow[1] * al1 + rs1; mrow[1] = mn1;
        if (tg == 0) { alf[r0] = al0; alf[r1] = al1; }
        __syncthreads();

        // ---- PV (SIMT f32x2, rows ty+16i) ----
        #pragma unroll
        for (int i = 0; i < 8; i++) {
            float a = alf[ty + 16 * i];
            u64t a2 = pack2(a, a);
            #pragma unroll
            for (int c = 0; c < 4; c++) o2[i][c] = mul2(o2[i][c], a2);
        }
        #pragma unroll 4
        for (int tj = 0; tj < 64; tj++) {
            u64t v2[4];
            #pragma unroll
            for (int c = 0; c < 4; c++) v2[c] = *(u64t*)(Vs + tj * 128 + 2 * tx + 32 * c);
            #pragma unroll
            for (int i = 0; i < 8; i++) {
                float p = Ps[(ty + 16 * i) * 65 + tj];
                u64t p2 = pack2(p, p);
                #pragma unroll
                for (int c = 0; c < 4; c++) o2[i][c] = fma2(p2, v2[c], o2[i][c]);
            }
        }
    }

    // hand l to PV-layout threads via smem
    __syncthreads();
    if (tg == 0) { alf[r0] = lrow[0]; alf[r1] = lrow[1]; }
    __syncthreads();

    const int b_ = bh >> 3;
    #pragma unroll
    for (int i = 0; i < 8; i++) {
        float inv = 1.0f / alf[ty + 16 * i];
        int sg = s0 + ty + 16 * i;
        int sp = h * 128 + (sg >> 3);
        int fp = (sg & 7) << 7;
        float* dst = g_att + ((size_t)b_ * 1024 + sp) * 1024 + fp;
        #pragma unroll
        for (int c = 0; c < 4; c++) {
            float2 v = unpack2(o2[i][c]);
            *(float2*)(dst + 2 * tx + 32 * c) = make_float2(v.x * inv, v.y * inv);
        }
    }
}

// ---------------- fused MLP + residual + LayerNorm ----------------
__global__ __launch_bounds__(256) void mlp_ln_kernel(const float* __restrict__ X,
                                                     const float* __restrict__ Wm,
                                                     const float* __restrict__ gamma,
                                                     const float* __restrict__ beta,
                                                     float* __restrict__ out)
{
    __shared__ float At[64][32];
    __shared__ float Wt[32][128];
    const int m0 = blockIdx.x * 64;
    const int tid = threadIdx.x;
    const int tx = tid & 15, ty = tid >> 4;

    float acc[4][8] = {};

    for (int k0 = 0; k0 < 1024; k0 += 32) {
        __syncthreads();
        #pragma unroll
        for (int i = 0; i < 2; i++) {
            int f = tid + i * 256;
            int row = f >> 3;
            int col = (f & 7) << 2;
            *(float4*)(&At[row][col]) = *(const float4*)(g_att + (size_t)(m0 + row) * 1024 + k0 + col);
        }
        #pragma unroll
        for (int i = 0; i < 4; i++) {
            int f = tid + i * 256;
            int row = f >> 5;
            int col = (f & 31) << 2;
            *(float4*)(&Wt[row][col]) = *(const float4*)(Wm + (size_t)(k0 + row) * 128 + col);
        }
        __syncthreads();

        #pragma unroll
        for (int k4 = 0; k4 < 8; k4++) {
            float4 a[4];
            #pragma unroll
            for (int i = 0; i < 4; i++) a[i] = *(float4*)&At[ty * 4 + i][k4 * 4];
            float ws[4][8];
            #pragma unroll
            for (int kk = 0; kk < 4; kk++) {
                float4 u = *(float4*)&Wt[k4 * 4 + kk][tx * 8];
                float4 v = *(float4*)&Wt[k4 * 4 + kk][tx * 8 + 4];
                ws[kk][0] = u.x; ws[kk][1] = u.y; ws[kk][2] = u.z; ws[kk][3] = u.w;
                ws[kk][4] = v.x; ws[kk][5] = v.y; ws[kk][6] = v.z; ws[kk][7] = v.w;
            }
            #pragma unroll
            for (int i = 0; i < 4; i++)
                #pragma unroll
                for (int j = 0; j < 8; j++)
                    acc[i][j] += a[i].x * ws[0][j] + a[i].y * ws[1][j] + a[i].z * ws[2][j] + a[i].w * ws[3][j];
        }
    }

    float gj[8], bj[8];
    #pragma unroll
    for (int j = 0; j < 8; j++) { gj[j] = gamma[tx * 8 + j]; bj[j] = beta[tx * 8 + j]; }

    #pragma unroll
    for (int i = 0; i < 4; i++) {
        int r = m0 + ty * 4 + i;
        float y[8];
        float s = 0.f;
        #pragma unroll
        for (int j = 0; j < 8; j++) {
            y[j] = acc[i][j] + X[(size_t)r * 128 + tx * 8 + j];
            s += y[j];
        }
        #pragma unroll
        for (int off = 8; off; off >>= 1) s += __shfl_xor_sync(0xffffffffu, s, off);
        float mu = s * (1.0f / 128.0f);
        float vs = 0.f;
        #pragma unroll
        for (int j = 0; j < 8; j++) { float d = y[j] - mu; vs += d * d; }
        #pragma unroll
        for (int off = 8; off; off >>= 1) vs += __shfl_xor_sync(0xffffffffu, vs, off);
        float inv = rsqrtf(vs * (1.0f / 128.0f) + 1e-5f);
        #pragma unroll
        for (int j = 0; j < 8; j++)
            out[(size_t)r * 128 + tx * 8 + j] = (y[j] - mu) * inv * gj[j] + bj[j];
    }
}

// ---------------- launch ----------------
extern "C" void kernel_launch(void* const* d_in, const int* in_sizes, int n_in,
                              void* d_out, int out_size)
{
    const float* x     = (const float*)d_in[0];
    const float* memp  = (const float*)d_in[1];
    const float* u1    = (const float*)d_in[3];
    const float* u2    = (const float*)d_in[4];
    const float* w_q   = (const float*)d_in[5];
    const float* w_kv  = (const float*)d_in[6];
    const float* w_r   = (const float*)d_in[7];
    const float* w_mlp = (const float*)d_in[8];
    const float* ln_g  = (const float*)d_in[9];
    const float* ln_b  = (const float*)d_in[10];
    float* out = (float*)d_out;

    const int ggemm_smem = (128 * 136 * 2 + 64 * 136 * 2) * 2;   // 104,448 B
    const int attn_smem  = (128 * 136 * 2 + 64 * 136 * 2) * 2    // Q,K hi/lo bf16
                         + (64 * 128 + 128 * 65 + 128 + 64) * 4; // V, Ps, alpha, bias = 171,264 B
    cudaFuncSetAttribute(ggemm_mma_kernel, cudaFuncAttributeMaxDynamicSharedMemorySize, ggemm_smem);
    cudaFuncSetAttribute(attn_kernel,      cudaFuncAttributeMaxDynamicSharedMemorySize, attn_smem);

    proj_kernel<0><<<dim3(16, 64), 256>>>(x, nullptr, w_q, 1024);
    proj_kernel<1><<<dim3(32, 128), 256>>>(x, memp, w_kv, 2048);
    proj_kernel<2><<<dim3(16, 32), 256>>>(nullptr, nullptr, w_r, 1024);
    udot_kernel<<<8192, 256>>>(u1, 0, NB * NH * TOT);
    udot_kernel<<<2048, 256>>>(u2, 1, NH * TOT);
    ggemm_mma_kernel<<<dim3(32, 8, 32), 256, ggemm_smem>>>();
    attn_kernel<<<dim3(8, 32), 256, attn_smem>>>();
    mlp_ln_kernel<<<64, 256>>>(x, w_mlp, ln_g, ln_b, out);
}

// round 8
// speedup vs baseline: 6.2336x; 1.3453x over previous
#include <cuda_runtime.h>
#include <cuda_bf16.h>
#include <math.h>
#include <stdint.h>

#define NB 4
#define NH 8
#define SEGL 1024
#define TOT 2048
#define DD 128

// ---------------- scratch (device globals; no allocations) ----------------
__device__ float g_k[NB*NH*TOT*DD];       // fp32 (udot)
__device__ float g_r[NH*TOT*DD];          // fp32 (udot)
__device__ __nv_bfloat16 g_qh[NB*NH*SEGL*DD];
__device__ __nv_bfloat16 g_ql[NB*NH*SEGL*DD];
__device__ __nv_bfloat16 g_kh[NB*NH*TOT*DD];
__device__ __nv_bfloat16 g_kl[NB*NH*TOT*DD];
__device__ __nv_bfloat16 g_vh[NB*NH*TOT*DD];   // V single bf16 plane
__device__ __nv_bfloat16 g_rh[NH*TOT*DD];
__device__ __nv_bfloat16 g_rl[NH*TOT*DD];
__device__ float g_u1k[NB*NH*TOT];
__device__ float g_u2r[NH*TOT];
__device__ float g_att[NB*SEGL*NH*DD];
__device__ __nv_bfloat16 g_G[(size_t)NB*NH*SEGL*TOT]; // 134MB bf16: [bh][s][rel]

// ---------------- helpers ----------------
typedef unsigned long long u64t;
__device__ __forceinline__ uint32_t smem_u32(const void* p) {
    uint32_t a;
    asm("{ .reg .u64 t; cvta.to.shared.u64 t, %1; cvt.u32.u64 %0, t; }" : "=r"(a) : "l"(p));
    return a;
}
__device__ __forceinline__ uint32_t pack_bf16x2(float lo, float hi) {
    uint32_t d; asm("cvt.rn.bf16x2.f32 %0, %1, %2;" : "=r"(d) : "f"(hi), "f"(lo)); return d;
}

#define LDSM_X4(r, addr) \
    asm volatile("ldmatrix.sync.aligned.m8n8.x4.shared.b16 {%0,%1,%2,%3}, [%4];" \
        : "=r"((r)[0]), "=r"((r)[1]), "=r"((r)[2]), "=r"((r)[3]) : "r"(addr))
#define LDSM_X4_T(r, addr) \
    asm volatile("ldmatrix.sync.aligned.m8n8.x4.trans.shared.b16 {%0,%1,%2,%3}, [%4];" \
        : "=r"((r)[0]), "=r"((r)[1]), "=r"((r)[2]), "=r"((r)[3]) : "r"(addr))
#define MMA_BF16(c, a, b) \
    asm volatile("mma.sync.aligned.m16n8k16.row.col.f32.bf16.bf16.f32 " \
        "{%0,%1,%2,%3}, {%4,%5,%6,%7}, {%8,%9}, {%0,%1,%2,%3};" \
        : "+f"((c)[0]), "+f"((c)[1]), "+f"((c)[2]), "+f"((c)[3]) \
        : "r"((a)[0]), "r"((a)[1]), "r"((a)[2]), "r"((a)[3]), "r"((b)[0]), "r"((b)[1]))

__device__ __forceinline__ void split4_bf16(float4 v, ushort4& hv, ushort4& lv) {
    __nv_bfloat16 b;
    b = __float2bfloat16(v.x); hv.x = __bfloat16_as_ushort(b);
    lv.x = __bfloat16_as_ushort(__float2bfloat16(v.x - __bfloat162float(b)));
    b = __float2bfloat16(v.y); hv.y = __bfloat16_as_ushort(b);
    lv.y = __bfloat16_as_ushort(__float2bfloat16(v.y - __bfloat162float(b)));
    b = __float2bfloat16(v.z); hv.z = __bfloat16_as_ushort(b);
    lv.z = __bfloat16_as_ushort(__float2bfloat16(v.z - __bfloat162float(b)));
    b = __float2bfloat16(v.w); hv.w = __bfloat16_as_ushort(b);
    lv.w = __bfloat16_as_ushort(__float2bfloat16(v.w - __bfloat162float(b)));
}
__device__ __forceinline__ ushort4 hi4_bf16(float4 v) {
    ushort4 h;
    h.x = __bfloat16_as_ushort(__float2bfloat16(v.x));
    h.y = __bfloat16_as_ushort(__float2bfloat16(v.y));
    h.z = __bfloat16_as_ushort(__float2bfloat16(v.z));
    h.w = __bfloat16_as_ushort(__float2bfloat16(v.w));
    return h;
}

// ---------------- projection GEMMs ----------------
template<int MODE>
__global__ __launch_bounds__(256) void proj_kernel(const float* __restrict__ X,
                                                   const float* __restrict__ MEMI,
                                                   const float* __restrict__ W, int N)
{
    __shared__ float As[64][64];
    __shared__ float Bs[64][64];
    const int m0 = blockIdx.y * 64;
    const int n0 = blockIdx.x * 64;
    const int tid = threadIdx.x;
    const int tx = tid & 15, ty = tid >> 4;

    float c[4][4] = {};

    for (int k0 = 0; k0 < 128; k0 += 64) {
        __syncthreads();
        #pragma unroll
        for (int i = 0; i < 4; i++) {
            int f = tid + i * 256;
            int row = f >> 4;
            int col = (f & 15) << 2;
            int m = m0 + row;
            float4 a;
            if (MODE == 0) {
                a = *(const float4*)(X + (size_t)m * 128 + k0 + col);
            } else if (MODE == 1) {
                int bb = m >> 11, sp = m & 2047;
                const float* src = (sp < 1024) ? (MEMI + ((size_t)bb * 1024 + sp) * 128)
                                               : (X    + ((size_t)bb * 1024 + sp - 1024) * 128);
                a = *(const float4*)(src + k0 + col);
            } else {
                float pp = (float)(2047 - m);
                float vv[4];
                #pragma unroll
                for (int cc = 0; cc < 4; cc++) {
                    int e = k0 + col + cc;
                    float ang = pp / powf(10000.0f, (float)(2 * e) * (1.0f / 128.0f));
                    vv[cc] = ((e & 1) == 0) ? sinf(ang) : cosf(ang);
                }
                a = make_float4(vv[0], vv[1], vv[2], vv[3]);
            }
            *(float4*)(&As[row][col]) = a;
        }
        #pragma unroll
        for (int i = 0; i < 4; i++) {
            int f = tid + i * 256;
            int krow = f >> 4;
            int nv = (f & 15) << 2;
            *(float4*)(&Bs[krow][nv]) = *(const float4*)(W + (size_t)(k0 + krow) * N + n0 + nv);
        }
        __syncthreads();

        #pragma unroll
        for (int k4 = 0; k4 < 16; k4++) {
            float4 a[4], b[4];
            #pragma unroll
            for (int i = 0; i < 4; i++) a[i] = *(float4*)&As[ty * 4 + i][k4 * 4];
            #pragma unroll
            for (int j = 0; j < 4; j++) b[j] = *(float4*)&Bs[k4 * 4 + j][tx * 4];
            #pragma unroll
            for (int i = 0; i < 4; i++) {
                c[i][0] += a[i].x*b[0].x + a[i].y*b[1].x + a[i].z*b[2].x + a[i].w*b[3].x;
                c[i][1] += a[i].x*b[0].y + a[i].y*b[1].y + a[i].z*b[2].y + a[i].w*b[3].y;
                c[i][2] += a[i].x*b[0].z + a[i].y*b[1].z + a[i].z*b[2].z + a[i].w*b[3].z;
                c[i][3] += a[i].x*b[0].w + a[i].y*b[1].w + a[i].z*b[2].w + a[i].w*b[3].w;
            }
        }
    }

    const int fp = n0 + tx * 4;
    #pragma unroll
    for (int i = 0; i < 4; i++) {
        int m = m0 + ty * 4 + i;
        float4 val = make_float4(c[i][0], c[i][1], c[i][2], c[i][3]);
        if (MODE == 0) {
            int b_ = m >> 10, sp = m & 1023;
            int h = sp >> 7;
            int s = ((sp & 127) << 3) + (fp >> 7);
            int e = fp & 127;
            size_t off = ((((size_t)b_ * 8 + h) * 1024 + s) << 7) + e;
            ushort4 hv, lv;
            split4_bf16(val, hv, lv);
            *(ushort4*)(g_qh + off) = hv;
            *(ushort4*)(g_ql + off) = lv;
        } else if (MODE == 1) {
            int bb = m >> 11, sp = m & 2047;
            int cc = bb * 2 + (sp >> 10);
            int h = (sp & 1023) >> 7;
            int t = ((sp & 127) << 4) + (fp >> 7);
            int e = fp & 127;
            if (cc < 4) {
                size_t off = ((((size_t)cc * 8 + h) * 2048 + t) << 7) + e;
                *(float4*)(g_k + off) = val;
                ushort4 hv, lv;
                split4_bf16(val, hv, lv);
                *(ushort4*)(g_kh + off) = hv;
                *(ushort4*)(g_kl + off) = lv;
            } else {
                size_t off = ((((size_t)(cc - 4) * 8 + h) * 2048 + t) << 7) + e;
                *(ushort4*)(g_vh + off) = hi4_bf16(val);
            }
        } else {
            int h = m >> 8;
            int t = ((m & 255) << 3) + (fp >> 7);
            int e = fp & 127;
            size_t off = (((size_t)h * 2048 + t) << 7) + e;
            *(float4*)(g_r + off) = val;
            ushort4 hv, lv;
            split4_bf16(val, hv, lv);
            *(ushort4*)(g_rh + off) = hv;
            *(ushort4*)(g_rl + off) = lv;
        }
    }
}

// ---------------- u1·k and u2·r ----------------
__global__ __launch_bounds__(256) void udot_kernel(const float* __restrict__ U, int which, int nrows)
{
    int row = blockIdx.x * 8 + (threadIdx.x >> 5);
    int lane = threadIdx.x & 31;
    if (row >= nrows) return;
    const float* Mat = which ? g_r : g_k;
    float* Out = which ? g_u2r : g_u1k;
    int h = (row >> 11) & 7;
    float4 u = *(const float4*)(U + h * 128 + lane * 4);
    float4 m = *(const float4*)(Mat + (size_t)row * 128 + lane * 4);
    float s = u.x * m.x + u.y * m.y + u.z * m.z + u.w * m.w;
    #pragma unroll
    for (int o = 16; o; o >>= 1) s += __shfl_xor_sync(0xffffffffu, s, o);
    if (lane == 0) Out[row] = s;
}

// ---------------- banded G = q.r via bf16 mma.sync (bf16 output) ----------------
__global__ __launch_bounds__(256, 2) void ggemm_mma_kernel()
{
    extern __shared__ __align__(16) unsigned short sm16[];
    unsigned short* Qh = sm16;              // 128*136
    unsigned short* Ql = Qh + 128 * 136;
    unsigned short* Rh = Ql + 128 * 136;    // 64*136
    unsigned short* Rl = Rh + 64 * 136;

    const int rt = blockIdx.x, st = blockIdx.y, bh = blockIdx.z;
    if (rt < 14 - 2 * st) return;
    const int h = bh & 7;
    const int s0 = st * 128, r0 = rt * 64;
    const int tid = threadIdx.x, wid = tid >> 5, lane = tid & 31;

    const unsigned short* qh = (const unsigned short*)g_qh + ((size_t)bh * 1024 + s0) * 128;
    const unsigned short* ql = (const unsigned short*)g_ql + ((size_t)bh * 1024 + s0) * 128;
    #pragma unroll
    for (int i = 0; i < 8; i++) {
        int f = tid + i * 256;
        int row = f >> 4, c8 = (f & 15) << 3;
        *(uint4*)(Qh + row * 136 + c8) = *(const uint4*)(qh + (size_t)row * 128 + c8);
        *(uint4*)(Ql + row * 136 + c8) = *(const uint4*)(ql + (size_t)row * 128 + c8);
    }
    const unsigned short* rh = (const unsigned short*)g_rh + ((size_t)h * 2048 + r0) * 128;
    const unsigned short* rl = (const unsigned short*)g_rl + ((size_t)h * 2048 + r0) * 128;
    #pragma unroll
    for (int i = 0; i < 4; i++) {
        int f = tid + i * 256;
        int row = f >> 4, c8 = (f & 15) << 3;
        *(uint4*)(Rh + row * 136 + c8) = *(const uint4*)(rh + (size_t)row * 128 + c8);
        *(uint4*)(Rl + row * 136 + c8) = *(const uint4*)(rl + (size_t)row * 128 + c8);
    }
    __syncthreads();

    const int wm = (wid >> 1) * 32;
    const int wn = (wid & 1) * 32;

    float c[2][4][4];
    #pragma unroll
    for (int mt = 0; mt < 2; mt++)
        #pragma unroll
        for (int nt = 0; nt < 4; nt++)
            #pragma unroll
            for (int e = 0; e < 4; e++) c[mt][nt][e] = 0.f;

    const int arow = (lane & 7) + ((lane >> 3) & 1) * 8;
    const int akoff = (lane >> 4) * 16;
    const int brow = lane & 7;
    const int bkoff = ((lane >> 3) & 1) * 16;

    const uint32_t qh_b = smem_u32(Qh), ql_b = smem_u32(Ql);
    const uint32_t rh_b = smem_u32(Rh), rl_b = smem_u32(Rl);

    #pragma unroll
    for (int ks = 0; ks < 8; ks++) {
        uint32_t ah[2][4], al[2][4];
        #pragma unroll
        for (int mt = 0; mt < 2; mt++) {
            uint32_t off = (uint32_t)((wm + mt * 16 + arow) * 272 + ks * 32 + akoff);
            LDSM_X4(ah[mt], qh_b + off);
            LDSM_X4(al[mt], ql_b + off);
        }
        uint32_t bhf[4][2], blf[4][2];
        #pragma unroll
        for (int nt = 0; nt < 4; nt++) {
            uint32_t off = (uint32_t)((wn + nt * 8 + brow) * 272 + ks * 32 + bkoff);
            asm volatile("ldmatrix.sync.aligned.m8n8.x2.shared.b16 {%0,%1}, [%2];"
                : "=r"(bhf[nt][0]), "=r"(bhf[nt][1]) : "r"(rh_b + off));
            asm volatile("ldmatrix.sync.aligned.m8n8.x2.shared.b16 {%0,%1}, [%2];"
                : "=r"(blf[nt][0]), "=r"(blf[nt][1]) : "r"(rl_b + off));
        }
        #pragma unroll
        for (int mt = 0; mt < 2; mt++)
            #pragma unroll
            for (int nt = 0; nt < 4; nt++) {
                MMA_BF16(c[mt][nt], ah[mt], bhf[nt]);
                MMA_BF16(c[mt][nt], ah[mt], blf[nt]);
                MMA_BF16(c[mt][nt], al[mt], bhf[nt]);
            }
    }

    const int gp = lane >> 2, tg = lane & 3;
    __nv_bfloat16* Gb = g_G + (size_t)bh * (1024 * 2048);
    #pragma unroll
    for (int mt = 0; mt < 2; mt++) {
        int mrow = s0 + wm + mt * 16 + gp;
        #pragma unroll
        for (int nt = 0; nt < 4; nt++) {
            int n = r0 + wn + nt * 8 + 2 * tg;
            *(uint32_t*)(Gb + (size_t)mrow * 2048 + n)       = pack_bf16x2(c[mt][nt][0], c[mt][nt][1]);
            *(uint32_t*)(Gb + (size_t)(mrow + 8) * 2048 + n) = pack_bf16x2(c[mt][nt][2], c[mt][nt][3]);
        }
    }
}

// ---------------- flash attention: QK + PV both bf16 mma.sync ----------------
__global__ __launch_bounds__(256, 1) void attn_kernel()
{
    extern __shared__ __align__(16) char smraw[];
    unsigned short* Qh = (unsigned short*)smraw;   // 128*136 bf16
    unsigned short* Ql = Qh + 128 * 136;
    unsigned short* Kh = Ql + 128 * 136;           // 64*136
    unsigned short* Kl = Kh + 64 * 136;
    unsigned short* Vh = Kl + 64 * 136;            // 64*136
    float* Ps   = (float*)(Vh + 64 * 136);         // 128*65 (G stage)
    float* bias = Ps + 128 * 65;                   // 64

    const int st = blockIdx.x, bh = blockIdx.y, h = bh & 7;
    const int s0 = st * 128;
    const int tid = threadIdx.x;
    const int wid = tid >> 5, lane = tid & 31;
    const int wm = wid * 16;
    const int gp = lane >> 2, tg = lane & 3;
    const int arow = (lane & 7) + ((lane >> 3) & 1) * 8;
    const int akoff = (lane >> 4) * 16;
    // QK B x4: pair np covers nt=2np,2np+1
    const int b4row = ((lane >> 4) & 1) * 8 + (lane & 7);
    const int b4koff = ((lane >> 3) & 1) * 16;
    // PV V trans x4: rows = t (k dim), cols = e (n dim)
    const int vtrow = ((lane >> 3) & 1) * 8 + (lane & 7);
    const int vncol = ((lane >> 4) & 1) * 8;

    const unsigned short* qhp = (const unsigned short*)g_qh + ((size_t)bh * 1024 + s0) * 128;
    const unsigned short* qlp = (const unsigned short*)g_ql + ((size_t)bh * 1024 + s0) * 128;
    const unsigned short* khp = (const unsigned short*)g_kh + (size_t)bh * (2048 * 128);
    const unsigned short* klp = (const unsigned short*)g_kl + (size_t)bh * (2048 * 128);
    const unsigned short* vhp = (const unsigned short*)g_vh + (size_t)bh * (2048 * 128);
    const __nv_bfloat16* Gbh = g_G + (size_t)bh * (1024 * 2048);

    // stage Q hi/lo once
    #pragma unroll
    for (int i = 0; i < 8; i++) {
        int f = tid + i * 256;
        int row = f >> 4, c8 = (f & 15) << 3;
        *(uint4*)(Qh + row * 136 + c8) = *(const uint4*)(qhp + (size_t)row * 128 + c8);
        *(uint4*)(Ql + row * 136 + c8) = *(const uint4*)(qlp + (size_t)row * 128 + c8);
    }

    const uint32_t qh_b = smem_u32(Qh), ql_b = smem_u32(Ql);
    const uint32_t kh_b = smem_u32(Kh), kl_b = smem_u32(Kl);
    const uint32_t vh_b = smem_u32(Vh);

    float o[16][4];   // PV accumulators, C-frag layout over e
    #pragma unroll
    for (int nt = 0; nt < 16; nt++)
        #pragma unroll
        for (int e = 0; e < 4; e++) o[nt][e] = 0.f;

    float mrow[2], lrow[2];
    mrow[0] = mrow[1] = -1e30f;
    lrow[0] = lrow[1] = 0.f;

    const float scale = 0.08838834764831843f; // 1/sqrt(128)
    const int r0 = wm + gp, r1 = r0 + 8;
    const int sg0 = s0 + r0, sg1 = s0 + r1;

    const int ntiles = 2 * st + 18;
    for (int tt = 0; tt < ntiles; tt++) {
        const int t0 = tt * 64;
        __syncthreads();
        // stage K hi/lo
        #pragma unroll
        for (int i = 0; i < 4; i++) {
            int f = tid + i * 256;
            int row = f >> 4, c8 = (f & 15) << 3;
            *(uint4*)(Kh + row * 136 + c8) = *(const uint4*)(khp + (size_t)(t0 + row) * 128 + c8);
            *(uint4*)(Kl + row * 136 + c8) = *(const uint4*)(klp + (size_t)(t0 + row) * 128 + c8);
        }
        // stage V (bf16 single plane)
        #pragma unroll
        for (int i = 0; i < 4; i++) {
            int f = tid + i * 256;
            int row = f >> 4, c8 = (f & 15) << 3;
            *(uint4*)(Vh + row * 136 + c8) = *(const uint4*)(vhp + (size_t)(t0 + row) * 128 + c8);
        }
        // stage G band (bf16 -> fp32 Ps)
        const int relbase = t0 - s0 + 1023;
        #pragma unroll
        for (int i = 0; i < 32; i++) {
            int idx = tid + i * 256;
            int row = idx >> 6, col = idx & 63;
            int rel = relbase + col - row;
            Ps[row * 65 + col] = (rel <= 2047) ? __bfloat162float(Gbh[(size_t)(s0 + row) * 2048 + rel]) : 0.f;
        }
        if (tid < 64) bias[tid] = g_u1k[(size_t)bh * 2048 + t0 + tid] + g_u2r[(size_t)h * 2048 + t0 + tid];
        __syncthreads();

        // ---- QK (3-term bf16 split): warp rows [wm, wm+16), cols 0..63 ----
        float cs[8][4];
        #pragma unroll
        for (int nt = 0; nt < 8; nt++)
            #pragma unroll
            for (int e = 0; e < 4; e++) cs[nt][e] = 0.f;

        #pragma unroll
        for (int ks = 0; ks < 8; ks++) {
            uint32_t ah[4], al4[4];
            uint32_t offA = (uint32_t)((wm + arow) * 272 + ks * 32 + akoff);
            LDSM_X4(ah, qh_b + offA);
            LDSM_X4(al4, ql_b + offA);
            #pragma unroll
            for (int np = 0; np < 4; np++) {
                uint32_t bh4[4], bl4[4];
                uint32_t offB = (uint32_t)((np * 16 + b4row) * 272 + ks * 32 + b4koff);
                LDSM_X4(bh4, kh_b + offB);
                LDSM_X4(bl4, kl_b + offB);
                MMA_BF16(cs[2 * np],     ah,  &bh4[0]);
                MMA_BF16(cs[2 * np],     ah,  &bl4[0]);
                MMA_BF16(cs[2 * np],     al4, &bh4[0]);
                MMA_BF16(cs[2 * np + 1], ah,  &bh4[2]);
                MMA_BF16(cs[2 * np + 1], ah,  &bl4[2]);
                MMA_BF16(cs[2 * np + 1], al4, &bh4[2]);
            }
        }

        // ---- bias + G + scale + mask ----
        float mx0 = -1e30f, mx1 = -1e30f;
        #pragma unroll
        for (int nt = 0; nt < 8; nt++) {
            int col = nt * 8 + 2 * tg;
            int tgl = t0 + col;
            float b0 = bias[col], b1 = bias[col + 1];
            float v00 = (cs[nt][0] + Ps[r0 * 65 + col]     + b0) * scale;
            float v01 = (cs[nt][1] + Ps[r0 * 65 + col + 1] + b1) * scale;
            float v10 = (cs[nt][2] + Ps[r1 * 65 + col]     + b0) * scale;
            float v11 = (cs[nt][3] + Ps[r1 * 65 + col + 1] + b1) * scale;
            v00 = (tgl     - sg0 <= 1024) ? v00 : -1e30f;
            v01 = (tgl + 1 - sg0 <= 1024) ? v01 : -1e30f;
            v10 = (tgl     - sg1 <= 1024) ? v10 : -1e30f;
            v11 = (tgl + 1 - sg1 <= 1024) ? v11 : -1e30f;
            cs[nt][0] = v00; cs[nt][1] = v01; cs[nt][2] = v10; cs[nt][3] = v11;
            mx0 = fmaxf(mx0, fmaxf(v00, v01));
            mx1 = fmaxf(mx1, fmaxf(v10, v11));
        }
        mx0 = fmaxf(mx0, __shfl_xor_sync(0xffffffffu, mx0, 1));
        mx0 = fmaxf(mx0, __shfl_xor_sync(0xffffffffu, mx0, 2));
        mx1 = fmaxf(mx1, __shfl_xor_sync(0xffffffffu, mx1, 1));
        mx1 = fmaxf(mx1, __shfl_xor_sync(0xffffffffu, mx1, 2));

        float mn0 = fmaxf(mrow[0], mx0), mn1 = fmaxf(mrow[1], mx1);
        float al0 = __expf(mrow[0] - mn0), al1 = __expf(mrow[1] - mn1);
        float rs0 = 0.f, rs1 = 0.f;
        #pragma unroll
        for (int nt = 0; nt < 8; nt++) {
            float p00 = __expf(cs[nt][0] - mn0), p01 = __expf(cs[nt][1] - mn0);
            float p10 = __expf(cs[nt][2] - mn1), p11 = __expf(cs[nt][3] - mn1);
            rs0 += p00 + p01; rs1 += p10 + p11;
            cs[nt][0] = p00; cs[nt][1] = p01; cs[nt][2] = p10; cs[nt][3] = p11;
        }
        rs0 += __shfl_xor_sync(0xffffffffu, rs0, 1);
        rs0 += __shfl_xor_sync(0xffffffffu, rs0, 2);
        rs1 += __shfl_xor_sync(0xffffffffu, rs1, 1);
        rs1 += __shfl_xor_sync(0xffffffffu, rs1, 2);
        lrow[0] = lrow[0] * al0 + rs0; mrow[0] = mn0;
        lrow[1] = lrow[1] * al1 + rs1; mrow[1] = mn1;

        // ---- rescale o by alpha (per fragment row) ----
        #pragma unroll
        for (int nt = 0; nt < 16; nt++) {
            o[nt][0] *= al0; o[nt][1] *= al0;
            o[nt][2] *= al1; o[nt][3] *= al1;
        }

        // ---- PV via mma.sync: P (regs->bf16 A-frags), V via ldmatrix.trans ----
        #pragma unroll
        for (int kc = 0; kc < 4; kc++) {
            uint32_t pa[4];
            pa[0] = pack_bf16x2(cs[2 * kc][0],     cs[2 * kc][1]);
            pa[1] = pack_bf16x2(cs[2 * kc][2],     cs[2 * kc][3]);
            pa[2] = pack_bf16x2(cs[2 * kc + 1][0], cs[2 * kc + 1][1]);
            pa[3] = pack_bf16x2(cs[2 * kc + 1][2], cs[2 * kc + 1][3]);
            #pragma unroll
            for (int ep = 0; ep < 8; ep++) {
                uint32_t vb4[4];
                uint32_t offV = (uint32_t)((kc * 16 + vtrow) * 272 + (ep * 16 + vncol) * 2);
                LDSM_X4_T(vb4, vh_b + offV);
                MMA_BF16(o[2 * ep],     pa, &vb4[0]);
                MMA_BF16(o[2 * ep + 1], pa, &vb4[2]);
            }
        }
    }

    // ---- epilogue: normalize in fragment layout, write att3 ----
    const int b_ = bh >> 3;
    float inv0 = 1.0f / lrow[0], inv1 = 1.0f / lrow[1];
    {
        int sp0 = h * 128 + (sg0 >> 3), fp0 = (sg0 & 7) << 7;
        int sp1 = h * 128 + (sg1 >> 3), fp1 = (sg1 & 7) << 7;
        float* d0 = g_att + ((size_t)b_ * 1024 + sp0) * 1024 + fp0;
        float* d1 = g_att + ((size_t)b_ * 1024 + sp1) * 1024 + fp1;
        #pragma unroll
        for (int nt = 0; nt < 16; nt++) {
            int e = nt * 8 + 2 * tg;
            *(float2*)(d0 + e) = make_float2(o[nt][0] * inv0, o[nt][1] * inv0);
            *(float2*)(d1 + e) = make_float2(o[nt][2] * inv1, o[nt][3] * inv1);
        }
    }
}

// ---------------- fused MLP + residual + LayerNorm ----------------
__global__ __launch_bounds__(256) void mlp_ln_kernel(const float* __restrict__ X,
                                                     const float* __restrict__ Wm,
                                                     const float* __restrict__ gamma,
                                                     const float* __restrict__ beta,
                                                     float* __restrict__ out)
{
    __shared__ float At[64][32];
    __shared__ float Wt[32][128];
    const int m0 = blockIdx.x * 64;
    const int tid = threadIdx.x;
    const int tx = tid & 15, ty = tid >> 4;

    float acc[4][8] = {};

    for (int k0 = 0; k0 < 1024; k0 += 32) {
        __syncthreads();
        #pragma unroll
        for (int i = 0; i < 2; i++) {
            int f = tid + i * 256;
            int row = f >> 3;
            int col = (f & 7) << 2;
            *(float4*)(&At[row][col]) = *(const float4*)(g_att + (size_t)(m0 + row) * 1024 + k0 + col);
        }
        #pragma unroll
        for (int i = 0; i < 4; i++) {
            int f = tid + i * 256;
            int row = f >> 5;
            int col = (f & 31) << 2;
            *(float4*)(&Wt[row][col]) = *(const float4*)(Wm + (size_t)(k0 + row) * 128 + col);
        }
        __syncthreads();

        #pragma unroll
        for (int k4 = 0; k4 < 8; k4++) {
            float4 a[4];
            #pragma unroll
            for (int i = 0; i < 4; i++) a[i] = *(float4*)&At[ty * 4 + i][k4 * 4];
            float ws[4][8];
            #pragma unroll
            for (int kk = 0; kk < 4; kk++) {
                float4 u = *(float4*)&Wt[k4 * 4 + kk][tx * 8];
                float4 v = *(float4*)&Wt[k4 * 4 + kk][tx * 8 + 4];
                ws[kk][0] = u.x; ws[kk][1] = u.y; ws[kk][2] = u.z; ws[kk][3] = u.w;
                ws[kk][4] = v.x; ws[kk][5] = v.y; ws[kk][6] = v.z; ws[kk][7] = v.w;
            }
            #pragma unroll
            for (int i = 0; i < 4; i++)
                #pragma unroll
                for (int j = 0; j < 8; j++)
                    acc[i][j] += a[i].x * ws[0][j] + a[i].y * ws[1][j] + a[i].z * ws[2][j] + a[i].w * ws[3][j];
        }
    }

    float gj[8], bj[8];
    #pragma unroll
    for (int j = 0; j < 8; j++) { gj[j] = gamma[tx * 8 + j]; bj[j] = beta[tx * 8 + j]; }

    #pragma unroll
    for (int i = 0; i < 4; i++) {
        int r = m0 + ty * 4 + i;
        float y[8];
        float s = 0.f;
        #pragma unroll
        for (int j = 0; j < 8; j++) {
            y[j] = acc[i][j] + X[(size_t)r * 128 + tx * 8 + j];
            s += y[j];
        }
        #pragma unroll
        for (int off = 8; off; off >>= 1) s += __shfl_xor_sync(0xffffffffu, s, off);
        float mu = s * (1.0f / 128.0f);
        float vs = 0.f;
        #pragma unroll
        for (int j = 0; j < 8; j++) { float d = y[j] - mu; vs += d * d; }
        #pragma unroll
        for (int off = 8; off; off >>= 1) vs += __shfl_xor_sync(0xffffffffu, vs, off);
        float inv = rsqrtf(vs * (1.0f / 128.0f) + 1e-5f);
        #pragma unroll
        for (int j = 0; j < 8; j++)
            out[(size_t)r * 128 + tx * 8 + j] = (y[j] - mu) * inv * gj[j] + bj[j];
    }
}

// ---------------- launch ----------------
extern "C" void kernel_launch(void* const* d_in, const int* in_sizes, int n_in,
                              void* d_out, int out_size)
{
    const float* x     = (const float*)d_in[0];
    const float* memp  = (const float*)d_in[1];
    const float* u1    = (const float*)d_in[3];
    const float* u2    = (const float*)d_in[4];
    const float* w_q   = (const float*)d_in[5];
    const float* w_kv  = (const float*)d_in[6];
    const float* w_r   = (const float*)d_in[7];
    const float* w_mlp = (const float*)d_in[8];
    const float* ln_g  = (const float*)d_in[9];
    const float* ln_b  = (const float*)d_in[10];
    float* out = (float*)d_out;

    const int ggemm_smem = (128 * 136 * 2 + 64 * 136 * 2) * 2;         // 104,448 B
    const int attn_smem  = (128 * 136 * 2 + 64 * 136 * 3) * 2          // Qh,Ql,Kh,Kl,Vh bf16
                         + (128 * 65 + 64) * 4;                        // Ps, bias = 155,392 B
    cudaFuncSetAttribute(ggemm_mma_kernel, cudaFuncAttributeMaxDynamicSharedMemorySize, ggemm_smem);
    cudaFuncSetAttribute(attn_kernel,      cudaFuncAttributeMaxDynamicSharedMemorySize, attn_smem);

    proj_kernel<0><<<dim3(16, 64), 256>>>(x, nullptr, w_q, 1024);
    proj_kernel<1><<<dim3(32, 128), 256>>>(x, memp, w_kv, 2048);
    proj_kernel<2><<<dim3(16, 32), 256>>>(nullptr, nullptr, w_r, 1024);
    udot_kernel<<<8192, 256>>>(u1, 0, NB * NH * TOT);
    udot_kernel<<<2048, 256>>>(u2, 1, NH * TOT);
    ggemm_mma_kernel<<<dim3(32, 8, 32), 256, ggemm_smem>>>();
    attn_kernel<<<dim3(8, 32), 256, attn_smem>>>();
    mlp_ln_kernel<<<64, 256>>>(x, w_mlp, ln_g, ln_b, out);
}

// round 9
// speedup vs baseline: 6.7963x; 1.0903x over previous
#include <cuda_runtime.h>
#include <cuda_bf16.h>
#include <math.h>
#include <stdint.h>

#define NB 4
#define NH 8
#define SEGL 1024
#define TOT 2048
#define DD 128

// ---------------- scratch (device globals; no allocations) ----------------
__device__ float g_k[NB*NH*TOT*DD];       // fp32 (udot)
__device__ float g_r[NH*TOT*DD];          // fp32 (udot)
__device__ float g_pos[TOT*DD];           // sinusoid table
__device__ __nv_bfloat16 g_qh[NB*NH*SEGL*DD];
__device__ __nv_bfloat16 g_ql[NB*NH*SEGL*DD];
__device__ __nv_bfloat16 g_kh[NB*NH*TOT*DD];
__device__ __nv_bfloat16 g_kl[NB*NH*TOT*DD];
__device__ __nv_bfloat16 g_vh[NB*NH*TOT*DD];   // V single bf16 plane
__device__ __nv_bfloat16 g_rh[NH*TOT*DD];
__device__ __nv_bfloat16 g_rl[NH*TOT*DD];
__device__ float g_u1k[NB*NH*TOT];
__device__ float g_u2r[NH*TOT];
__device__ float g_att[NB*SEGL*NH*DD];
__device__ __nv_bfloat16 g_G[(size_t)NB*NH*SEGL*TOT]; // 134MB bf16: [bh][s][rel]

// ---------------- helpers ----------------
__device__ __forceinline__ uint32_t smem_u32(const void* p) {
    uint32_t a;
    asm("{ .reg .u64 t; cvta.to.shared.u64 t, %1; cvt.u32.u64 %0, t; }" : "=r"(a) : "l"(p));
    return a;
}
__device__ __forceinline__ uint32_t pack_bf16x2(float lo, float hi) {
    uint32_t d; asm("cvt.rn.bf16x2.f32 %0, %1, %2;" : "=r"(d) : "f"(hi), "f"(lo)); return d;
}

#define LDSM_X4(r, addr) \
    asm volatile("ldmatrix.sync.aligned.m8n8.x4.shared.b16 {%0,%1,%2,%3}, [%4];" \
        : "=r"((r)[0]), "=r"((r)[1]), "=r"((r)[2]), "=r"((r)[3]) : "r"(addr))
#define LDSM_X4_T(r, addr) \
    asm volatile("ldmatrix.sync.aligned.m8n8.x4.trans.shared.b16 {%0,%1,%2,%3}, [%4];" \
        : "=r"((r)[0]), "=r"((r)[1]), "=r"((r)[2]), "=r"((r)[3]) : "r"(addr))
#define MMA_BF16(c, a, b) \
    asm volatile("mma.sync.aligned.m16n8k16.row.col.f32.bf16.bf16.f32 " \
        "{%0,%1,%2,%3}, {%4,%5,%6,%7}, {%8,%9}, {%0,%1,%2,%3};" \
        : "+f"((c)[0]), "+f"((c)[1]), "+f"((c)[2]), "+f"((c)[3]) \
        : "r"((a)[0]), "r"((a)[1]), "r"((a)[2]), "r"((a)[3]), "r"((b)[0]), "r"((b)[1]))

__device__ __forceinline__ void split4_bf16(float4 v, ushort4& hv, ushort4& lv) {
    __nv_bfloat16 b;
    b = __float2bfloat16(v.x); hv.x = __bfloat16_as_ushort(b);
    lv.x = __bfloat16_as_ushort(__float2bfloat16(v.x - __bfloat162float(b)));
    b = __float2bfloat16(v.y); hv.y = __bfloat16_as_ushort(b);
    lv.y = __bfloat16_as_ushort(__float2bfloat16(v.y - __bfloat162float(b)));
    b = __float2bfloat16(v.z); hv.z = __bfloat16_as_ushort(b);
    lv.z = __bfloat16_as_ushort(__float2bfloat16(v.z - __bfloat162float(b)));
    b = __float2bfloat16(v.w); hv.w = __bfloat16_as_ushort(b);
    lv.w = __bfloat16_as_ushort(__float2bfloat16(v.w - __bfloat162float(b)));
}
__device__ __forceinline__ void split2_bf16(float a, float b, ushort2& hv, ushort2& lv) {
    __nv_bfloat16 t;
    t = __float2bfloat16(a); hv.x = __bfloat16_as_ushort(t);
    lv.x = __bfloat16_as_ushort(__float2bfloat16(a - __bfloat162float(t)));
    t = __float2bfloat16(b); hv.y = __bfloat16_as_ushort(t);
    lv.y = __bfloat16_as_ushort(__float2bfloat16(b - __bfloat162float(t)));
}

// ---------------- sinusoid position table ----------------
__global__ __launch_bounds__(256) void pos_kernel()
{
    int idx = blockIdx.x * 256 + threadIdx.x;   // < 2048*128
    int m = idx >> 7, e = idx & 127;
    float pp = (float)(2047 - m);
    float ang = pp / powf(10000.0f, (float)(2 * e) * (1.0f / 128.0f));
    g_pos[idx] = ((e & 1) == 0) ? sinf(ang) : cosf(ang);
}

// ---------------- projection GEMMs via bf16 mma.sync (3-term split) ----------------
// Tile: 128 M-rows x 64 N-cols, K = 128. 8 warps x 16 rows each.
// A staged hi/lo [128][136]; W staged [k][n] hi/lo [128][72], B-frags via ldmatrix.trans.
template<int MODE>
__global__ __launch_bounds__(256, 2) void proj_mma_kernel(const float* __restrict__ X,
                                                          const float* __restrict__ MEMI,
                                                          const float* __restrict__ W, int N)
{
    extern __shared__ __align__(16) unsigned short sm16[];
    unsigned short* Ah = sm16;              // 128*136
    unsigned short* Al = Ah + 128 * 136;
    unsigned short* Bh = Al + 128 * 136;    // 128*72 ([k][n])
    unsigned short* Bl = Bh + 128 * 72;

    const int m0 = blockIdx.y * 128;
    const int n0 = blockIdx.x * 64;
    const int tid = threadIdx.x, wid = tid >> 5, lane = tid & 31;

    // stage A (128 x 128 fp32 -> hi/lo bf16)
    #pragma unroll
    for (int i = 0; i < 16; i++) {
        int f = tid + i * 256;
        int row = f >> 5, col = (f & 31) << 2;
        int m = m0 + row;
        float4 a;
        if (MODE == 0) {
            a = *(const float4*)(X + (size_t)m * 128 + col);
        } else if (MODE == 1) {
            int bb = m >> 11, sp = m & 2047;
            const float* src = (sp < 1024) ? (MEMI + ((size_t)bb * 1024 + sp) * 128)
                                           : (X    + ((size_t)bb * 1024 + sp - 1024) * 128);
            a = *(const float4*)(src + col);
        } else {
            a = *(const float4*)(g_pos + (size_t)m * 128 + col);
        }
        ushort4 hv, lv;
        split4_bf16(a, hv, lv);
        *(ushort4*)(Ah + row * 136 + col) = hv;
        *(ushort4*)(Al + row * 136 + col) = lv;
    }
    // stage W tile (128 k-rows x 64 n-cols fp32 -> hi/lo bf16, natural [k][n])
    #pragma unroll
    for (int i = 0; i < 8; i++) {
        int f = tid + i * 256;
        int row = f >> 4, col = (f & 15) << 2;
        float4 w = *(const float4*)(W + (size_t)row * N + n0 + col);
        ushort4 hv, lv;
        split4_bf16(w, hv, lv);
        *(ushort4*)(Bh + row * 72 + col) = hv;
        *(ushort4*)(Bl + row * 72 + col) = lv;
    }
    __syncthreads();

    const int wm = wid * 16;
    const int arow = (lane & 7) + ((lane >> 3) & 1) * 8;
    const int akoff = (lane >> 4) * 16;
    const int vtrow = ((lane >> 3) & 1) * 8 + (lane & 7);
    const int vncol = ((lane >> 4) & 1) * 8;

    const uint32_t ah_b = smem_u32(Ah), al_b = smem_u32(Al);
    const uint32_t bh_b = smem_u32(Bh), bl_b = smem_u32(Bl);

    float cs[8][4];
    #pragma unroll
    for (int nt = 0; nt < 8; nt++)
        #pragma unroll
        for (int e = 0; e < 4; e++) cs[nt][e] = 0.f;

    #pragma unroll
    for (int ks = 0; ks < 8; ks++) {
        uint32_t ah[4], al4[4];
        uint32_t offA = (uint32_t)((wm + arow) * 272 + ks * 32 + akoff);
        LDSM_X4(ah, ah_b + offA);
        LDSM_X4(al4, al_b + offA);
        #pragma unroll
        for (int np = 0; np < 4; np++) {
            uint32_t bh4[4], bl4[4];
            uint32_t offB = (uint32_t)((ks * 16 + vtrow) * 144 + (np * 16 + vncol) * 2);
            LDSM_X4_T(bh4, bh_b + offB);
            LDSM_X4_T(bl4, bl_b + offB);
            MMA_BF16(cs[2 * np],     ah,  &bh4[0]);
            MMA_BF16(cs[2 * np],     ah,  &bl4[0]);
            MMA_BF16(cs[2 * np],     al4, &bh4[0]);
            MMA_BF16(cs[2 * np + 1], ah,  &bh4[2]);
            MMA_BF16(cs[2 * np + 1], ah,  &bl4[2]);
            MMA_BF16(cs[2 * np + 1], al4, &bh4[2]);
        }
    }

    // scatter epilogue in C-fragment coordinates (pairs of consecutive n)
    const int gp = lane >> 2, tg = lane & 3;
    #pragma unroll
    for (int half = 0; half < 2; half++) {
        int m = m0 + wm + gp + 8 * half;
        #pragma unroll
        for (int nt = 0; nt < 8; nt++) {
            int col = nt * 8 + 2 * tg;
            int fp = n0 + col;
            float v0 = cs[nt][2 * half], v1 = cs[nt][2 * half + 1];
            if (MODE == 0) {
                int b_ = m >> 10, sp = m & 1023;
                int h = sp >> 7;
                int s = ((sp & 127) << 3) + (fp >> 7);
                int e = fp & 127;
                size_t off = ((((size_t)b_ * 8 + h) * 1024 + s) << 7) + e;
                ushort2 hv, lv;
                split2_bf16(v0, v1, hv, lv);
                *(ushort2*)(g_qh + off) = hv;
                *(ushort2*)(g_ql + off) = lv;
            } else if (MODE == 1) {
                int bb = m >> 11, sp = m & 2047;
                int cc = bb * 2 + (sp >> 10);
                int h = (sp & 1023) >> 7;
                int t = ((sp & 127) << 4) + (fp >> 7);
                int e = fp & 127;
                if (cc < 4) {
                    size_t off = ((((size_t)cc * 8 + h) * 2048 + t) << 7) + e;
                    *(float2*)(g_k + off) = make_float2(v0, v1);
                    ushort2 hv, lv;
                    split2_bf16(v0, v1, hv, lv);
                    *(ushort2*)(g_kh + off) = hv;
                    *(ushort2*)(g_kl + off) = lv;
                } else {
                    size_t off = ((((size_t)(cc - 4) * 8 + h) * 2048 + t) << 7) + e;
                    ushort2 hv;
                    hv.x = __bfloat16_as_ushort(__float2bfloat16(v0));
                    hv.y = __bfloat16_as_ushort(__float2bfloat16(v1));
                    *(ushort2*)(g_vh + off) = hv;
                }
            } else {
                int h = m >> 8;
                int t = ((m & 255) << 3) + (fp >> 7);
                int e = fp & 127;
                size_t off = (((size_t)h * 2048 + t) << 7) + e;
                *(float2*)(g_r + off) = make_float2(v0, v1);
                ushort2 hv, lv;
                split2_bf16(v0, v1, hv, lv);
                *(ushort2*)(g_rh + off) = hv;
                *(ushort2*)(g_rl + off) = lv;
            }
        }
    }
}

// ---------------- u1·k and u2·r ----------------
__global__ __launch_bounds__(256) void udot_kernel(const float* __restrict__ U, int which, int nrows)
{
    int row = blockIdx.x * 8 + (threadIdx.x >> 5);
    int lane = threadIdx.x & 31;
    if (row >= nrows) return;
    const float* Mat = which ? g_r : g_k;
    float* Out = which ? g_u2r : g_u1k;
    int h = (row >> 11) & 7;
    float4 u = *(const float4*)(U + h * 128 + lane * 4);
    float4 m = *(const float4*)(Mat + (size_t)row * 128 + lane * 4);
    float s = u.x * m.x + u.y * m.y + u.z * m.z + u.w * m.w;
    #pragma unroll
    for (int o = 16; o; o >>= 1) s += __shfl_xor_sync(0xffffffffu, s, o);
    if (lane == 0) Out[row] = s;
}

// ---------------- banded G = q.r via bf16 mma.sync (bf16 output, R8-proven) ----------------
__global__ __launch_bounds__(256, 2) void ggemm_mma_kernel()
{
    extern __shared__ __align__(16) unsigned short sm16[];
    unsigned short* Qh = sm16;              // 128*136
    unsigned short* Ql = Qh + 128 * 136;
    unsigned short* Rh = Ql + 128 * 136;    // 64*136
    unsigned short* Rl = Rh + 64 * 136;

    const int rt = blockIdx.x, st = blockIdx.y, bh = blockIdx.z;
    if (rt < 14 - 2 * st) return;
    const int h = bh & 7;
    const int s0 = st * 128, r0 = rt * 64;
    const int tid = threadIdx.x, wid = tid >> 5, lane = tid & 31;

    const unsigned short* qh = (const unsigned short*)g_qh + ((size_t)bh * 1024 + s0) * 128;
    const unsigned short* ql = (const unsigned short*)g_ql + ((size_t)bh * 1024 + s0) * 128;
    #pragma unroll
    for (int i = 0; i < 8; i++) {
        int f = tid + i * 256;
        int row = f >> 4, c8 = (f & 15) << 3;
        *(uint4*)(Qh + row * 136 + c8) = *(const uint4*)(qh + (size_t)row * 128 + c8);
        *(uint4*)(Ql + row * 136 + c8) = *(const uint4*)(ql + (size_t)row * 128 + c8);
    }
    const unsigned short* rh = (const unsigned short*)g_rh + ((size_t)h * 2048 + r0) * 128;
    const unsigned short* rl = (const unsigned short*)g_rl + ((size_t)h * 2048 + r0) * 128;
    #pragma unroll
    for (int i = 0; i < 4; i++) {
        int f = tid + i * 256;
        int row = f >> 4, c8 = (f & 15) << 3;
        *(uint4*)(Rh + row * 136 + c8) = *(const uint4*)(rh + (size_t)row * 128 + c8);
        *(uint4*)(Rl + row * 136 + c8) = *(const uint4*)(rl + (size_t)row * 128 + c8);
    }
    __syncthreads();

    const int wm = (wid >> 1) * 32;
    const int wn = (wid & 1) * 32;

    float c[2][4][4];
    #pragma unroll
    for (int mt = 0; mt < 2; mt++)
        #pragma unroll
        for (int nt = 0; nt < 4; nt++)
            #pragma unroll
            for (int e = 0; e < 4; e++) c[mt][nt][e] = 0.f;

    const int arow = (lane & 7) + ((lane >> 3) & 1) * 8;
    const int akoff = (lane >> 4) * 16;
    const int brow = lane & 7;
    const int bkoff = ((lane >> 3) & 1) * 16;

    const uint32_t qh_b = smem_u32(Qh), ql_b = smem_u32(Ql);
    const uint32_t rh_b = smem_u32(Rh), rl_b = smem_u32(Rl);

    #pragma unroll
    for (int ks = 0; ks < 8; ks++) {
        uint32_t ah[2][4], al[2][4];
        #pragma unroll
        for (int mt = 0; mt < 2; mt++) {
            uint32_t off = (uint32_t)((wm + mt * 16 + arow) * 272 + ks * 32 + akoff);
            LDSM_X4(ah[mt], qh_b + off);
            LDSM_X4(al[mt], ql_b + off);
        }
        uint32_t bhf[4][2], blf[4][2];
        #pragma unroll
        for (int nt = 0; nt < 4; nt++) {
            uint32_t off = (uint32_t)((wn + nt * 8 + brow) * 272 + ks * 32 + bkoff);
            asm volatile("ldmatrix.sync.aligned.m8n8.x2.shared.b16 {%0,%1}, [%2];"
                : "=r"(bhf[nt][0]), "=r"(bhf[nt][1]) : "r"(rh_b + off));
            asm volatile("ldmatrix.sync.aligned.m8n8.x2.shared.b16 {%0,%1}, [%2];"
                : "=r"(blf[nt][0]), "=r"(blf[nt][1]) : "r"(rl_b + off));
        }
        #pragma unroll
        for (int mt = 0; mt < 2; mt++)
            #pragma unroll
            for (int nt = 0; nt < 4; nt++) {
                MMA_BF16(c[mt][nt], ah[mt], bhf[nt]);
                MMA_BF16(c[mt][nt], ah[mt], blf[nt]);
                MMA_BF16(c[mt][nt], al[mt], bhf[nt]);
            }
    }

    const int gp = lane >> 2, tg = lane & 3;
    __nv_bfloat16* Gb = g_G + (size_t)bh * (1024 * 2048);
    #pragma unroll
    for (int mt = 0; mt < 2; mt++) {
        int mrow = s0 + wm + mt * 16 + gp;
        #pragma unroll
        for (int nt = 0; nt < 4; nt++) {
            int n = r0 + wn + nt * 8 + 2 * tg;
            *(uint32_t*)(Gb + (size_t)mrow * 2048 + n)       = pack_bf16x2(c[mt][nt][0], c[mt][nt][1]);
            *(uint32_t*)(Gb + (size_t)(mrow + 8) * 2048 + n) = pack_bf16x2(c[mt][nt][2], c[mt][nt][3]);
        }
    }
}

// ---------------- flash attention: QK + PV both bf16 mma.sync (R8-proven) ----------------
__global__ __launch_bounds__(256, 1) void attn_kernel()
{
    extern __shared__ __align__(16) char smraw[];
    unsigned short* Qh = (unsigned short*)smraw;   // 128*136 bf16
    unsigned short* Ql = Qh + 128 * 136;
    unsigned short* Kh = Ql + 128 * 136;           // 64*136
    unsigned short* Kl = Kh + 64 * 136;
    unsigned short* Vh = Kl + 64 * 136;            // 64*136
    float* Ps   = (float*)(Vh + 64 * 136);         // 128*65 (G stage)
    float* bias = Ps + 128 * 65;                   // 64

    const int st = blockIdx.x, bh = blockIdx.y, h = bh & 7;
    const int s0 = st * 128;
    const int tid = threadIdx.x;
    const int wid = tid >> 5, lane = tid & 31;
    const int wm = wid * 16;
    const int gp = lane >> 2, tg = lane & 3;
    const int arow = (lane & 7) + ((lane >> 3) & 1) * 8;
    const int akoff = (lane >> 4) * 16;
    const int b4row = ((lane >> 4) & 1) * 8 + (lane & 7);
    const int b4koff = ((lane >> 3) & 1) * 16;
    const int vtrow = ((lane >> 3) & 1) * 8 + (lane & 7);
    const int vncol = ((lane >> 4) & 1) * 8;

    const unsigned short* qhp = (const unsigned short*)g_qh + ((size_t)bh * 1024 + s0) * 128;
    const unsigned short* qlp = (const unsigned short*)g_ql + ((size_t)bh * 1024 + s0) * 128;
    const unsigned short* khp = (const unsigned short*)g_kh + (size_t)bh * (2048 * 128);
    const unsigned short* klp = (const unsigned short*)g_kl + (size_t)bh * (2048 * 128);
    const unsigned short* vhp = (const unsigned short*)g_vh + (size_t)bh * (2048 * 128);
    const __nv_bfloat16* Gbh = g_G + (size_t)bh * (1024 * 2048);

    #pragma unroll
    for (int i = 0; i < 8; i++) {
        int f = tid + i * 256;
        int row = f >> 4, c8 = (f & 15) << 3;
        *(uint4*)(Qh + row * 136 + c8) = *(const uint4*)(qhp + (size_t)row * 128 + c8);
        *(uint4*)(Ql + row * 136 + c8) = *(const uint4*)(qlp + (size_t)row * 128 + c8);
    }

    const uint32_t qh_b = smem_u32(Qh), ql_b = smem_u32(Ql);
    const uint32_t kh_b = smem_u32(Kh), kl_b = smem_u32(Kl);
    const uint32_t vh_b = smem_u32(Vh);

    float o[16][4];
    #pragma unroll
    for (int nt = 0; nt < 16; nt++)
        #pragma unroll
        for (int e = 0; e < 4; e++) o[nt][e] = 0.f;

    float mrow[2], lrow[2];
    mrow[0] = mrow[1] = -1e30f;
    lrow[0] = lrow[1] = 0.f;

    const float scale = 0.08838834764831843f; // 1/sqrt(128)
    const int r0 = wm + gp, r1 = r0 + 8;
    const int sg0 = s0 + r0, sg1 = s0 + r1;

    const int ntiles = 2 * st + 18;
    for (int tt = 0; tt < ntiles; tt++) {
        const int t0 = tt * 64;
        __syncthreads();
        #pragma unroll
        for (int i = 0; i < 4; i++) {
            int f = tid + i * 256;
            int row = f >> 4, c8 = (f & 15) << 3;
            *(uint4*)(Kh + row * 136 + c8) = *(const uint4*)(khp + (size_t)(t0 + row) * 128 + c8);
            *(uint4*)(Kl + row * 136 + c8) = *(const uint4*)(klp + (size_t)(t0 + row) * 128 + c8);
        }
        #pragma unroll
        for (int i = 0; i < 4; i++) {
            int f = tid + i * 256;
            int row = f >> 4, c8 = (f & 15) << 3;
            *(uint4*)(Vh + row * 136 + c8) = *(const uint4*)(vhp + (size_t)(t0 + row) * 128 + c8);
        }
        const int relbase = t0 - s0 + 1023;
        #pragma unroll
        for (int i = 0; i < 32; i++) {
            int idx = tid + i * 256;
            int row = idx >> 6, col = idx & 63;
            int rel = relbase + col - row;
            Ps[row * 65 + col] = (rel <= 2047) ? __bfloat162float(Gbh[(size_t)(s0 + row) * 2048 + rel]) : 0.f;
        }
        if (tid < 64) bias[tid] = g_u1k[(size_t)bh * 2048 + t0 + tid] + g_u2r[(size_t)h * 2048 + t0 + tid];
        __syncthreads();

        float cs[8][4];
        #pragma unroll
        for (int nt = 0; nt < 8; nt++)
            #pragma unroll
            for (int e = 0; e < 4; e++) cs[nt][e] = 0.f;

        #pragma unroll
        for (int ks = 0; ks < 8; ks++) {
            uint32_t ah[4], al4[4];
            uint32_t offA = (uint32_t)((wm + arow) * 272 + ks * 32 + akoff);
            LDSM_X4(ah, qh_b + offA);
            LDSM_X4(al4, ql_b + offA);
            #pragma unroll
            for (int np = 0; np < 4; np++) {
                uint32_t bh4[4], bl4[4];
                uint32_t offB = (uint32_t)((np * 16 + b4row) * 272 + ks * 32 + b4koff);
                LDSM_X4(bh4, kh_b + offB);
                LDSM_X4(bl4, kl_b + offB);
                MMA_BF16(cs[2 * np],     ah,  &bh4[0]);
                MMA_BF16(cs[2 * np],     ah,  &bl4[0]);
                MMA_BF16(cs[2 * np],     al4, &bh4[0]);
                MMA_BF16(cs[2 * np + 1], ah,  &bh4[2]);
                MMA_BF16(cs[2 * np + 1], ah,  &bl4[2]);
                MMA_BF16(cs[2 * np + 1], al4, &bh4[2]);
            }
        }

        float mx0 = -1e30f, mx1 = -1e30f;
        #pragma unroll
        for (int nt = 0; nt < 8; nt++) {
            int col = nt * 8 + 2 * tg;
            int tgl = t0 + col;
            float b0 = bias[col], b1 = bias[col + 1];
            float v00 = (cs[nt][0] + Ps[r0 * 65 + col]     + b0) * scale;
            float v01 = (cs[nt][1] + Ps[r0 * 65 + col + 1] + b1) * scale;
            float v10 = (cs[nt][2] + Ps[r1 * 65 + col]     + b0) * scale;
            float v11 = (cs[nt][3] + Ps[r1 * 65 + col + 1] + b1) * scale;
            v00 = (tgl     - sg0 <= 1024) ? v00 : -1e30f;
            v01 = (tgl + 1 - sg0 <= 1024) ? v01 : -1e30f;
            v10 = (tgl     - sg1 <= 1024) ? v10 : -1e30f;
            v11 = (tgl + 1 - sg1 <= 1024) ? v11 : -1e30f;
            cs[nt][0] = v00; cs[nt][1] = v01; cs[nt][2] = v10; cs[nt][3] = v11;
            mx0 = fmaxf(mx0, fmaxf(v00, v01));
            mx1 = fmaxf(mx1, fmaxf(v10, v11));
        }
        mx0 = fmaxf(mx0, __shfl_xor_sync(0xffffffffu, mx0, 1));
        mx0 = fmaxf(mx0, __shfl_xor_sync(0xffffffffu, mx0, 2));
        mx1 = fmaxf(mx1, __shfl_xor_sync(0xffffffffu, mx1, 1));
        mx1 = fmaxf(mx1, __shfl_xor_sync(0xffffffffu, mx1, 2));

        float mn0 = fmaxf(mrow[0], mx0), mn1 = fmaxf(mrow[1], mx1);
        float al0 = __expf(mrow[0] - mn0), al1 = __expf(mrow[1] - mn1);
        float rs0 = 0.f, rs1 = 0.f;
        #pragma unroll
        for (int nt = 0; nt < 8; nt++) {
            float p00 = __expf(cs[nt][0] - mn0), p01 = __expf(cs[nt][1] - mn0);
            float p10 = __expf(cs[nt][2] - mn1), p11 = __expf(cs[nt][3] - mn1);
            rs0 += p00 + p01; rs1 += p10 + p11;
            cs[nt][0] = p00; cs[nt][1] = p01; cs[nt][2] = p10; cs[nt][3] = p11;
        }
        rs0 += __shfl_xor_sync(0xffffffffu, rs0, 1);
        rs0 += __shfl_xor_sync(0xffffffffu, rs0, 2);
        rs1 += __shfl_xor_sync(0xffffffffu, rs1, 1);
        rs1 += __shfl_xor_sync(0xffffffffu, rs1, 2);
        lrow[0] = lrow[0] * al0 + rs0; mrow[0] = mn0;
        lrow[1] = lrow[1] * al1 + rs1; mrow[1] = mn1;

        #pragma unroll
        for (int nt = 0; nt < 16; nt++) {
            o[nt][0] *= al0; o[nt][1] *= al0;
            o[nt][2] *= al1; o[nt][3] *= al1;
        }

        #pragma unroll
        for (int kc = 0; kc < 4; kc++) {
            uint32_t pa[4];
            pa[0] = pack_bf16x2(cs[2 * kc][0],     cs[2 * kc][1]);
            pa[1] = pack_bf16x2(cs[2 * kc][2],     cs[2 * kc][3]);
            pa[2] = pack_bf16x2(cs[2 * kc + 1][0], cs[2 * kc + 1][1]);
            pa[3] = pack_bf16x2(cs[2 * kc + 1][2], cs[2 * kc + 1][3]);
            #pragma unroll
            for (int ep = 0; ep < 8; ep++) {
                uint32_t vb4[4];
                uint32_t offV = (uint32_t)((kc * 16 + vtrow) * 272 + (ep * 16 + vncol) * 2);
                LDSM_X4_T(vb4, vh_b + offV);
                MMA_BF16(o[2 * ep],     pa, &vb4[0]);
                MMA_BF16(o[2 * ep + 1], pa, &vb4[2]);
            }
        }
    }

    const int b_ = bh >> 3;
    float inv0 = 1.0f / lrow[0], inv1 = 1.0f / lrow[1];
    {
        int sp0 = h * 128 + (sg0 >> 3), fp0 = (sg0 & 7) << 7;
        int sp1 = h * 128 + (sg1 >> 3), fp1 = (sg1 & 7) << 7;
        float* d0 = g_att + ((size_t)b_ * 1024 + sp0) * 1024 + fp0;
        float* d1 = g_att + ((size_t)b_ * 1024 + sp1) * 1024 + fp1;
        #pragma unroll
        for (int nt = 0; nt < 16; nt++) {
            int e = nt * 8 + 2 * tg;
            *(float2*)(d0 + e) = make_float2(o[nt][0] * inv0, o[nt][1] * inv0);
            *(float2*)(d1 + e) = make_float2(o[nt][2] * inv1, o[nt][3] * inv1);
        }
    }
}

// ---------------- fused MLP + residual + LayerNorm ----------------
__global__ __launch_bounds__(256) void mlp_ln_kernel(const float* __restrict__ X,
                                                     const float* __restrict__ Wm,
                                                     const float* __restrict__ gamma,
                                                     const float* __restrict__ beta,
                                                     float* __restrict__ out)
{
    __shared__ float At[64][32];
    __shared__ float Wt[32][128];
    const int m0 = blockIdx.x * 64;
    const int tid = threadIdx.x;
    const int tx = tid & 15, ty = tid >> 4;

    float acc[4][8] = {};

    for (int k0 = 0; k0 < 1024; k0 += 32) {
        __syncthreads();
        #pragma unroll
        for (int i = 0; i < 2; i++) {
            int f = tid + i * 256;
            int row = f >> 3;
            int col = (f & 7) << 2;
            *(float4*)(&At[row][col]) = *(const float4*)(g_att + (size_t)(m0 + row) * 1024 + k0 + col);
        }
        #pragma unroll
        for (int i = 0; i < 4; i++) {
            int f = tid + i * 256;
            int row = f >> 5;
            int col = (f & 31) << 2;
            *(float4*)(&Wt[row][col]) = *(const float4*)(Wm + (size_t)(k0 + row) * 128 + col);
        }
        __syncthreads();

        #pragma unroll
        for (int k4 = 0; k4 < 8; k4++) {
            float4 a[4];
            #pragma unroll
            for (int i = 0; i < 4; i++) a[i] = *(float4*)&At[ty * 4 + i][k4 * 4];
            float ws[4][8];
            #pragma unroll
            for (int kk = 0; kk < 4; kk++) {
                float4 u = *(float4*)&Wt[k4 * 4 + kk][tx * 8];
                float4 v = *(float4*)&Wt[k4 * 4 + kk][tx * 8 + 4];
                ws[kk][0] = u.x; ws[kk][1] = u.y; ws[kk][2] = u.z; ws[kk][3] = u.w;
                ws[kk][4] = v.x; ws[kk][5] = v.y; ws[kk][6] = v.z; ws[kk][7] = v.w;
            }
            #pragma unroll
            for (int i = 0; i < 4; i++)
                #pragma unroll
                for (int j = 0; j < 8; j++)
                    acc[i][j] += a[i].x * ws[0][j] + a[i].y * ws[1][j] + a[i].z * ws[2][j] + a[i].w * ws[3][j];
        }
    }

    float gj[8], bj[8];
    #pragma unroll
    for (int j = 0; j < 8; j++) { gj[j] = gamma[tx * 8 + j]; bj[j] = beta[tx * 8 + j]; }

    #pragma unroll
    for (int i = 0; i < 4; i++) {
        int r = m0 + ty * 4 + i;
        float y[8];
        float s = 0.f;
        #pragma unroll
        for (int j = 0; j < 8; j++) {
            y[j] = acc[i][j] + X[(size_t)r * 128 + tx * 8 + j];
            s += y[j];
        }
        #pragma unroll
        for (int off = 8; off; off >>= 1) s += __shfl_xor_sync(0xffffffffu, s, off);
        float mu = s * (1.0f / 128.0f);
        float vs = 0.f;
        #pragma unroll
        for (int j = 0; j < 8; j++) { float d = y[j] - mu; vs += d * d; }
        #pragma unroll
        for (int off = 8; off; off >>= 1) vs += __shfl_xor_sync(0xffffffffu, vs, off);
        float inv = rsqrtf(vs * (1.0f / 128.0f) + 1e-5f);
        #pragma unroll
        for (int j = 0; j < 8; j++)
            out[(size_t)r * 128 + tx * 8 + j] = (y[j] - mu) * inv * gj[j] + bj[j];
    }
}

// ---------------- launch ----------------
extern "C" void kernel_launch(void* const* d_in, const int* in_sizes, int n_in,
                              void* d_out, int out_size)
{
    const float* x     = (const float*)d_in[0];
    const float* memp  = (const float*)d_in[1];
    const float* u1    = (const float*)d_in[3];
    const float* u2    = (const float*)d_in[4];
    const float* w_q   = (const float*)d_in[5];
    const float* w_kv  = (const float*)d_in[6];
    const float* w_r   = (const float*)d_in[7];
    const float* w_mlp = (const float*)d_in[8];
    const float* ln_g  = (const float*)d_in[9];
    const float* ln_b  = (const float*)d_in[10];
    float* out = (float*)d_out;

    const int proj_smem  = (128 * 136 * 2 + 128 * 72 * 2) * 2;         // 106,496 B
    const int ggemm_smem = (128 * 136 * 2 + 64 * 136 * 2) * 2;         // 104,448 B
    const int attn_smem  = (128 * 136 * 2 + 64 * 136 * 3) * 2
                         + (128 * 65 + 64) * 4;                        // 155,392 B
    cudaFuncSetAttribute(proj_mma_kernel<0>, cudaFuncAttributeMaxDynamicSharedMemorySize, proj_smem);
    cudaFuncSetAttribute(proj_mma_kernel<1>, cudaFuncAttributeMaxDynamicSharedMemorySize, proj_smem);
    cudaFuncSetAttribute(proj_mma_kernel<2>, cudaFuncAttributeMaxDynamicSharedMemorySize, proj_smem);
    cudaFuncSetAttribute(ggemm_mma_kernel, cudaFuncAttributeMaxDynamicSharedMemorySize, ggemm_smem);
    cudaFuncSetAttribute(attn_kernel,      cudaFuncAttributeMaxDynamicSharedMemorySize, attn_smem);

    pos_kernel<<<1024, 256>>>();
    proj_mma_kernel<0><<<dim3(16, 32), 256, proj_smem>>>(x, nullptr, w_q, 1024);
    proj_mma_kernel<1><<<dim3(32, 64), 256, proj_smem>>>(x, memp, w_kv, 2048);
    proj_mma_kernel<2><<<dim3(16, 16), 256, proj_smem>>>(nullptr, nullptr, w_r, 1024);
    udot_kernel<<<8192, 256>>>(u1, 0, NB * NH * TOT);
    udot_kernel<<<2048, 256>>>(u2, 1, NH * TOT);
    ggemm_mma_kernel<<<dim3(32, 8, 32), 256, ggemm_smem>>>();
    attn_kernel<<<dim3(8, 32), 256, attn_smem>>>();
    mlp_ln_kernel<<<64, 256>>>(x, w_mlp, ln_g, ln_b, out);
}

// round 10
// speedup vs baseline: 9.1503x; 1.3464x over previous
#include <cuda_runtime.h>
#include <cuda_bf16.h>
#include <math.h>
#include <stdint.h>

#define NB 4
#define NH 8
#define SEGL 1024
#define TOT 2048
#define DD 128

// ---------------- scratch (device globals; no allocations) ----------------
__device__ float g_k[NB*NH*TOT*DD];       // fp32 (udot)
__device__ float g_r[NH*TOT*DD];          // fp32 (udot)
__device__ float g_pos[TOT*DD];           // sinusoid table
__device__ __nv_bfloat16 g_qh[NB*NH*SEGL*DD];
__device__ __nv_bfloat16 g_ql[NB*NH*SEGL*DD];
__device__ __nv_bfloat16 g_kh[NB*NH*TOT*DD];
__device__ __nv_bfloat16 g_kl[NB*NH*TOT*DD];
__device__ __nv_bfloat16 g_vh[NB*NH*TOT*DD];   // V single bf16 plane
__device__ __nv_bfloat16 g_rh[NH*TOT*DD];
__device__ __nv_bfloat16 g_rl[NH*TOT*DD];
__device__ float g_u1k[NB*NH*TOT];
__device__ float g_u2r[NH*TOT];
__device__ float g_att[NB*SEGL*NH*DD];
__device__ __nv_bfloat16 g_G[(size_t)NB*NH*SEGL*TOT + 4096]; // +pad for aligned over-fetch

// ---------------- helpers ----------------
__device__ __forceinline__ uint32_t smem_u32(const void* p) {
    uint32_t a;
    asm("{ .reg .u64 t; cvta.to.shared.u64 t, %1; cvt.u32.u64 %0, t; }" : "=r"(a) : "l"(p));
    return a;
}
__device__ __forceinline__ uint32_t pack_bf16x2(float lo, float hi) {
    uint32_t d; asm("cvt.rn.bf16x2.f32 %0, %1, %2;" : "=r"(d) : "f"(hi), "f"(lo)); return d;
}
__device__ __forceinline__ void cp16(uint32_t dst, const void* src) {
    asm volatile("cp.async.cg.shared.global [%0], [%1], 16;" :: "r"(dst), "l"(src) : "memory");
}
#define CP_COMMIT() asm volatile("cp.async.commit_group;" ::: "memory")
#define CP_WAIT(n)  asm volatile("cp.async.wait_group %0;" :: "n"(n) : "memory")

#define LDSM_X4(r, addr) \
    asm volatile("ldmatrix.sync.aligned.m8n8.x4.shared.b16 {%0,%1,%2,%3}, [%4];" \
        : "=r"((r)[0]), "=r"((r)[1]), "=r"((r)[2]), "=r"((r)[3]) : "r"(addr))
#define LDSM_X4_T(r, addr) \
    asm volatile("ldmatrix.sync.aligned.m8n8.x4.trans.shared.b16 {%0,%1,%2,%3}, [%4];" \
        : "=r"((r)[0]), "=r"((r)[1]), "=r"((r)[2]), "=r"((r)[3]) : "r"(addr))
#define MMA_BF16(c, a, b) \
    asm volatile("mma.sync.aligned.m16n8k16.row.col.f32.bf16.bf16.f32 " \
        "{%0,%1,%2,%3}, {%4,%5,%6,%7}, {%8,%9}, {%0,%1,%2,%3};" \
        : "+f"((c)[0]), "+f"((c)[1]), "+f"((c)[2]), "+f"((c)[3]) \
        : "r"((a)[0]), "r"((a)[1]), "r"((a)[2]), "r"((a)[3]), "r"((b)[0]), "r"((b)[1]))

__device__ __forceinline__ void split4_bf16(float4 v, ushort4& hv, ushort4& lv) {
    __nv_bfloat16 b;
    b = __float2bfloat16(v.x); hv.x = __bfloat16_as_ushort(b);
    lv.x = __bfloat16_as_ushort(__float2bfloat16(v.x - __bfloat162float(b)));
    b = __float2bfloat16(v.y); hv.y = __bfloat16_as_ushort(b);
    lv.y = __bfloat16_as_ushort(__float2bfloat16(v.y - __bfloat162float(b)));
    b = __float2bfloat16(v.z); hv.z = __bfloat16_as_ushort(b);
    lv.z = __bfloat16_as_ushort(__float2bfloat16(v.z - __bfloat162float(b)));
    b = __float2bfloat16(v.w); hv.w = __bfloat16_as_ushort(b);
    lv.w = __bfloat16_as_ushort(__float2bfloat16(v.w - __bfloat162float(b)));
}
__device__ __forceinline__ void split2_bf16(float a, float b, ushort2& hv, ushort2& lv) {
    __nv_bfloat16 t;
    t = __float2bfloat16(a); hv.x = __bfloat16_as_ushort(t);
    lv.x = __bfloat16_as_ushort(__float2bfloat16(a - __bfloat162float(t)));
    t = __float2bfloat16(b); hv.y = __bfloat16_as_ushort(t);
    lv.y = __bfloat16_as_ushort(__float2bfloat16(b - __bfloat162float(t)));
}

// ---------------- sinusoid position table ----------------
__global__ __launch_bounds__(256) void pos_kernel()
{
    int idx = blockIdx.x * 256 + threadIdx.x;
    int m = idx >> 7, e = idx & 127;
    float pp = (float)(2047 - m);
    float ang = pp / powf(10000.0f, (float)(2 * e) * (1.0f / 128.0f));
    g_pos[idx] = ((e & 1) == 0) ? sinf(ang) : cosf(ang);
}

// ---------------- projection GEMMs via bf16 mma.sync (R9-proven) ----------------
template<int MODE>
__global__ __launch_bounds__(256, 2) void proj_mma_kernel(const float* __restrict__ X,
                                                          const float* __restrict__ MEMI,
                                                          const float* __restrict__ W, int N)
{
    extern __shared__ __align__(16) unsigned short sm16[];
    unsigned short* Ah = sm16;              // 128*136
    unsigned short* Al = Ah + 128 * 136;
    unsigned short* Bh = Al + 128 * 136;    // 128*72 ([k][n])
    unsigned short* Bl = Bh + 128 * 72;

    const int m0 = blockIdx.y * 128;
    const int n0 = blockIdx.x * 64;
    const int tid = threadIdx.x, wid = tid >> 5, lane = tid & 31;

    #pragma unroll
    for (int i = 0; i < 16; i++) {
        int f = tid + i * 256;
        int row = f >> 5, col = (f & 31) << 2;
        int m = m0 + row;
        float4 a;
        if (MODE == 0) {
            a = *(const float4*)(X + (size_t)m * 128 + col);
        } else if (MODE == 1) {
            int bb = m >> 11, sp = m & 2047;
            const float* src = (sp < 1024) ? (MEMI + ((size_t)bb * 1024 + sp) * 128)
                                           : (X    + ((size_t)bb * 1024 + sp - 1024) * 128);
            a = *(const float4*)(src + col);
        } else {
            a = *(const float4*)(g_pos + (size_t)m * 128 + col);
        }
        ushort4 hv, lv;
        split4_bf16(a, hv, lv);
        *(ushort4*)(Ah + row * 136 + col) = hv;
        *(ushort4*)(Al + row * 136 + col) = lv;
    }
    #pragma unroll
    for (int i = 0; i < 8; i++) {
        int f = tid + i * 256;
        int row = f >> 4, col = (f & 15) << 2;
        float4 w = *(const float4*)(W + (size_t)row * N + n0 + col);
        ushort4 hv, lv;
        split4_bf16(w, hv, lv);
        *(ushort4*)(Bh + row * 72 + col) = hv;
        *(ushort4*)(Bl + row * 72 + col) = lv;
    }
    __syncthreads();

    const int wm = wid * 16;
    const int arow = (lane & 7) + ((lane >> 3) & 1) * 8;
    const int akoff = (lane >> 4) * 16;
    const int vtrow = ((lane >> 3) & 1) * 8 + (lane & 7);
    const int vncol = ((lane >> 4) & 1) * 8;

    const uint32_t ah_b = smem_u32(Ah), al_b = smem_u32(Al);
    const uint32_t bh_b = smem_u32(Bh), bl_b = smem_u32(Bl);

    float cs[8][4];
    #pragma unroll
    for (int nt = 0; nt < 8; nt++)
        #pragma unroll
        for (int e = 0; e < 4; e++) cs[nt][e] = 0.f;

    #pragma unroll
    for (int ks = 0; ks < 8; ks++) {
        uint32_t ah[4], al4[4];
        uint32_t offA = (uint32_t)((wm + arow) * 272 + ks * 32 + akoff);
        LDSM_X4(ah, ah_b + offA);
        LDSM_X4(al4, al_b + offA);
        #pragma unroll
        for (int np = 0; np < 4; np++) {
            uint32_t bh4[4], bl4[4];
            uint32_t offB = (uint32_t)((ks * 16 + vtrow) * 144 + (np * 16 + vncol) * 2);
            LDSM_X4_T(bh4, bh_b + offB);
            LDSM_X4_T(bl4, bl_b + offB);
            MMA_BF16(cs[2 * np],     ah,  &bh4[0]);
            MMA_BF16(cs[2 * np],     ah,  &bl4[0]);
            MMA_BF16(cs[2 * np],     al4, &bh4[0]);
            MMA_BF16(cs[2 * np + 1], ah,  &bh4[2]);
            MMA_BF16(cs[2 * np + 1], ah,  &bl4[2]);
            MMA_BF16(cs[2 * np + 1], al4, &bh4[2]);
        }
    }

    const int gp = lane >> 2, tg = lane & 3;
    #pragma unroll
    for (int half = 0; half < 2; half++) {
        int m = m0 + wm + gp + 8 * half;
        #pragma unroll
        for (int nt = 0; nt < 8; nt++) {
            int col = nt * 8 + 2 * tg;
            int fp = n0 + col;
            float v0 = cs[nt][2 * half], v1 = cs[nt][2 * half + 1];
            if (MODE == 0) {
                int b_ = m >> 10, sp = m & 1023;
                int h = sp >> 7;
                int s = ((sp & 127) << 3) + (fp >> 7);
                int e = fp & 127;
                size_t off = ((((size_t)b_ * 8 + h) * 1024 + s) << 7) + e;
                ushort2 hv, lv;
                split2_bf16(v0, v1, hv, lv);
                *(ushort2*)(g_qh + off) = hv;
                *(ushort2*)(g_ql + off) = lv;
            } else if (MODE == 1) {
                int bb = m >> 11, sp = m & 2047;
                int cc = bb * 2 + (sp >> 10);
                int h = (sp & 1023) >> 7;
                int t = ((sp & 127) << 4) + (fp >> 7);
                int e = fp & 127;
                if (cc < 4) {
                    size_t off = ((((size_t)cc * 8 + h) * 2048 + t) << 7) + e;
                    *(float2*)(g_k + off) = make_float2(v0, v1);
                    ushort2 hv, lv;
                    split2_bf16(v0, v1, hv, lv);
                    *(ushort2*)(g_kh + off) = hv;
                    *(ushort2*)(g_kl + off) = lv;
                } else {
                    size_t off = ((((size_t)(cc - 4) * 8 + h) * 2048 + t) << 7) + e;
                    ushort2 hv;
                    hv.x = __bfloat16_as_ushort(__float2bfloat16(v0));
                    hv.y = __bfloat16_as_ushort(__float2bfloat16(v1));
                    *(ushort2*)(g_vh + off) = hv;
                }
            } else {
                int h = m >> 8;
                int t = ((m & 255) << 3) + (fp >> 7);
                int e = fp & 127;
                size_t off = (((size_t)h * 2048 + t) << 7) + e;
                *(float2*)(g_r + off) = make_float2(v0, v1);
                ushort2 hv, lv;
                split2_bf16(v0, v1, hv, lv);
                *(ushort2*)(g_rh + off) = hv;
                *(ushort2*)(g_rl + off) = lv;
            }
        }
    }
}

// ---------------- u1·k and u2·r ----------------
__global__ __launch_bounds__(256) void udot_kernel(const float* __restrict__ U, int which, int nrows)
{
    int row = blockIdx.x * 8 + (threadIdx.x >> 5);
    int lane = threadIdx.x & 31;
    if (row >= nrows) return;
    const float* Mat = which ? g_r : g_k;
    float* Out = which ? g_u2r : g_u1k;
    int h = (row >> 11) & 7;
    float4 u = *(const float4*)(U + h * 128 + lane * 4);
    float4 m = *(const float4*)(Mat + (size_t)row * 128 + lane * 4);
    float s = u.x * m.x + u.y * m.y + u.z * m.z + u.w * m.w;
    #pragma unroll
    for (int o = 16; o; o >>= 1) s += __shfl_xor_sync(0xffffffffu, s, o);
    if (lane == 0) Out[row] = s;
}

// ---------------- banded G = q.r via bf16 mma.sync (R8-proven, bf16 output) ----------------
__global__ __launch_bounds__(256, 2) void ggemm_mma_kernel()
{
    extern __shared__ __align__(16) unsigned short sm16[];
    unsigned short* Qh = sm16;              // 128*136
    unsigned short* Ql = Qh + 128 * 136;
    unsigned short* Rh = Ql + 128 * 136;    // 64*136
    unsigned short* Rl = Rh + 64 * 136;

    const int rt = blockIdx.x, st = blockIdx.y, bh = blockIdx.z;
    if (rt < 14 - 2 * st) return;
    const int h = bh & 7;
    const int s0 = st * 128, r0 = rt * 64;
    const int tid = threadIdx.x, wid = tid >> 5, lane = tid & 31;

    const unsigned short* qh = (const unsigned short*)g_qh + ((size_t)bh * 1024 + s0) * 128;
    const unsigned short* ql = (const unsigned short*)g_ql + ((size_t)bh * 1024 + s0) * 128;
    #pragma unroll
    for (int i = 0; i < 8; i++) {
        int f = tid + i * 256;
        int row = f >> 4, c8 = (f & 15) << 3;
        *(uint4*)(Qh + row * 136 + c8) = *(const uint4*)(qh + (size_t)row * 128 + c8);
        *(uint4*)(Ql + row * 136 + c8) = *(const uint4*)(ql + (size_t)row * 128 + c8);
    }
    const unsigned short* rh = (const unsigned short*)g_rh + ((size_t)h * 2048 + r0) * 128;
    const unsigned short* rl = (const unsigned short*)g_rl + ((size_t)h * 2048 + r0) * 128;
    #pragma unroll
    for (int i = 0; i < 4; i++) {
        int f = tid + i * 256;
        int row = f >> 4, c8 = (f & 15) << 3;
        *(uint4*)(Rh + row * 136 + c8) = *(const uint4*)(rh + (size_t)row * 128 + c8);
        *(uint4*)(Rl + row * 136 + c8) = *(const uint4*)(rl + (size_t)row * 128 + c8);
    }
    __syncthreads();

    const int wm = (wid >> 1) * 32;
    const int wn = (wid & 1) * 32;

    float c[2][4][4];
    #pragma unroll
    for (int mt = 0; mt < 2; mt++)
        #pragma unroll
        for (int nt = 0; nt < 4; nt++)
            #pragma unroll
            for (int e = 0; e < 4; e++) c[mt][nt][e] = 0.f;

    const int arow = (lane & 7) + ((lane >> 3) & 1) * 8;
    const int akoff = (lane >> 4) * 16;
    const int brow = lane & 7;
    const int bkoff = ((lane >> 3) & 1) * 16;

    const uint32_t qh_b = smem_u32(Qh), ql_b = smem_u32(Ql);
    const uint32_t rh_b = smem_u32(Rh), rl_b = smem_u32(Rl);

    #pragma unroll
    for (int ks = 0; ks < 8; ks++) {
        uint32_t ah[2][4], al[2][4];
        #pragma unroll
        for (int mt = 0; mt < 2; mt++) {
            uint32_t off = (uint32_t)((wm + mt * 16 + arow) * 272 + ks * 32 + akoff);
            LDSM_X4(ah[mt], qh_b + off);
            LDSM_X4(al[mt], ql_b + off);
        }
        uint32_t bhf[4][2], blf[4][2];
        #pragma unroll
        for (int nt = 0; nt < 4; nt++) {
            uint32_t off = (uint32_t)((wn + nt * 8 + brow) * 272 + ks * 32 + bkoff);
            asm volatile("ldmatrix.sync.aligned.m8n8.x2.shared.b16 {%0,%1}, [%2];"
                : "=r"(bhf[nt][0]), "=r"(bhf[nt][1]) : "r"(rh_b + off));
            asm volatile("ldmatrix.sync.aligned.m8n8.x2.shared.b16 {%0,%1}, [%2];"
                : "=r"(blf[nt][0]), "=r"(blf[nt][1]) : "r"(rl_b + off));
        }
        #pragma unroll
        for (int mt = 0; mt < 2; mt++)
            #pragma unroll
            for (int nt = 0; nt < 4; nt++) {
                MMA_BF16(c[mt][nt], ah[mt], bhf[nt]);
                MMA_BF16(c[mt][nt], ah[mt], blf[nt]);
                MMA_BF16(c[mt][nt], al[mt], bhf[nt]);
            }
    }

    const int gp = lane >> 2, tg = lane & 3;
    __nv_bfloat16* Gb = g_G + (size_t)bh * (1024 * 2048);
    #pragma unroll
    for (int mt = 0; mt < 2; mt++) {
        int mrow = s0 + wm + mt * 16 + gp;
        #pragma unroll
        for (int nt = 0; nt < 4; nt++) {
            int n = r0 + wn + nt * 8 + 2 * tg;
            *(uint32_t*)(Gb + (size_t)mrow * 2048 + n)       = pack_bf16x2(c[mt][nt][0], c[mt][nt][1]);
            *(uint32_t*)(Gb + (size_t)(mrow + 8) * 2048 + n) = pack_bf16x2(c[mt][nt][2], c[mt][nt][3]);
        }
    }
}

// ---------------- flash attention: cp.async double-buffered, QK+PV bf16 mma ----------------
__global__ __launch_bounds__(256, 1) void attn_kernel()
{
    extern __shared__ __align__(16) char smraw[];
    unsigned short* Qh  = (unsigned short*)smraw;     // 128*136
    unsigned short* Ql  = Qh + 128 * 136;
    unsigned short* Kh0 = Ql + 128 * 136;             // 2 bufs x 64*136
    unsigned short* Kl0 = Kh0 + 2 * 64 * 136;
    unsigned short* Vh0 = Kl0 + 2 * 64 * 136;
    unsigned short* Gs0 = Vh0 + 2 * 64 * 136;         // 2 bufs x 128*80
    float* biasF = (float*)(Gs0 + 2 * 128 * 80);      // 2 bufs x 128 floats (u1k|u2r)

    const int st = blockIdx.x, bh = blockIdx.y, h = bh & 7;
    const int s0 = st * 128;
    const int tid = threadIdx.x;
    const int wid = tid >> 5, lane = tid & 31;
    const int wm = wid * 16;
    const int gp = lane >> 2, tg = lane & 3;
    const int arow = (lane & 7) + ((lane >> 3) & 1) * 8;
    const int akoff = (lane >> 4) * 16;
    const int b4row = ((lane >> 4) & 1) * 8 + (lane & 7);
    const int b4koff = ((lane >> 3) & 1) * 16;
    const int vtrow = ((lane >> 3) & 1) * 8 + (lane & 7);
    const int vncol = ((lane >> 4) & 1) * 8;

    const unsigned short* qhp = (const unsigned short*)g_qh + ((size_t)bh * 1024 + s0) * 128;
    const unsigned short* qlp = (const unsigned short*)g_ql + ((size_t)bh * 1024 + s0) * 128;
    const unsigned short* khp = (const unsigned short*)g_kh + (size_t)bh * (2048 * 128);
    const unsigned short* klp = (const unsigned short*)g_kl + (size_t)bh * (2048 * 128);
    const unsigned short* vhp = (const unsigned short*)g_vh + (size_t)bh * (2048 * 128);
    const unsigned short* Gbh = (const unsigned short*)g_G + (size_t)bh * (1024 * 2048);

    // stage Q hi/lo once (plain loads)
    #pragma unroll
    for (int i = 0; i < 8; i++) {
        int f = tid + i * 256;
        int row = f >> 4, c8 = (f & 15) << 3;
        *(uint4*)(Qh + row * 136 + c8) = *(const uint4*)(qhp + (size_t)row * 128 + c8);
        *(uint4*)(Ql + row * 136 + c8) = *(const uint4*)(qlp + (size_t)row * 128 + c8);
    }

    const uint32_t qh_b = smem_u32(Qh), ql_b = smem_u32(Ql);
    const uint32_t khBase = smem_u32(Kh0), klBase = smem_u32(Kl0), vhBase = smem_u32(Vh0);
    const uint32_t gsBase = smem_u32(Gs0), biasBase = smem_u32(biasF);

    // stage one tile's K/V/G/bias via cp.async into buffer b
    auto stage = [&](int b, int tt) {
        const int t0 = tt * 64;
        const uint32_t kh = khBase + b * 17408;
        const uint32_t kl = klBase + b * 17408;
        const uint32_t vh = vhBase + b * 17408;
        const uint32_t gs = gsBase + b * 20480;
        const uint32_t bb = biasBase + b * 512;
        #pragma unroll
        for (int i = 0; i < 12; i++) {           // K hi/lo + V: 3 x 1024 chunks
            int idx = tid + i * 256;
            int p = idx >> 10;
            int rc = idx & 1023;
            int row = rc >> 4, ch = rc & 15;
            uint32_t dst = (p == 0 ? kh : p == 1 ? kl : vh) + (uint32_t)(row * 272 + ch * 16);
            const unsigned short* src = (p == 0 ? khp : p == 1 ? klp : vhp)
                                      + (size_t)(t0 + row) * 128 + ch * 8;
            cp16(dst, src);
        }
        const int relbase = t0 - s0 + 1023;
        #pragma unroll
        for (int i = 0; i < 5; i++) {            // G band: 128 rows x 9 chunks
            int idx = tid + i * 256;
            if (idx < 1152) {
                int row = idx / 9, ch = idx - row * 9;
                int start = (relbase - row) & ~7;
                cp16(gs + (uint32_t)(row * 160 + ch * 16),
                     Gbh + (size_t)(s0 + row) * 2048 + start + ch * 8);
            }
        }
        if (tid < 32) {                          // bias: u1k | u2r, 64 floats each
            int arr = tid >> 4, c = tid & 15;
            const float* src = arr ? (g_u2r + (size_t)h * 2048 + t0 + c * 4)
                                   : (g_u1k + (size_t)bh * 2048 + t0 + c * 4);
            cp16(bb + (uint32_t)(arr * 256 + c * 16), src);
        }
    };

    float o[16][4];
    #pragma unroll
    for (int nt = 0; nt < 16; nt++)
        #pragma unroll
        for (int e = 0; e < 4; e++) o[nt][e] = 0.f;

    float mrow[2], lrow[2];
    mrow[0] = mrow[1] = -1e30f;
    lrow[0] = lrow[1] = 0.f;

    const float scale = 0.08838834764831843f; // 1/sqrt(128)
    const int r0 = wm + gp, r1 = r0 + 8;
    const int sg0 = s0 + r0, sg1 = s0 + r1;

    const int ntiles = 2 * st + 18;
    stage(0, 0);
    CP_COMMIT();
    int buf = 0;

    for (int tt = 0; tt < ntiles; tt++) {
        __syncthreads();                         // everyone done reading buf^1 (prev tile)
        if (tt + 1 < ntiles) {
            stage(buf ^ 1, tt + 1);
            CP_COMMIT();
            CP_WAIT(1);                          // current tile's group complete
        } else {
            CP_WAIT(0);
        }
        __syncthreads();                         // current tile visible block-wide

        const int t0 = tt * 64;
        const int relbase = t0 - s0 + 1023;
        const uint32_t kh_b = khBase + buf * 17408;
        const uint32_t kl_b = klBase + buf * 17408;
        const uint32_t vh_b = vhBase + buf * 17408;
        const unsigned short* GsB = Gs0 + buf * 10240;
        const float* bA = biasF + buf * 128;
        const int off0 = (relbase - r0) & 7;
        const int off1 = (relbase - r1) & 7;

        // ---- QK (3-term bf16 split) ----
        float cs[8][4];
        #pragma unroll
        for (int nt = 0; nt < 8; nt++)
            #pragma unroll
            for (int e = 0; e < 4; e++) cs[nt][e] = 0.f;

        #pragma unroll
        for (int ks = 0; ks < 8; ks++) {
            uint32_t ah[4], al4[4];
            uint32_t offA = (uint32_t)((wm + arow) * 272 + ks * 32 + akoff);
            LDSM_X4(ah, qh_b + offA);
            LDSM_X4(al4, ql_b + offA);
            #pragma unroll
            for (int np = 0; np < 4; np++) {
                uint32_t bh4[4], bl4[4];
                uint32_t offB = (uint32_t)((np * 16 + b4row) * 272 + ks * 32 + b4koff);
                LDSM_X4(bh4, kh_b + offB);
                LDSM_X4(bl4, kl_b + offB);
                MMA_BF16(cs[2 * np],     ah,  &bh4[0]);
                MMA_BF16(cs[2 * np],     ah,  &bl4[0]);
                MMA_BF16(cs[2 * np],     al4, &bh4[0]);
                MMA_BF16(cs[2 * np + 1], ah,  &bh4[2]);
                MMA_BF16(cs[2 * np + 1], ah,  &bl4[2]);
                MMA_BF16(cs[2 * np + 1], al4, &bh4[2]);
            }
        }

        // ---- bias + G + scale + mask ----
        float mx0 = -1e30f, mx1 = -1e30f;
        #pragma unroll
        for (int nt = 0; nt < 8; nt++) {
            int col = nt * 8 + 2 * tg;
            int tgl = t0 + col;
            float b0 = bA[col] + bA[64 + col];
            float b1 = bA[col + 1] + bA[64 + col + 1];
            float g00 = __bfloat162float(*(const __nv_bfloat16*)(GsB + r0 * 80 + off0 + col));
            float g01 = __bfloat162float(*(const __nv_bfloat16*)(GsB + r0 * 80 + off0 + col + 1));
            float g10 = __bfloat162float(*(const __nv_bfloat16*)(GsB + r1 * 80 + off1 + col));
            float g11 = __bfloat162float(*(const __nv_bfloat16*)(GsB + r1 * 80 + off1 + col + 1));
            float v00 = (cs[nt][0] + g00 + b0) * scale;
            float v01 = (cs[nt][1] + g01 + b1) * scale;
            float v10 = (cs[nt][2] + g10 + b0) * scale;
            float v11 = (cs[nt][3] + g11 + b1) * scale;
            v00 = (tgl     - sg0 <= 1024) ? v00 : -1e30f;
            v01 = (tgl + 1 - sg0 <= 1024) ? v01 : -1e30f;
            v10 = (tgl     - sg1 <= 1024) ? v10 : -1e30f;
            v11 = (tgl + 1 - sg1 <= 1024) ? v11 : -1e30f;
            cs[nt][0] = v00; cs[nt][1] = v01; cs[nt][2] = v10; cs[nt][3] = v11;
            mx0 = fmaxf(mx0, fmaxf(v00, v01));
            mx1 = fmaxf(mx1, fmaxf(v10, v11));
        }
        mx0 = fmaxf(mx0, __shfl_xor_sync(0xffffffffu, mx0, 1));
        mx0 = fmaxf(mx0, __shfl_xor_sync(0xffffffffu, mx0, 2));
        mx1 = fmaxf(mx1, __shfl_xor_sync(0xffffffffu, mx1, 1));
        mx1 = fmaxf(mx1, __shfl_xor_sync(0xffffffffu, mx1, 2));

        float mn0 = fmaxf(mrow[0], mx0), mn1 = fmaxf(mrow[1], mx1);
        float al0 = __expf(mrow[0] - mn0), al1 = __expf(mrow[1] - mn1);
        float rs0 = 0.f, rs1 = 0.f;
        #pragma unroll
        for (int nt = 0; nt < 8; nt++) {
            float p00 = __expf(cs[nt][0] - mn0), p01 = __expf(cs[nt][1] - mn0);
            float p10 = __expf(cs[nt][2] - mn1), p11 = __expf(cs[nt][3] - mn1);
            rs0 += p00 + p01; rs1 += p10 + p11;
            cs[nt][0] = p00; cs[nt][1] = p01; cs[nt][2] = p10; cs[nt][3] = p11;
        }
        rs0 += __shfl_xor_sync(0xffffffffu, rs0, 1);
        rs0 += __shfl_xor_sync(0xffffffffu, rs0, 2);
        rs1 += __shfl_xor_sync(0xffffffffu, rs1, 1);
        rs1 += __shfl_xor_sync(0xffffffffu, rs1, 2);
        lrow[0] = lrow[0] * al0 + rs0; mrow[0] = mn0;
        lrow[1] = lrow[1] * al1 + rs1; mrow[1] = mn1;

        #pragma unroll
        for (int nt = 0; nt < 16; nt++) {
            o[nt][0] *= al0; o[nt][1] *= al0;
            o[nt][2] *= al1; o[nt][3] *= al1;
        }

        // ---- PV: P regs->bf16 A-frags, V via ldmatrix.trans ----
        #pragma unroll
        for (int kc = 0; kc < 4; kc++) {
            uint32_t pa[4];
            pa[0] = pack_bf16x2(cs[2 * kc][0],     cs[2 * kc][1]);
            pa[1] = pack_bf16x2(cs[2 * kc][2],     cs[2 * kc][3]);
            pa[2] = pack_bf16x2(cs[2 * kc + 1][0], cs[2 * kc + 1][1]);
            pa[3] = pack_bf16x2(cs[2 * kc + 1][2], cs[2 * kc + 1][3]);
            #pragma unroll
            for (int ep = 0; ep < 8; ep++) {
                uint32_t vb4[4];
                uint32_t offV = (uint32_t)((kc * 16 + vtrow) * 272 + (ep * 16 + vncol) * 2);
                LDSM_X4_T(vb4, vh_b + offV);
                MMA_BF16(o[2 * ep],     pa, &vb4[0]);
                MMA_BF16(o[2 * ep + 1], pa, &vb4[2]);
            }
        }
        buf ^= 1;
    }

    // ---- epilogue ----
    const int b_ = bh >> 3;
    float inv0 = 1.0f / lrow[0], inv1 = 1.0f / lrow[1];
    {
        int sp0 = h * 128 + (sg0 >> 3), fp0 = (sg0 & 7) << 7;
        int sp1 = h * 128 + (sg1 >> 3), fp1 = (sg1 & 7) << 7;
        float* d0 = g_att + ((size_t)b_ * 1024 + sp0) * 1024 + fp0;
        float* d1 = g_att + ((size_t)b_ * 1024 + sp1) * 1024 + fp1;
        #pragma unroll
        for (int nt = 0; nt < 16; nt++) {
            int e = nt * 8 + 2 * tg;
            *(float2*)(d0 + e) = make_float2(o[nt][0] * inv0, o[nt][1] * inv0);
            *(float2*)(d1 + e) = make_float2(o[nt][2] * inv1, o[nt][3] * inv1);
        }
    }
}

// ---------------- fused MLP + residual + LayerNorm ----------------
__global__ __launch_bounds__(256) void mlp_ln_kernel(const float* __restrict__ X,
                                                     const float* __restrict__ Wm,
                                                     const float* __restrict__ gamma,
                                                     const float* __restrict__ beta,
                                                     float* __restrict__ out)
{
    __shared__ float At[64][32];
    __shared__ float Wt[32][128];
    const int m0 = blockIdx.x * 64;
    const int tid = threadIdx.x;
    const int tx = tid & 15, ty = tid >> 4;

    float acc[4][8] = {};

    for (int k0 = 0; k0 < 1024; k0 += 32) {
        __syncthreads();
        #pragma unroll
        for (int i = 0; i < 2; i++) {
            int f = tid + i * 256;
            int row = f >> 3;
            int col = (f & 7) << 2;
            *(float4*)(&At[row][col]) = *(const float4*)(g_att + (size_t)(m0 + row) * 1024 + k0 + col);
        }
        #pragma unroll
        for (int i = 0; i < 4; i++) {
            int f = tid + i * 256;
            int row = f >> 5;
            int col = (f & 31) << 2;
            *(float4*)(&Wt[row][col]) = *(const float4*)(Wm + (size_t)(k0 + row) * 128 + col);
        }
        __syncthreads();

        #pragma unroll
        for (int k4 = 0; k4 < 8; k4++) {
            float4 a[4];
            #pragma unroll
            for (int i = 0; i < 4; i++) a[i] = *(float4*)&At[ty * 4 + i][k4 * 4];
            float ws[4][8];
            #pragma unroll
            for (int kk = 0; kk < 4; kk++) {
                float4 u = *(float4*)&Wt[k4 * 4 + kk][tx * 8];
                float4 v = *(float4*)&Wt[k4 * 4 + kk][tx * 8 + 4];
                ws[kk][0] = u.x; ws[kk][1] = u.y; ws[kk][2] = u.z; ws[kk][3] = u.w;
                ws[kk][4] = v.x; ws[kk][5] = v.y; ws[kk][6] = v.z; ws[kk][7] = v.w;
            }
            #pragma unroll
            for (int i = 0; i < 4; i++)
                #pragma unroll
                for (int j = 0; j < 8; j++)
                    acc[i][j] += a[i].x * ws[0][j] + a[i].y * ws[1][j] + a[i].z * ws[2][j] + a[i].w * ws[3][j];
        }
    }

    float gj[8], bj[8];
    #pragma unroll
    for (int j = 0; j < 8; j++) { gj[j] = gamma[tx * 8 + j]; bj[j] = beta[tx * 8 + j]; }

    #pragma unroll
    for (int i = 0; i < 4; i++) {
        int r = m0 + ty * 4 + i;
        float y[8];
        float s = 0.f;
        #pragma unroll
        for (int j = 0; j < 8; j++) {
            y[j] = acc[i][j] + X[(size_t)r * 128 + tx * 8 + j];
            s += y[j];
        }
        #pragma unroll
        for (int off = 8; off; off >>= 1) s += __shfl_xor_sync(0xffffffffu, s, off);
        float mu = s * (1.0f / 128.0f);
        float vs = 0.f;
        #pragma unroll
        for (int j = 0; j < 8; j++) { float d = y[j] - mu; vs += d * d; }
        #pragma unroll
        for (int off = 8; off; off >>= 1) vs += __shfl_xor_sync(0xffffffffu, vs, off);
        float inv = rsqrtf(vs * (1.0f / 128.0f) + 1e-5f);
        #pragma unroll
        for (int j = 0; j < 8; j++)
            out[(size_t)r * 128 + tx * 8 + j] = (y[j] - mu) * inv * gj[j] + bj[j];
    }
}

// ---------------- launch ----------------
extern "C" void kernel_launch(void* const* d_in, const int* in_sizes, int n_in,
                              void* d_out, int out_size)
{
    const float* x     = (const float*)d_in[0];
    const float* memp  = (const float*)d_in[1];
    const float* u1    = (const float*)d_in[3];
    const float* u2    = (const float*)d_in[4];
    const float* w_q   = (const float*)d_in[5];
    const float* w_kv  = (const float*)d_in[6];
    const float* w_r   = (const float*)d_in[7];
    const float* w_mlp = (const float*)d_in[8];
    const float* ln_g  = (const float*)d_in[9];
    const float* ln_b  = (const float*)d_in[10];
    float* out = (float*)d_out;

    const int proj_smem  = (128 * 136 * 2 + 128 * 72 * 2) * 2;                     // 106,496 B
    const int ggemm_smem = (128 * 136 * 2 + 64 * 136 * 2) * 2;                     // 104,448 B
    const int attn_smem  = (128 * 136 * 2 + 2 * 64 * 136 * 3 + 2 * 128 * 80) * 2
                         + 2 * 128 * 4;                                            // 216,064 B
    cudaFuncSetAttribute(proj_mma_kernel<0>, cudaFuncAttributeMaxDynamicSharedMemorySize, proj_smem);
    cudaFuncSetAttribute(proj_mma_kernel<1>, cudaFuncAttributeMaxDynamicSharedMemorySize, proj_smem);
    cudaFuncSetAttribute(proj_mma_kernel<2>, cudaFuncAttributeMaxDynamicSharedMemorySize, proj_smem);
    cudaFuncSetAttribute(ggemm_mma_kernel, cudaFuncAttributeMaxDynamicSharedMemorySize, ggemm_smem);
    cudaFuncSetAttribute(attn_kernel,      cudaFuncAttributeMaxDynamicSharedMemorySize, attn_smem);

    pos_kernel<<<1024, 256>>>();
    proj_mma_kernel<0><<<dim3(16, 32), 256, proj_smem>>>(x, nullptr, w_q, 1024);
    proj_mma_kernel<1><<<dim3(32, 64), 256, proj_smem>>>(x, memp, w_kv, 2048);
    proj_mma_kernel<2><<<dim3(16, 16), 256, proj_smem>>>(nullptr, nullptr, w_r, 1024);
    udot_kernel<<<8192, 256>>>(u1, 0, NB * NH * TOT);
    udot_kernel<<<2048, 256>>>(u2, 1, NH * TOT);
    ggemm_mma_kernel<<<dim3(32, 8, 32), 256, ggemm_smem>>>();
    attn_kernel<<<dim3(8, 32), 256, attn_smem>>>();
    mlp_ln_kernel<<<64, 256>>>(x, w_mlp, ln_g, ln_b, out);
}